// round 1
// baseline (speedup 1.0000x reference)
#include <cuda_runtime.h>

#define N_NODES 50000
#define N_EDGES 800000
#define NODE_C  128
#define EDGE_C  64

// Scratch for scatter-add aggregation (no cudaMalloc allowed).
__device__ float g_aggr[(size_t)N_NODES * EDGE_C];

__device__ __forceinline__ float silu_f(float x) {
    return x / (1.0f + __expf(-x));
}

// ---------------------------------------------------------------------------
// Zero the aggregation scratch (must precede edge kernel atomics).
// ---------------------------------------------------------------------------
__global__ void zero_aggr_kernel() {
    size_t i = (size_t)blockIdx.x * blockDim.x + threadIdx.x;
    size_t n4 = (size_t)N_NODES * EDGE_C / 4;
    if (i < n4) reinterpret_cast<float4*>(g_aggr)[i] = make_float4(0.f, 0.f, 0.f, 0.f);
}

// ---------------------------------------------------------------------------
// Edge kernel: per 64-edge tile
//   state[64,320] = [xn[snd] | xn[rcv] | xe]           (gathered)
//   h   = silu(state @ eW1 + eb1)      [64,128]
//   out = silu(h @ eW2 + eb2)          [64,64]
//   edges_out <- out ; atomicAdd(aggr[rcv], out)
//
// 256 threads, 4x8 (GEMM1) / 4x4 (GEMM2) register micro-tiles.
// SMEM layout (floats):
//   phase 1: As[32][68] at 0 (2176), Bs[32][128] at 2176 (4096)
//   phase 2: Hs[64][132] at 0 (8448), Bs2[32][64] at 8448 (2048)
// ---------------------------------------------------------------------------
#define SM_FLOATS 10496   // 41984 bytes
#define AS_STRIDE 68
#define BS_OFF    2176
#define HS_STRIDE 132
#define BS2_OFF   8448

__global__ __launch_bounds__(256, 2)
void edge_kernel(const float* __restrict__ xn,
                 const float* __restrict__ xe,
                 const void*  __restrict__ eidx,
                 const float* __restrict__ eW1,
                 const float* __restrict__ eb1,
                 const float* __restrict__ eW2,
                 const float* __restrict__ eb2,
                 float* __restrict__ edges_out)
{
    __shared__ float sm[SM_FLOATS];
    __shared__ int s_snd[64], s_rcv[64];

    const int tid = threadIdx.x;
    const int ty  = tid >> 4;     // 0..15  -> rows ty*4 .. ty*4+3
    const int tx  = tid & 15;     // 0..15  -> cols tx*8 .. (GEMM1) / tx*4 (GEMM2)
    const int e0  = blockIdx.x * 64;

    // Detect edge_index element width (int32 vs int64, values < 2^31 so
    // int64 buffers have all-zero odd 32-bit words).
    const unsigned* w = reinterpret_cast<const unsigned*>(eidx);
    const bool is64 = ((w[1] | w[3] | w[5] | w[7] | w[9] | w[11] | w[13] | w[15]) == 0u);

    if (tid < 64) {
        size_t e = (size_t)e0 + tid;
        if (is64) {
            const long long* p = reinterpret_cast<const long long*>(eidx);
            s_snd[tid] = (int)p[e];
            s_rcv[tid] = (int)p[(size_t)N_EDGES + e];
        } else {
            const int* p = reinterpret_cast<const int*>(eidx);
            s_snd[tid] = p[e];
            s_rcv[tid] = p[(size_t)N_EDGES + e];
        }
    }
    __syncthreads();

    // ---------------- GEMM1: [64,320] @ [320,128] ----------------
    float c[4][8];
#pragma unroll
    for (int i = 0; i < 4; i++)
#pragma unroll
        for (int j = 0; j < 8; j++) c[i][j] = 0.f;

#pragma unroll 1
    for (int ch = 0; ch < 10; ch++) {
        // A gather: 64 rows x 32 k = 512 float4 loads (transposed store)
#pragma unroll
        for (int r = 0; r < 2; r++) {
            int q  = tid + 256 * r;
            int m  = q >> 3;            // edge within tile
            int kl = (q & 7) * 4;       // k within chunk
            const float* rowp;
            if (ch < 4)      rowp = xn + (size_t)s_snd[m] * NODE_C + ch * 32;
            else if (ch < 8) rowp = xn + (size_t)s_rcv[m] * NODE_C + (ch - 4) * 32;
            else             rowp = xe + (size_t)(e0 + m) * EDGE_C + (ch - 8) * 32;
            float4 v = *reinterpret_cast<const float4*>(rowp + kl);
            sm[(kl + 0) * AS_STRIDE + m] = v.x;
            sm[(kl + 1) * AS_STRIDE + m] = v.y;
            sm[(kl + 2) * AS_STRIDE + m] = v.z;
            sm[(kl + 3) * AS_STRIDE + m] = v.w;
        }
        // B: eW1 rows [ch*32, ch*32+32) x 128 cols = 1024 float4
        const float4* bsrc = reinterpret_cast<const float4*>(eW1 + (size_t)ch * 32 * 128);
        float4* bdst = reinterpret_cast<float4*>(sm + BS_OFF);
#pragma unroll
        for (int r = 0; r < 4; r++) bdst[tid + 256 * r] = bsrc[tid + 256 * r];
        __syncthreads();

#pragma unroll
        for (int k = 0; k < 32; k++) {
            float4 a  = *reinterpret_cast<float4*>(sm + k * AS_STRIDE + ty * 4);
            float4 b0 = *reinterpret_cast<float4*>(sm + BS_OFF + k * 128 + tx * 8);
            float4 b1 = *reinterpret_cast<float4*>(sm + BS_OFF + k * 128 + tx * 8 + 4);
            float av[4] = {a.x, a.y, a.z, a.w};
            float bv[8] = {b0.x, b0.y, b0.z, b0.w, b1.x, b1.y, b1.z, b1.w};
#pragma unroll
            for (int i = 0; i < 4; i++)
#pragma unroll
                for (int j = 0; j < 8; j++)
                    c[i][j] = fmaf(av[i], bv[j], c[i][j]);
        }
        __syncthreads();
    }

    // bias + silu -> Hs[64][132]
    {
        float bb[8];
#pragma unroll
        for (int j = 0; j < 8; j++) bb[j] = eb1[tx * 8 + j];
#pragma unroll
        for (int i = 0; i < 4; i++) {
            int rrow = ty * 4 + i;
#pragma unroll
            for (int j = 0; j < 8; j++)
                sm[rrow * HS_STRIDE + tx * 8 + j] = silu_f(c[i][j] + bb[j]);
        }
    }
    __syncthreads();

    // ---------------- GEMM2: [64,128] @ [128,64] ----------------
    float c2[4][4];
#pragma unroll
    for (int i = 0; i < 4; i++)
#pragma unroll
        for (int j = 0; j < 4; j++) c2[i][j] = 0.f;

#pragma unroll 1
    for (int ch = 0; ch < 4; ch++) {
        const float4* b2src = reinterpret_cast<const float4*>(eW2 + (size_t)ch * 32 * 64);
        float4* b2dst = reinterpret_cast<float4*>(sm + BS2_OFF);
        b2dst[tid]       = b2src[tid];
        b2dst[tid + 256] = b2src[tid + 256];
        __syncthreads();

#pragma unroll
        for (int k = 0; k < 32; k++) {
            float4 b = *reinterpret_cast<float4*>(sm + BS2_OFF + k * 64 + tx * 4);
            float bv[4] = {b.x, b.y, b.z, b.w};
#pragma unroll
            for (int i = 0; i < 4; i++) {
                float a = sm[(ty * 4 + i) * HS_STRIDE + ch * 32 + k];
#pragma unroll
                for (int j = 0; j < 4; j++)
                    c2[i][j] = fmaf(a, bv[j], c2[i][j]);
            }
        }
        __syncthreads();
    }

    // epilogue: silu, store edge output, scatter-add into aggr
    {
        float bb2[4];
#pragma unroll
        for (int j = 0; j < 4; j++) bb2[j] = eb2[tx * 4 + j];
#pragma unroll
        for (int i = 0; i < 4; i++) {
            int rrow = ty * 4 + i;
            int e    = e0 + rrow;
            int rcv  = s_rcv[rrow];
            float4 o;
            o.x = silu_f(c2[i][0] + bb2[0]);
            o.y = silu_f(c2[i][1] + bb2[1]);
            o.z = silu_f(c2[i][2] + bb2[2]);
            o.w = silu_f(c2[i][3] + bb2[3]);
            *reinterpret_cast<float4*>(edges_out + (size_t)e * EDGE_C + tx * 4) = o;
            float* ag = g_aggr + (size_t)rcv * EDGE_C + tx * 4;
            atomicAdd(ag + 0, o.x);
            atomicAdd(ag + 1, o.y);
            atomicAdd(ag + 2, o.z);
            atomicAdd(ag + 3, o.w);
        }
    }
}

// ---------------------------------------------------------------------------
// Node kernel: per 64-node tile
//   n[64,192] = [xn | aggr]
//   out = silu(n @ nW1 + nb1) @ nW2 + nb2   [64,128]
// GEMM2 chunks of 16 to fit 48KB static SMEM.
// ---------------------------------------------------------------------------
__global__ __launch_bounds__(256, 2)
void node_kernel(const float* __restrict__ xn,
                 const float* __restrict__ nW1,
                 const float* __restrict__ nb1,
                 const float* __restrict__ nW2,
                 const float* __restrict__ nb2,
                 float* __restrict__ nodes_out)
{
    __shared__ float sm[SM_FLOATS];

    const int tid = threadIdx.x;
    const int ty  = tid >> 4;
    const int tx  = tid & 15;
    const int m0  = blockIdx.x * 64;

    // ---------------- GEMM1: [64,192] @ [192,128] ----------------
    float c[4][8];
#pragma unroll
    for (int i = 0; i < 4; i++)
#pragma unroll
        for (int j = 0; j < 8; j++) c[i][j] = 0.f;

#pragma unroll 1
    for (int ch = 0; ch < 6; ch++) {
#pragma unroll
        for (int r = 0; r < 2; r++) {
            int q  = tid + 256 * r;
            int m  = q >> 3;
            int kl = (q & 7) * 4;
            size_t row = (size_t)m0 + m;
            float4 v = make_float4(0.f, 0.f, 0.f, 0.f);
            if (row < N_NODES) {
                const float* rowp = (ch < 4)
                    ? xn + row * NODE_C + ch * 32
                    : g_aggr + row * EDGE_C + (ch - 4) * 32;
                v = *reinterpret_cast<const float4*>(rowp + kl);
            }
            sm[(kl + 0) * AS_STRIDE + m] = v.x;
            sm[(kl + 1) * AS_STRIDE + m] = v.y;
            sm[(kl + 2) * AS_STRIDE + m] = v.z;
            sm[(kl + 3) * AS_STRIDE + m] = v.w;
        }
        const float4* bsrc = reinterpret_cast<const float4*>(nW1 + (size_t)ch * 32 * 128);
        float4* bdst = reinterpret_cast<float4*>(sm + BS_OFF);
#pragma unroll
        for (int r = 0; r < 4; r++) bdst[tid + 256 * r] = bsrc[tid + 256 * r];
        __syncthreads();

#pragma unroll
        for (int k = 0; k < 32; k++) {
            float4 a  = *reinterpret_cast<float4*>(sm + k * AS_STRIDE + ty * 4);
            float4 b0 = *reinterpret_cast<float4*>(sm + BS_OFF + k * 128 + tx * 8);
            float4 b1 = *reinterpret_cast<float4*>(sm + BS_OFF + k * 128 + tx * 8 + 4);
            float av[4] = {a.x, a.y, a.z, a.w};
            float bv[8] = {b0.x, b0.y, b0.z, b0.w, b1.x, b1.y, b1.z, b1.w};
#pragma unroll
            for (int i = 0; i < 4; i++)
#pragma unroll
                for (int j = 0; j < 8; j++)
                    c[i][j] = fmaf(av[i], bv[j], c[i][j]);
        }
        __syncthreads();
    }

    // bias + silu -> Hs
    {
        float bb[8];
#pragma unroll
        for (int j = 0; j < 8; j++) bb[j] = nb1[tx * 8 + j];
#pragma unroll
        for (int i = 0; i < 4; i++) {
            int rrow = ty * 4 + i;
#pragma unroll
            for (int j = 0; j < 8; j++)
                sm[rrow * HS_STRIDE + tx * 8 + j] = silu_f(c[i][j] + bb[j]);
        }
    }
    __syncthreads();

    // ---------------- GEMM2: [64,128] @ [128,128], chunks of 16 ----------------
    float c2[4][8];
#pragma unroll
    for (int i = 0; i < 4; i++)
#pragma unroll
        for (int j = 0; j < 8; j++) c2[i][j] = 0.f;

#pragma unroll 1
    for (int ch = 0; ch < 8; ch++) {
        const float4* b2src = reinterpret_cast<const float4*>(nW2 + (size_t)ch * 16 * 128);
        float4* b2dst = reinterpret_cast<float4*>(sm + BS2_OFF);
        b2dst[tid]       = b2src[tid];
        b2dst[tid + 256] = b2src[tid + 256];
        __syncthreads();

#pragma unroll
        for (int k = 0; k < 16; k++) {
            float4 b0 = *reinterpret_cast<float4*>(sm + BS2_OFF + k * 128 + tx * 8);
            float4 b1 = *reinterpret_cast<float4*>(sm + BS2_OFF + k * 128 + tx * 8 + 4);
            float bv[8] = {b0.x, b0.y, b0.z, b0.w, b1.x, b1.y, b1.z, b1.w};
#pragma unroll
            for (int i = 0; i < 4; i++) {
                float a = sm[(ty * 4 + i) * HS_STRIDE + ch * 16 + k];
#pragma unroll
                for (int j = 0; j < 8; j++)
                    c2[i][j] = fmaf(a, bv[j], c2[i][j]);
            }
        }
        __syncthreads();
    }

    // epilogue: + nb2 (no silu), store
    {
        float bb[8];
#pragma unroll
        for (int j = 0; j < 8; j++) bb[j] = nb2[tx * 8 + j];
#pragma unroll
        for (int i = 0; i < 4; i++) {
            size_t row = (size_t)m0 + ty * 4 + i;
            if (row < N_NODES) {
                float4 o0, o1;
                o0.x = c2[i][0] + bb[0];
                o0.y = c2[i][1] + bb[1];
                o0.z = c2[i][2] + bb[2];
                o0.w = c2[i][3] + bb[3];
                o1.x = c2[i][4] + bb[4];
                o1.y = c2[i][5] + bb[5];
                o1.z = c2[i][6] + bb[6];
                o1.w = c2[i][7] + bb[7];
                float* op = nodes_out + row * NODE_C + tx * 8;
                *reinterpret_cast<float4*>(op)     = o0;
                *reinterpret_cast<float4*>(op + 4) = o1;
            }
        }
    }
}

// ---------------------------------------------------------------------------
extern "C" void kernel_launch(void* const* d_in, const int* in_sizes, int n_in,
                              void* d_out, int out_size)
{
    const float* xn   = (const float*)d_in[0];   // [50000,128]
    const float* xe   = (const float*)d_in[1];   // [800000,64]
    const void*  eidx =               d_in[2];   // [2,800000] int32 or int64
    const float* eW1  = (const float*)d_in[3];   // [320,128]
    const float* eb1  = (const float*)d_in[4];   // [128]
    const float* eW2  = (const float*)d_in[5];   // [128,64]
    const float* eb2  = (const float*)d_in[6];   // [64]
    const float* nW1  = (const float*)d_in[7];   // [192,128]
    const float* nb1  = (const float*)d_in[8];   // [128]
    const float* nW2  = (const float*)d_in[9];   // [128,128]
    const float* nb2  = (const float*)d_in[10];  // [128]

    float* nodes_out = (float*)d_out;                                   // [50000,128]
    float* edges_out = (float*)d_out + (size_t)N_NODES * NODE_C;        // [800000,64]

    // 1) zero aggregation scratch
    zero_aggr_kernel<<<(N_NODES * EDGE_C / 4 + 255) / 256, 256>>>();
    // 2) fused edge MLP + scatter-add
    edge_kernel<<<N_EDGES / 64, 256>>>(xn, xe, eidx, eW1, eb1, eW2, eb2, edges_out);
    // 3) fused node MLP
    node_kernel<<<(N_NODES + 63) / 64, 256>>>(xn, nW1, nb1, nW2, nb2, nodes_out);
}

// round 3
// speedup vs baseline: 2.3054x; 2.3054x over previous
#include <cuda_runtime.h>
#include <cuda_fp16.h>
#include <cstdint>

#define N_NODES 50000
#define N_EDGES 800000
#define NODE_C  128
#define EDGE_C  64

// ---------------------------------------------------------------------------
// Device scratch (no cudaMalloc allowed)
// ---------------------------------------------------------------------------
__device__ float g_aggr[(size_t)N_NODES * EDGE_C];
// Pre-transposed, fp16 hi/lo-split weights: Wt[n][k] = W[k][n]
__device__ __align__(16) __half g_eW1t_hi[128 * 320];
__device__ __align__(16) __half g_eW1t_lo[128 * 320];
__device__ __align__(16) __half g_eW2t_hi[64 * 128];
__device__ __align__(16) __half g_eW2t_lo[64 * 128];
__device__ __align__(16) __half g_nW1t_hi[128 * 192];
__device__ __align__(16) __half g_nW1t_lo[128 * 192];
__device__ __align__(16) __half g_nW2t_hi[128 * 128];
__device__ __align__(16) __half g_nW2t_lo[128 * 128];

// ---------------------------------------------------------------------------
// Helpers
// ---------------------------------------------------------------------------
__device__ __forceinline__ uint32_t smem_u32(const void* p) {
    uint32_t a;
    asm("{ .reg .u64 t; cvta.to.shared.u64 t, %1; cvt.u32.u64 %0, t; }"
        : "=r"(a) : "l"(p));
    return a;
}

// Panels: [rows][64] fp16, 128-byte rows, XOR-swizzled 16B blocks.
__device__ __forceinline__ uint32_t panel_off(uint32_t r, uint32_t k) {
    return r * 128u + ((((k >> 3) ^ (r & 7u)) << 4) | ((k & 7u) << 1));
}

__device__ __forceinline__ void ldsm_x4(uint32_t* d, uint32_t a) {
    asm volatile("ldmatrix.sync.aligned.m8n8.x4.shared.b16 {%0,%1,%2,%3}, [%4];"
                 : "=r"(d[0]), "=r"(d[1]), "=r"(d[2]), "=r"(d[3]) : "r"(a));
}
__device__ __forceinline__ void ldsm_x2(uint32_t* d, uint32_t a) {
    asm volatile("ldmatrix.sync.aligned.m8n8.x2.shared.b16 {%0,%1}, [%2];"
                 : "=r"(d[0]), "=r"(d[1]) : "r"(a));
}

#define MMA16816(c, a, b) \
    asm volatile("mma.sync.aligned.m16n8k16.row.col.f32.f16.f16.f32 " \
        "{%0,%1,%2,%3},{%4,%5,%6,%7},{%8,%9},{%0,%1,%2,%3};" \
        : "+f"((c)[0]), "+f"((c)[1]), "+f"((c)[2]), "+f"((c)[3]) \
        : "r"((a)[0]), "r"((a)[1]), "r"((a)[2]), "r"((a)[3]), \
          "r"((b)[0]), "r"((b)[1]))

__device__ __forceinline__ uint32_t f16x2(float lo, float hi) {
    uint32_t r;
    asm("cvt.rn.f16x2.f32 %0, %1, %2;" : "=r"(r) : "f"(hi), "f"(lo));
    return r;
}
__device__ __forceinline__ float h_round(float x) {
    return __half2float(__float2half_rn(x));
}
__device__ __forceinline__ float silu_f(float x) {
    return x / (1.0f + __expf(-x));
}

// Pack 8 floats (two float4) into hi uint4 + lo uint4 (fp16 split)
__device__ __forceinline__ void split8(float4 v0, float4 v1, uint4& hi, uint4& lo) {
    float a0 = h_round(v0.x), a1 = h_round(v0.y), a2 = h_round(v0.z), a3 = h_round(v0.w);
    float a4 = h_round(v1.x), a5 = h_round(v1.y), a6 = h_round(v1.z), a7 = h_round(v1.w);
    hi.x = f16x2(a0, a1); hi.y = f16x2(a2, a3); hi.z = f16x2(a4, a5); hi.w = f16x2(a6, a7);
    lo.x = f16x2(v0.x - a0, v0.y - a1);
    lo.y = f16x2(v0.z - a2, v0.w - a3);
    lo.z = f16x2(v1.x - a4, v1.y - a5);
    lo.w = f16x2(v1.z - a6, v1.w - a7);
}

// ---------------------------------------------------------------------------
// Small setup kernels
// ---------------------------------------------------------------------------
__global__ void zero_aggr_kernel() {
    size_t i = (size_t)blockIdx.x * blockDim.x + threadIdx.x;
    size_t n4 = (size_t)N_NODES * EDGE_C / 4;
    if (i < n4) reinterpret_cast<float4*>(g_aggr)[i] = make_float4(0.f, 0.f, 0.f, 0.f);
}

__global__ void prep_weights_kernel(const float* __restrict__ eW1,
                                    const float* __restrict__ eW2,
                                    const float* __restrict__ nW1,
                                    const float* __restrict__ nW2) {
    int i = blockIdx.x * 256 + threadIdx.x;
    if (i < 128 * 320) {
        int n = i / 320, k = i % 320;
        float v = eW1[(size_t)k * 128 + n];
        float h = h_round(v);
        g_eW1t_hi[i] = __float2half_rn(h);
        g_eW1t_lo[i] = __float2half_rn(v - h);
    }
    if (i < 64 * 128) {
        int n = i / 128, k = i % 128;
        float v = eW2[(size_t)k * 64 + n];
        float h = h_round(v);
        g_eW2t_hi[i] = __float2half_rn(h);
        g_eW2t_lo[i] = __float2half_rn(v - h);
    }
    if (i < 128 * 192) {
        int n = i / 192, k = i % 192;
        float v = nW1[(size_t)k * 128 + n];
        float h = h_round(v);
        g_nW1t_hi[i] = __float2half_rn(h);
        g_nW1t_lo[i] = __float2half_rn(v - h);
    }
    if (i < 128 * 128) {
        int n = i / 128, k = i % 128;
        float v = nW2[(size_t)k * 128 + n];
        float h = h_round(v);
        g_nW2t_hi[i] = __float2half_rn(h);
        g_nW2t_lo[i] = __float2half_rn(v - h);
    }
}

// ---------------------------------------------------------------------------
// SMEM layout (both kernels), 131072 bytes dynamic:
//   [0      .. 16K)  A_hi panel [128][64]          | later B2_hi
//   [16K    .. 32K)  A_lo panel                    | later B2 (cont.)
//   [32K    .. 48K)  B_hi panel [128][64]          | later B2_lo
//   [48K    .. 64K)  B_lo panel                    | (cont.)
//   [64K    .. 80K)  h_hi panel0 [128][64]
//   [80K    .. 96K)  h_hi panel1
//   [96K    ..112K)  h_lo panel0
//   [112K   ..128K)  h_lo panel1
// ---------------------------------------------------------------------------
#define SMEM_BYTES 131072

// ---------------------------------------------------------------------------
// Edge kernel: 128 edges / CTA, 8 warps (4 M-strips x 2 N-halves)
// ---------------------------------------------------------------------------
__global__ __launch_bounds__(256, 1)
void edge_mma_kernel(const float* __restrict__ xn,
                     const float* __restrict__ xe,
                     const void*  __restrict__ eidx,
                     const float* __restrict__ eb1,
                     const float* __restrict__ eb2,
                     float* __restrict__ edges_out)
{
    extern __shared__ __align__(1024) char dsm[];
    __shared__ int s_rcv[128];

    const int tid  = threadIdx.x;
    const int wid  = tid >> 5;
    const int lane = tid & 31;
    const int mw   = wid & 3;      // M strip (32 rows)
    const int nw   = wid >> 2;     // N half  (64 cols in GEMM1, 32 in GEMM2)
    const int e0   = blockIdx.x * 128;

    const uint32_t sb = smem_u32(dsm);
    const uint32_t la_r  = lane & 15;          // ldmatrix A row lane
    const uint32_t la_kb = (lane >> 4) << 3;   // ldmatrix A k-block lane
    const uint32_t lb_r  = lane & 7;           // ldmatrix B row lane
    const uint32_t lb_kb = ((lane >> 3) & 1) << 3;

    // edge indices (int32/int64 auto-detect), receiver needed for scatter
    int my_snd, my_rcv;
    {
        const unsigned* w = reinterpret_cast<const unsigned*>(eidx);
        const bool is64 = ((w[1] | w[3] | w[5] | w[7] | w[9] | w[11] | w[13] | w[15]) == 0u);
        const int m = tid >> 1;
        size_t e = (size_t)e0 + m;
        if (is64) {
            const long long* p = reinterpret_cast<const long long*>(eidx);
            my_snd = (int)p[e];
            my_rcv = (int)p[(size_t)N_EDGES + e];
        } else {
            const int* p = reinterpret_cast<const int*>(eidx);
            my_snd = p[e];
            my_rcv = p[(size_t)N_EDGES + e];
        }
        if ((tid & 1) == 0) s_rcv[m] = my_rcv;
    }

    // ---------------- GEMM1: [128,320] @ Wt^T -> [128,128] ----------------
    float c[2][8][4];
#pragma unroll
    for (int a = 0; a < 2; a++)
#pragma unroll
        for (int b = 0; b < 8; b++)
#pragma unroll
            for (int d = 0; d < 4; d++) c[a][b][d] = 0.f;

    const int gm = tid >> 1;      // gather row
    const int gh = tid & 1;       // k-half (32 floats)

#pragma unroll 1
    for (int ch = 0; ch < 5; ch++) {
        // load A rows + B rows into regs first (overlap latency)
        const float* rowp;
        if (ch < 2)      rowp = xn + (size_t)my_snd * NODE_C + ch * 64;
        else if (ch < 4) rowp = xn + (size_t)my_rcv * NODE_C + (ch - 2) * 64;
        else             rowp = xe + (size_t)(e0 + gm) * EDGE_C;
        const float4* rp = reinterpret_cast<const float4*>(rowp) + gh * 8;
        float4 av[8];
#pragma unroll
        for (int i = 0; i < 8; i++) av[i] = rp[i];

        const int bn = tid >> 1;  // weight row n
        const uint4* gwh = reinterpret_cast<const uint4*>(g_eW1t_hi + (size_t)bn * 320 + ch * 64) + gh * 4;
        const uint4* gwl = reinterpret_cast<const uint4*>(g_eW1t_lo + (size_t)bn * 320 + ch * 64) + gh * 4;
        uint4 bvh[4], bvl[4];
#pragma unroll
        for (int i = 0; i < 4; i++) { bvh[i] = gwh[i]; bvl[i] = gwl[i]; }

        __syncthreads();   // previous chunk's MMAs done reading SMEM

        // store A (split) and B panels
#pragma unroll
        for (int i = 0; i < 4; i++) {
            uint4 hi, lo;
            split8(av[2 * i], av[2 * i + 1], hi, lo);
            uint32_t off = panel_off((uint32_t)gm, (uint32_t)(gh * 32 + i * 8));
            *(uint4*)(dsm + off)         = hi;
            *(uint4*)(dsm + 16384 + off) = lo;
        }
#pragma unroll
        for (int i = 0; i < 4; i++) {
            uint32_t off = panel_off((uint32_t)bn, (uint32_t)(gh * 32 + i * 8));
            *(uint4*)(dsm + 32768 + off) = bvh[i];
            *(uint4*)(dsm + 49152 + off) = bvl[i];
        }
        __syncthreads();

        // compute
#pragma unroll
        for (int ks = 0; ks < 4; ks++) {
            const uint32_t kb = ks * 16;
            uint32_t ah[2][4], al[2][4];
#pragma unroll
            for (int mf = 0; mf < 2; mf++) {
                uint32_t r = (uint32_t)(mw * 32 + mf * 16) + la_r;
                uint32_t po = panel_off(r, kb + la_kb);
                ldsm_x4(ah[mf], sb + po);
                ldsm_x4(al[mf], sb + 16384 + po);
            }
#pragma unroll
            for (int nf = 0; nf < 8; nf++) {
                uint32_t n = (uint32_t)(nw * 64 + nf * 8) + lb_r;
                uint32_t po = panel_off(n, kb + lb_kb);
                uint32_t bh[2], bl[2];
                ldsm_x2(bh, sb + 32768 + po);
                ldsm_x2(bl, sb + 49152 + po);
#pragma unroll
                for (int mf = 0; mf < 2; mf++) {
                    MMA16816(c[mf][nf], ah[mf], bh);
                    MMA16816(c[mf][nf], ah[mf], bl);
                    MMA16816(c[mf][nf], al[mf], bh);
                }
            }
        }
    }
    __syncthreads();

    // ------------- Epilogue1: bias + SiLU -> h split panels -------------
    {
        const int l4 = lane >> 2;
        const int l2 = (lane & 3) * 2;
        float2 bias[8];
#pragma unroll
        for (int nf = 0; nf < 8; nf++) {
            int col = nw * 64 + nf * 8 + l2;
            bias[nf].x = __ldg(eb1 + col);
            bias[nf].y = __ldg(eb1 + col + 1);
        }
        const uint32_t hbase_hi = 65536u + (uint32_t)nw * 16384u;
        const uint32_t hbase_lo = 98304u + (uint32_t)nw * 16384u;
#pragma unroll
        for (int mf = 0; mf < 2; mf++) {
            uint32_t m = (uint32_t)(mw * 32 + mf * 16 + l4);
#pragma unroll
            for (int nf = 0; nf < 8; nf++) {
                uint32_t k = (uint32_t)(nf * 8 + l2);
                float x0 = silu_f(c[mf][nf][0] + bias[nf].x);
                float x1 = silu_f(c[mf][nf][1] + bias[nf].y);
                float x2 = silu_f(c[mf][nf][2] + bias[nf].x);
                float x3 = silu_f(c[mf][nf][3] + bias[nf].y);
                float h0 = h_round(x0), h1 = h_round(x1);
                float h2 = h_round(x2), h3 = h_round(x3);
                uint32_t o0 = panel_off(m, k);
                uint32_t o1 = panel_off(m + 8, k);
                *(uint32_t*)(dsm + hbase_hi + o0) = f16x2(h0, h1);
                *(uint32_t*)(dsm + hbase_lo + o0) = f16x2(x0 - h0, x1 - h1);
                *(uint32_t*)(dsm + hbase_hi + o1) = f16x2(h2, h3);
                *(uint32_t*)(dsm + hbase_lo + o1) = f16x2(x2 - h2, x3 - h3);
            }
        }
    }
    // load B2 = eW2t [64][128] -> panels at 0(hi p0), 8K(hi p1), 16K(lo p0), 24K(lo p1)
    {
        const int n = tid >> 2;
        const int q = tid & 3;
        const uint4* gwh = reinterpret_cast<const uint4*>(g_eW2t_hi + (size_t)n * 128);
        const uint4* gwl = reinterpret_cast<const uint4*>(g_eW2t_lo + (size_t)n * 128);
#pragma unroll
        for (int p = 0; p < 2; p++) {
#pragma unroll
            for (int j = 0; j < 2; j++) {
                int b = q * 2 + j;
                uint32_t off = (uint32_t)(p * 8192) + panel_off((uint32_t)n, (uint32_t)(b * 8));
                *(uint4*)(dsm + off)         = gwh[p * 8 + b];
                *(uint4*)(dsm + 16384 + off) = gwl[p * 8 + b];
            }
        }
    }
    __syncthreads();

    // ---------------- GEMM2: h[128,128] @ eW2t^T -> [128,64] ----------------
    float c2[2][4][4];
#pragma unroll
    for (int a = 0; a < 2; a++)
#pragma unroll
        for (int b = 0; b < 4; b++)
#pragma unroll
            for (int d = 0; d < 4; d++) c2[a][b][d] = 0.f;

#pragma unroll
    for (int p = 0; p < 2; p++) {
        const uint32_t Ah = sb + 65536u + (uint32_t)p * 16384u;
        const uint32_t Al = sb + 98304u + (uint32_t)p * 16384u;
        const uint32_t Bh = sb + (uint32_t)p * 8192u;
        const uint32_t Bl = sb + 16384u + (uint32_t)p * 8192u;
#pragma unroll
        for (int ks = 0; ks < 4; ks++) {
            const uint32_t kb = ks * 16;
            uint32_t ah[2][4], al[2][4];
#pragma unroll
            for (int mf = 0; mf < 2; mf++) {
                uint32_t r = (uint32_t)(mw * 32 + mf * 16) + la_r;
                uint32_t po = panel_off(r, kb + la_kb);
                ldsm_x4(ah[mf], Ah + po);
                ldsm_x4(al[mf], Al + po);
            }
#pragma unroll
            for (int nf = 0; nf < 4; nf++) {
                uint32_t n = (uint32_t)(nw * 32 + nf * 8) + lb_r;
                uint32_t po = panel_off(n, kb + lb_kb);
                uint32_t bh[2], bl[2];
                ldsm_x2(bh, Bh + po);
                ldsm_x2(bl, Bl + po);
#pragma unroll
                for (int mf = 0; mf < 2; mf++) {
                    MMA16816(c2[mf][nf], ah[mf], bh);
                    MMA16816(c2[mf][nf], ah[mf], bl);
                    MMA16816(c2[mf][nf], al[mf], bh);
                }
            }
        }
    }

    // ------------- Epilogue2: SiLU, store edges_out, scatter-add -------------
    {
        const int l4 = lane >> 2;
        const int l2 = (lane & 3) * 2;
        float2 bias[4];
#pragma unroll
        for (int nf = 0; nf < 4; nf++) {
            int col = nw * 32 + nf * 8 + l2;
            bias[nf].x = __ldg(eb2 + col);
            bias[nf].y = __ldg(eb2 + col + 1);
        }
#pragma unroll
        for (int mf = 0; mf < 2; mf++) {
            int m0r = mw * 32 + mf * 16 + l4;
#pragma unroll
            for (int half = 0; half < 2; half++) {
                int m = m0r + half * 8;
                int rcv = s_rcv[m];
                float* orow = edges_out + (size_t)(e0 + m) * EDGE_C;
                float* arow = g_aggr + (size_t)rcv * EDGE_C;
#pragma unroll
                for (int nf = 0; nf < 4; nf++) {
                    int col = nw * 32 + nf * 8 + l2;
                    float o0 = silu_f(c2[mf][nf][half * 2]     + bias[nf].x);
                    float o1 = silu_f(c2[mf][nf][half * 2 + 1] + bias[nf].y);
                    float2 ov = {o0, o1};
                    *reinterpret_cast<float2*>(orow + col) = ov;
                    atomicAdd(arow + col, o0);
                    atomicAdd(arow + col + 1, o1);
                }
            }
        }
    }
}

// ---------------------------------------------------------------------------
// Node kernel: 128 nodes / CTA
//   GEMM1 [128,192]@[192,128] (3 chunks) -> SiLU -> GEMM2 [128,128]@[128,128]
// ---------------------------------------------------------------------------
__global__ __launch_bounds__(256, 1)
void node_mma_kernel(const float* __restrict__ xn,
                     const float* __restrict__ nb1,
                     const float* __restrict__ nb2,
                     float* __restrict__ nodes_out)
{
    extern __shared__ __align__(1024) char dsm[];

    const int tid  = threadIdx.x;
    const int wid  = tid >> 5;
    const int lane = tid & 31;
    const int mw   = wid & 3;
    const int nw   = wid >> 2;
    const int m0   = blockIdx.x * 128;

    const uint32_t sb = smem_u32(dsm);
    const uint32_t la_r  = lane & 15;
    const uint32_t la_kb = (lane >> 4) << 3;
    const uint32_t lb_r  = lane & 7;
    const uint32_t lb_kb = ((lane >> 3) & 1) << 3;

    float c[2][8][4];
#pragma unroll
    for (int a = 0; a < 2; a++)
#pragma unroll
        for (int b = 0; b < 8; b++)
#pragma unroll
            for (int d = 0; d < 4; d++) c[a][b][d] = 0.f;

    const int gm = tid >> 1;
    const int gh = tid & 1;
    const size_t grow = (size_t)m0 + gm;
    const bool gvalid = grow < N_NODES;

#pragma unroll 1
    for (int ch = 0; ch < 3; ch++) {
        const float* rowp = (ch < 2) ? xn + grow * NODE_C + ch * 64
                                     : g_aggr + grow * EDGE_C;
        const float4* rp = reinterpret_cast<const float4*>(rowp) + gh * 8;
        float4 av[8];
#pragma unroll
        for (int i = 0; i < 8; i++)
            av[i] = gvalid ? rp[i] : make_float4(0.f, 0.f, 0.f, 0.f);

        const int bn = tid >> 1;
        const uint4* gwh = reinterpret_cast<const uint4*>(g_nW1t_hi + (size_t)bn * 192 + ch * 64) + gh * 4;
        const uint4* gwl = reinterpret_cast<const uint4*>(g_nW1t_lo + (size_t)bn * 192 + ch * 64) + gh * 4;
        uint4 bvh[4], bvl[4];
#pragma unroll
        for (int i = 0; i < 4; i++) { bvh[i] = gwh[i]; bvl[i] = gwl[i]; }

        __syncthreads();
#pragma unroll
        for (int i = 0; i < 4; i++) {
            uint4 hi, lo;
            split8(av[2 * i], av[2 * i + 1], hi, lo);
            uint32_t off = panel_off((uint32_t)gm, (uint32_t)(gh * 32 + i * 8));
            *(uint4*)(dsm + off)         = hi;
            *(uint4*)(dsm + 16384 + off) = lo;
        }
#pragma unroll
        for (int i = 0; i < 4; i++) {
            uint32_t off = panel_off((uint32_t)bn, (uint32_t)(gh * 32 + i * 8));
            *(uint4*)(dsm + 32768 + off) = bvh[i];
            *(uint4*)(dsm + 49152 + off) = bvl[i];
        }
        __syncthreads();

#pragma unroll
        for (int ks = 0; ks < 4; ks++) {
            const uint32_t kb = ks * 16;
            uint32_t ah[2][4], al[2][4];
#pragma unroll
            for (int mf = 0; mf < 2; mf++) {
                uint32_t r = (uint32_t)(mw * 32 + mf * 16) + la_r;
                uint32_t po = panel_off(r, kb + la_kb);
                ldsm_x4(ah[mf], sb + po);
                ldsm_x4(al[mf], sb + 16384 + po);
            }
#pragma unroll
            for (int nf = 0; nf < 8; nf++) {
                uint32_t n = (uint32_t)(nw * 64 + nf * 8) + lb_r;
                uint32_t po = panel_off(n, kb + lb_kb);
                uint32_t bh[2], bl[2];
                ldsm_x2(bh, sb + 32768 + po);
                ldsm_x2(bl, sb + 49152 + po);
#pragma unroll
                for (int mf = 0; mf < 2; mf++) {
                    MMA16816(c[mf][nf], ah[mf], bh);
                    MMA16816(c[mf][nf], ah[mf], bl);
                    MMA16816(c[mf][nf], al[mf], bh);
                }
            }
        }
    }
    __syncthreads();

    // Epilogue1: bias + SiLU -> h split
    {
        const int l4 = lane >> 2;
        const int l2 = (lane & 3) * 2;
        float2 bias[8];
#pragma unroll
        for (int nf = 0; nf < 8; nf++) {
            int col = nw * 64 + nf * 8 + l2;
            bias[nf].x = __ldg(nb1 + col);
            bias[nf].y = __ldg(nb1 + col + 1);
        }
        const uint32_t hbase_hi = 65536u + (uint32_t)nw * 16384u;
        const uint32_t hbase_lo = 98304u + (uint32_t)nw * 16384u;
#pragma unroll
        for (int mf = 0; mf < 2; mf++) {
            uint32_t m = (uint32_t)(mw * 32 + mf * 16 + l4);
#pragma unroll
            for (int nf = 0; nf < 8; nf++) {
                uint32_t k = (uint32_t)(nf * 8 + l2);
                float x0 = silu_f(c[mf][nf][0] + bias[nf].x);
                float x1 = silu_f(c[mf][nf][1] + bias[nf].y);
                float x2 = silu_f(c[mf][nf][2] + bias[nf].x);
                float x3 = silu_f(c[mf][nf][3] + bias[nf].y);
                float h0 = h_round(x0), h1 = h_round(x1);
                float h2 = h_round(x2), h3 = h_round(x3);
                uint32_t o0 = panel_off(m, k);
                uint32_t o1 = panel_off(m + 8, k);
                *(uint32_t*)(dsm + hbase_hi + o0) = f16x2(h0, h1);
                *(uint32_t*)(dsm + hbase_lo + o0) = f16x2(x0 - h0, x1 - h1);
                *(uint32_t*)(dsm + hbase_hi + o1) = f16x2(h2, h3);
                *(uint32_t*)(dsm + hbase_lo + o1) = f16x2(x2 - h2, x3 - h3);
            }
        }
    }
    // B2 = nW2t [128][128] -> hi p0@0, p1@16K, lo p0@32K, p1@48K
    {
        const int n = tid >> 1;
        const int hh = tid & 1;
        const uint4* gwh = reinterpret_cast<const uint4*>(g_nW2t_hi + (size_t)n * 128);
        const uint4* gwl = reinterpret_cast<const uint4*>(g_nW2t_lo + (size_t)n * 128);
#pragma unroll
        for (int p = 0; p < 2; p++) {
#pragma unroll
            for (int j = 0; j < 4; j++) {
                int b = hh * 4 + j;
                uint32_t off = (uint32_t)(p * 16384) + panel_off((uint32_t)n, (uint32_t)(b * 8));
                *(uint4*)(dsm + off)         = gwh[p * 8 + b];
                *(uint4*)(dsm + 32768 + off) = gwl[p * 8 + b];
            }
        }
    }
    __syncthreads();

    // GEMM2: [128,128]@[128,128]
    float c2[2][8][4];
#pragma unroll
    for (int a = 0; a < 2; a++)
#pragma unroll
        for (int b = 0; b < 8; b++)
#pragma unroll
            for (int d = 0; d < 4; d++) c2[a][b][d] = 0.f;

#pragma unroll
    for (int p = 0; p < 2; p++) {
        const uint32_t Ah = sb + 65536u + (uint32_t)p * 16384u;
        const uint32_t Al = sb + 98304u + (uint32_t)p * 16384u;
        const uint32_t Bh = sb + (uint32_t)p * 16384u;
        const uint32_t Bl = sb + 32768u + (uint32_t)p * 16384u;
#pragma unroll
        for (int ks = 0; ks < 4; ks++) {
            const uint32_t kb = ks * 16;
            uint32_t ah[2][4], al[2][4];
#pragma unroll
            for (int mf = 0; mf < 2; mf++) {
                uint32_t r = (uint32_t)(mw * 32 + mf * 16) + la_r;
                uint32_t po = panel_off(r, kb + la_kb);
                ldsm_x4(ah[mf], Ah + po);
                ldsm_x4(al[mf], Al + po);
            }
#pragma unroll
            for (int nf = 0; nf < 8; nf++) {
                uint32_t n = (uint32_t)(nw * 64 + nf * 8) + lb_r;
                uint32_t po = panel_off(n, kb + lb_kb);
                uint32_t bh[2], bl[2];
                ldsm_x2(bh, Bh + po);
                ldsm_x2(bl, Bl + po);
#pragma unroll
                for (int mf = 0; mf < 2; mf++) {
                    MMA16816(c2[mf][nf], ah[mf], bh);
                    MMA16816(c2[mf][nf], ah[mf], bl);
                    MMA16816(c2[mf][nf], al[mf], bh);
                }
            }
        }
    }

    // Epilogue2: + bias, store
    {
        const int l4 = lane >> 2;
        const int l2 = (lane & 3) * 2;
        float2 bias[8];
#pragma unroll
        for (int nf = 0; nf < 8; nf++) {
            int col = nw * 64 + nf * 8 + l2;
            bias[nf].x = __ldg(nb2 + col);
            bias[nf].y = __ldg(nb2 + col + 1);
        }
#pragma unroll
        for (int mf = 0; mf < 2; mf++) {
#pragma unroll
            for (int half = 0; half < 2; half++) {
                size_t m = (size_t)(mw * 32 + mf * 16 + l4 + half * 8);
                size_t row = (size_t)m0 + m;
                if (row < N_NODES) {
                    float* orow = nodes_out + row * NODE_C;
#pragma unroll
                    for (int nf = 0; nf < 8; nf++) {
                        int col = nw * 64 + nf * 8 + l2;
                        float2 ov;
                        ov.x = c2[mf][nf][half * 2]     + bias[nf].x;
                        ov.y = c2[mf][nf][half * 2 + 1] + bias[nf].y;
                        *reinterpret_cast<float2*>(orow + col) = ov;
                    }
                }
            }
        }
    }
}

// ---------------------------------------------------------------------------
extern "C" void kernel_launch(void* const* d_in, const int* in_sizes, int n_in,
                              void* d_out, int out_size)
{
    const float* xn   = (const float*)d_in[0];
    const float* xe   = (const float*)d_in[1];
    const void*  eidx =               d_in[2];
    const float* eW1  = (const float*)d_in[3];
    const float* eb1  = (const float*)d_in[4];
    const float* eW2  = (const float*)d_in[5];
    const float* eb2  = (const float*)d_in[6];
    const float* nW1  = (const float*)d_in[7];
    const float* nb1  = (const float*)d_in[8];
    const float* nW2  = (const float*)d_in[9];
    const float* nb2  = (const float*)d_in[10];

    float* nodes_out = (float*)d_out;
    float* edges_out = (float*)d_out + (size_t)N_NODES * NODE_C;

    cudaFuncSetAttribute(edge_mma_kernel, cudaFuncAttributeMaxDynamicSharedMemorySize, SMEM_BYTES);
    cudaFuncSetAttribute(node_mma_kernel, cudaFuncAttributeMaxDynamicSharedMemorySize, SMEM_BYTES);

    prep_weights_kernel<<<160, 256>>>(eW1, eW2, nW1, nW2);
    zero_aggr_kernel<<<(N_NODES * EDGE_C / 4 + 255) / 256, 256>>>();
    edge_mma_kernel<<<N_EDGES / 128, 256, SMEM_BYTES>>>(xn, xe, eidx, eb1, eb2, edges_out);
    node_mma_kernel<<<(N_NODES + 127) / 128, 256, SMEM_BYTES>>>(xn, nb1, nb2, nodes_out);
}

// round 4
// speedup vs baseline: 2.8847x; 1.2513x over previous
#include <cuda_runtime.h>
#include <cuda_fp16.h>
#include <cstdint>

#define N_NODES 50000
#define N_EDGES 800000
#define NODE_C  128
#define EDGE_C  64

// ---------------------------------------------------------------------------
// Device scratch (no cudaMalloc allowed)
// ---------------------------------------------------------------------------
__device__ float g_aggr[(size_t)N_NODES * EDGE_C];
// Pre-transposed, fp16 hi/lo-split weights: Wt[n][k] = W[k][n]
__device__ __align__(16) __half g_eW1t_hi[128 * 320];
__device__ __align__(16) __half g_eW1t_lo[128 * 320];
__device__ __align__(16) __half g_eW2t_hi[64 * 128];
__device__ __align__(16) __half g_eW2t_lo[64 * 128];
__device__ __align__(16) __half g_nW1t_hi[128 * 192];
__device__ __align__(16) __half g_nW1t_lo[128 * 192];
__device__ __align__(16) __half g_nW2t_hi[128 * 128];
__device__ __align__(16) __half g_nW2t_lo[128 * 128];

// ---------------------------------------------------------------------------
// Helpers
// ---------------------------------------------------------------------------
__device__ __forceinline__ uint32_t smem_u32(const void* p) {
    uint32_t a;
    asm("{ .reg .u64 t; cvta.to.shared.u64 t, %1; cvt.u32.u64 %0, t; }"
        : "=r"(a) : "l"(p));
    return a;
}

// Panels: [rows][64] fp16, 128-byte rows, XOR-swizzled 16B blocks.
__device__ __forceinline__ uint32_t panel_off(uint32_t r, uint32_t k) {
    return r * 128u + ((((k >> 3) ^ (r & 7u)) << 4) | ((k & 7u) << 1));
}

__device__ __forceinline__ void ldsm_x4(uint32_t* d, uint32_t a) {
    asm volatile("ldmatrix.sync.aligned.m8n8.x4.shared.b16 {%0,%1,%2,%3}, [%4];"
                 : "=r"(d[0]), "=r"(d[1]), "=r"(d[2]), "=r"(d[3]) : "r"(a));
}
__device__ __forceinline__ void ldsm_x2(uint32_t* d, uint32_t a) {
    asm volatile("ldmatrix.sync.aligned.m8n8.x2.shared.b16 {%0,%1}, [%2];"
                 : "=r"(d[0]), "=r"(d[1]) : "r"(a));
}

#define MMA16816(c, a, b) \
    asm volatile("mma.sync.aligned.m16n8k16.row.col.f32.f16.f16.f32 " \
        "{%0,%1,%2,%3},{%4,%5,%6,%7},{%8,%9},{%0,%1,%2,%3};" \
        : "+f"((c)[0]), "+f"((c)[1]), "+f"((c)[2]), "+f"((c)[3]) \
        : "r"((a)[0]), "r"((a)[1]), "r"((a)[2]), "r"((a)[3]), \
          "r"((b)[0]), "r"((b)[1]))

__device__ __forceinline__ void cp16(uint32_t dst, const void* src) {
    asm volatile("cp.async.cg.shared.global [%0], [%1], 16;"
                 :: "r"(dst), "l"(src) : "memory");
}
#define CP_COMMIT() asm volatile("cp.async.commit_group;" ::: "memory")
#define CP_WAIT(n)  asm volatile("cp.async.wait_group %0;" :: "n"(n) : "memory")

__device__ __forceinline__ uint32_t f16x2(float lo, float hi) {
    uint32_t r;
    asm("cvt.rn.f16x2.f32 %0, %1, %2;" : "=r"(r) : "f"(hi), "f"(lo));
    return r;
}
__device__ __forceinline__ float h_round(float x) {
    return __half2float(__float2half_rn(x));
}
__device__ __forceinline__ float silu_f(float x) {
    return x / (1.0f + __expf(-x));
}
__device__ __forceinline__ void split8(float4 v0, float4 v1, uint4& hi, uint4& lo) {
    float a0 = h_round(v0.x), a1 = h_round(v0.y), a2 = h_round(v0.z), a3 = h_round(v0.w);
    float a4 = h_round(v1.x), a5 = h_round(v1.y), a6 = h_round(v1.z), a7 = h_round(v1.w);
    hi.x = f16x2(a0, a1); hi.y = f16x2(a2, a3); hi.z = f16x2(a4, a5); hi.w = f16x2(a6, a7);
    lo.x = f16x2(v0.x - a0, v0.y - a1);
    lo.y = f16x2(v0.z - a2, v0.w - a3);
    lo.z = f16x2(v1.x - a4, v1.y - a5);
    lo.w = f16x2(v1.z - a6, v1.w - a7);
}

// ---------------------------------------------------------------------------
// Setup kernels
// ---------------------------------------------------------------------------
__global__ void zero_aggr_kernel() {
    size_t i = (size_t)blockIdx.x * blockDim.x + threadIdx.x;
    size_t n4 = (size_t)N_NODES * EDGE_C / 4;
    if (i < n4) reinterpret_cast<float4*>(g_aggr)[i] = make_float4(0.f, 0.f, 0.f, 0.f);
}

__global__ void prep_weights_kernel(const float* __restrict__ eW1,
                                    const float* __restrict__ eW2,
                                    const float* __restrict__ nW1,
                                    const float* __restrict__ nW2) {
    int i = blockIdx.x * 256 + threadIdx.x;
    if (i < 128 * 320) {
        int n = i / 320, k = i % 320;
        float v = eW1[(size_t)k * 128 + n];
        float h = h_round(v);
        g_eW1t_hi[i] = __float2half_rn(h);
        g_eW1t_lo[i] = __float2half_rn(v - h);
    }
    if (i < 64 * 128) {
        int n = i / 128, k = i % 128;
        float v = eW2[(size_t)k * 64 + n];
        float h = h_round(v);
        g_eW2t_hi[i] = __float2half_rn(h);
        g_eW2t_lo[i] = __float2half_rn(v - h);
    }
    if (i < 128 * 192) {
        int n = i / 192, k = i % 192;
        float v = nW1[(size_t)k * 128 + n];
        float h = h_round(v);
        g_nW1t_hi[i] = __float2half_rn(h);
        g_nW1t_lo[i] = __float2half_rn(v - h);
    }
    if (i < 128 * 128) {
        int n = i / 128, k = i % 128;
        float v = nW2[(size_t)k * 128 + n];
        float h = h_round(v);
        g_nW2t_hi[i] = __float2half_rn(h);
        g_nW2t_lo[i] = __float2half_rn(v - h);
    }
}

// ---------------------------------------------------------------------------
// Edge kernel: 128 edges / CTA, 512 threads (16 warps: 4 M-strips x 4 N-strips)
// SMEM (96KB dynamic):
//   GEMM1: A_hi@0, A_lo@16K, Bbuf0 hi@32K lo@48K, Bbuf1 hi@64K lo@80K
//   After: h_hi p0@0 p1@16K, h_lo p0@32K p1@48K,
//          B2 hi p0@64K p1@72K, lo p0@80K p1@88K  (prefetched during last chunk)
// ---------------------------------------------------------------------------
#define EDGE_SMEM 98304
#define NODE_SMEM 131072

__global__ __launch_bounds__(512, 1)
void edge_mma_kernel(const float* __restrict__ xn,
                     const float* __restrict__ xe,
                     const void*  __restrict__ eidx,
                     const float* __restrict__ eb1,
                     const float* __restrict__ eb2,
                     float* __restrict__ edges_out)
{
    extern __shared__ __align__(1024) char dsm[];
    __shared__ int s_snd[128], s_rcv[128];

    const int tid  = threadIdx.x;
    const int wid  = tid >> 5;
    const int lane = tid & 31;
    const int mw   = wid & 3;      // 32-row strip
    const int nw   = wid >> 2;     // 32-col strip (GEMM1) / 16-col (GEMM2)
    const int e0   = blockIdx.x * 128;

    const uint32_t sb = smem_u32(dsm);
    const uint32_t la_r  = lane & 15;
    const uint32_t la_kb = (lane >> 4) << 3;
    const uint32_t lb_r  = lane & 7;
    const uint32_t lb_kb = ((lane >> 3) & 1) << 3;

    // edge indices
    {
        const unsigned* w = reinterpret_cast<const unsigned*>(eidx);
        const bool is64 = ((w[1] | w[3] | w[5] | w[7] | w[9] | w[11] | w[13] | w[15]) == 0u);
        if (tid < 128) {
            size_t e = (size_t)e0 + tid;
            if (is64) {
                const long long* p = reinterpret_cast<const long long*>(eidx);
                s_snd[tid] = (int)p[e];
                s_rcv[tid] = (int)p[(size_t)N_EDGES + e];
            } else {
                const int* p = reinterpret_cast<const int*>(eidx);
                s_snd[tid] = p[e];
                s_rcv[tid] = p[(size_t)N_EDGES + e];
            }
        }
    }
    __syncthreads();

    const int gm = tid >> 2;      // gather row (0..127)
    const int gq = tid & 3;       // 16-float quarter of the 64-k chunk
    const int bn = tid >> 2;      // weight row
    const int bq = tid & 3;

    // --- prefetch chunk 0: B via cp.async, A via LDG into regs ---
    {
        const __half* shi = g_eW1t_hi + (size_t)bn * 320 + bq * 16;
        const __half* slo = g_eW1t_lo + (size_t)bn * 320 + bq * 16;
#pragma unroll
        for (int j = 0; j < 2; j++) {
            uint32_t off = panel_off((uint32_t)bn, (uint32_t)(bq * 16 + j * 8));
            cp16(sb + 32768u + off, shi + j * 8);
            cp16(sb + 49152u + off, slo + j * 8);
        }
        CP_COMMIT();
    }
    float4 av[4];
    {
        const float* rowp = xn + (size_t)s_snd[gm] * NODE_C;
        const float4* rp = reinterpret_cast<const float4*>(rowp) + gq * 4;
#pragma unroll
        for (int i = 0; i < 4; i++) av[i] = rp[i];
    }

    float c[2][4][4];
#pragma unroll
    for (int a = 0; a < 2; a++)
#pragma unroll
        for (int b = 0; b < 4; b++)
#pragma unroll
            for (int d = 0; d < 4; d++) c[a][b][d] = 0.f;

    // ---------------- GEMM1: 5 K-chunks of 64 ----------------
#pragma unroll 1
    for (int ch = 0; ch < 5; ch++) {
        __syncthreads();   // prev MMAs done with A panel & next B buffer
        // store A (split)
#pragma unroll
        for (int i = 0; i < 2; i++) {
            uint4 hi, lo;
            split8(av[2 * i], av[2 * i + 1], hi, lo);
            uint32_t off = panel_off((uint32_t)gm, (uint32_t)(gq * 16 + i * 8));
            *(uint4*)(dsm + off)         = hi;
            *(uint4*)(dsm + 16384 + off) = lo;
        }
        if (ch < 4) {
            // prefetch next B chunk + next A rows
            const int nc = ch + 1;
            uint32_t dhi = 32768u + (uint32_t)((nc & 1) * 32768);
            const __half* shi = g_eW1t_hi + (size_t)bn * 320 + nc * 64 + bq * 16;
            const __half* slo = g_eW1t_lo + (size_t)bn * 320 + nc * 64 + bq * 16;
#pragma unroll
            for (int j = 0; j < 2; j++) {
                uint32_t off = panel_off((uint32_t)bn, (uint32_t)(bq * 16 + j * 8));
                cp16(sb + dhi + off, shi + j * 8);
                cp16(sb + dhi + 16384u + off, slo + j * 8);
            }
            CP_COMMIT();
            const float* rowp;
            if (nc < 2)      rowp = xn + (size_t)s_snd[gm] * NODE_C + nc * 64;
            else if (nc < 4) rowp = xn + (size_t)s_rcv[gm] * NODE_C + (nc - 2) * 64;
            else             rowp = xe + (size_t)(e0 + gm) * EDGE_C;
            const float4* rp = reinterpret_cast<const float4*>(rowp) + gq * 4;
#pragma unroll
            for (int i = 0; i < 4; i++) av[i] = rp[i];
        } else {
            // prefetch B2 (eW2t 64x128) into [64K..96K): hi p0@64K p1@72K, lo p0@80K p1@88K
            const int n2 = tid >> 3;
            const int q2 = tid & 7;
            const __half* shi = g_eW2t_hi + (size_t)n2 * 128;
            const __half* slo = g_eW2t_lo + (size_t)n2 * 128;
#pragma unroll
            for (int j = 0; j < 2; j++) {
                int seg = q2 * 2 + j;
                uint32_t p = (uint32_t)(seg >> 3);
                uint32_t off = p * 8192u + panel_off((uint32_t)n2, (uint32_t)((seg & 7) * 8));
                cp16(sb + 65536u + off, shi + seg * 8);
                cp16(sb + 81920u + off, slo + seg * 8);
            }
            CP_COMMIT();
        }
        CP_WAIT(1);        // current chunk's B arrived
        __syncthreads();

        const uint32_t Bhi = sb + 32768u + (uint32_t)((ch & 1) * 32768);
        const uint32_t Blo = Bhi + 16384u;
#pragma unroll
        for (int ks = 0; ks < 4; ks++) {
            const uint32_t kb = ks * 16;
            uint32_t ah[2][4], al[2][4];
#pragma unroll
            for (int mf = 0; mf < 2; mf++) {
                uint32_t r = (uint32_t)(mw * 32 + mf * 16) + la_r;
                uint32_t po = panel_off(r, kb + la_kb);
                ldsm_x4(ah[mf], sb + po);
                ldsm_x4(al[mf], sb + 16384u + po);
            }
#pragma unroll
            for (int nf = 0; nf < 4; nf++) {
                uint32_t n = (uint32_t)(nw * 32 + nf * 8) + lb_r;
                uint32_t po = panel_off(n, kb + lb_kb);
                uint32_t bh[2], bl[2];
                ldsm_x2(bh, Bhi + po);
                ldsm_x2(bl, Blo + po);
#pragma unroll
                for (int mf = 0; mf < 2; mf++) {
                    MMA16816(c[mf][nf], ah[mf], bh);
                    MMA16816(c[mf][nf], ah[mf], bl);
                    MMA16816(c[mf][nf], al[mf], bh);
                }
            }
        }
    }
    __syncthreads();

    // ------------- Epilogue1: bias + SiLU -> h split panels (reuse [0..64K)) -------------
    {
        const int l4 = lane >> 2;
        const int l2 = (lane & 3) * 2;
        const uint32_t p = (uint32_t)(nw >> 1);
        const uint32_t hb_hi = p * 16384u;
        const uint32_t hb_lo = 32768u + p * 16384u;
#pragma unroll
        for (int nf = 0; nf < 4; nf++) {
            int col = nw * 32 + nf * 8 + l2;
            float b0 = __ldg(eb1 + col), b1 = __ldg(eb1 + col + 1);
            uint32_t kk = (uint32_t)((nw & 1) * 32 + nf * 8 + l2);
#pragma unroll
            for (int mf = 0; mf < 2; mf++) {
                uint32_t m = (uint32_t)(mw * 32 + mf * 16 + l4);
                float x0 = silu_f(c[mf][nf][0] + b0);
                float x1 = silu_f(c[mf][nf][1] + b1);
                float x2 = silu_f(c[mf][nf][2] + b0);
                float x3 = silu_f(c[mf][nf][3] + b1);
                float h0 = h_round(x0), h1 = h_round(x1);
                float h2 = h_round(x2), h3 = h_round(x3);
                uint32_t o0 = panel_off(m, kk);
                uint32_t o1 = panel_off(m + 8, kk);
                *(uint32_t*)(dsm + hb_hi + o0) = f16x2(h0, h1);
                *(uint32_t*)(dsm + hb_lo + o0) = f16x2(x0 - h0, x1 - h1);
                *(uint32_t*)(dsm + hb_hi + o1) = f16x2(h2, h3);
                *(uint32_t*)(dsm + hb_lo + o1) = f16x2(x2 - h2, x3 - h3);
            }
        }
    }
    CP_WAIT(0);            // B2 arrived
    __syncthreads();

    // ---------------- GEMM2: h[128,128] @ eW2t^T -> [128,64] ----------------
    float c2[2][2][4];
#pragma unroll
    for (int a = 0; a < 2; a++)
#pragma unroll
        for (int b = 0; b < 2; b++)
#pragma unroll
            for (int d = 0; d < 4; d++) c2[a][b][d] = 0.f;

#pragma unroll
    for (int p = 0; p < 2; p++) {
        const uint32_t Ah = sb + (uint32_t)p * 16384u;
        const uint32_t Al = sb + 32768u + (uint32_t)p * 16384u;
        const uint32_t Bh = sb + 65536u + (uint32_t)p * 8192u;
        const uint32_t Bl = sb + 81920u + (uint32_t)p * 8192u;
#pragma unroll
        for (int ks = 0; ks < 4; ks++) {
            const uint32_t kb = ks * 16;
            uint32_t ah[2][4], al[2][4];
#pragma unroll
            for (int mf = 0; mf < 2; mf++) {
                uint32_t r = (uint32_t)(mw * 32 + mf * 16) + la_r;
                uint32_t po = panel_off(r, kb + la_kb);
                ldsm_x4(ah[mf], Ah + po);
                ldsm_x4(al[mf], Al + po);
            }
#pragma unroll
            for (int nf = 0; nf < 2; nf++) {
                uint32_t n = (uint32_t)(nw * 16 + nf * 8) + lb_r;
                uint32_t po = panel_off(n, kb + lb_kb);
                uint32_t bh[2], bl[2];
                ldsm_x2(bh, Bh + po);
                ldsm_x2(bl, Bl + po);
#pragma unroll
                for (int mf = 0; mf < 2; mf++) {
                    MMA16816(c2[mf][nf], ah[mf], bh);
                    MMA16816(c2[mf][nf], ah[mf], bl);
                    MMA16816(c2[mf][nf], al[mf], bh);
                }
            }
        }
    }

    // ------------- Epilogue2: SiLU, store, scatter-add -------------
    {
        const int l4 = lane >> 2;
        const int l2 = (lane & 3) * 2;
        float b0[2], b1[2];
#pragma unroll
        for (int nf = 0; nf < 2; nf++) {
            int col = nw * 16 + nf * 8 + l2;
            b0[nf] = __ldg(eb2 + col);
            b1[nf] = __ldg(eb2 + col + 1);
        }
#pragma unroll
        for (int mf = 0; mf < 2; mf++) {
#pragma unroll
            for (int half = 0; half < 2; half++) {
                int m = mw * 32 + mf * 16 + l4 + half * 8;
                int rcv = s_rcv[m];
                float* orow = edges_out + (size_t)(e0 + m) * EDGE_C;
                float* arow = g_aggr + (size_t)rcv * EDGE_C;
#pragma unroll
                for (int nf = 0; nf < 2; nf++) {
                    int col = nw * 16 + nf * 8 + l2;
                    float o0 = silu_f(c2[mf][nf][half * 2]     + b0[nf]);
                    float o1 = silu_f(c2[mf][nf][half * 2 + 1] + b1[nf]);
                    float2 ov = {o0, o1};
                    *reinterpret_cast<float2*>(orow + col) = ov;
                    atomicAdd(arow + col,     o0);
                    atomicAdd(arow + col + 1, o1);
                }
            }
        }
    }
}

// ---------------------------------------------------------------------------
// Node kernel: 128 nodes / CTA, 512 threads
// SMEM (128KB): GEMM1 as edge; h@[0..64K); B2 hi p0@64K p1@80K, lo p0@96K p1@112K
// ---------------------------------------------------------------------------
__global__ __launch_bounds__(512, 1)
void node_mma_kernel(const float* __restrict__ xn,
                     const float* __restrict__ nb1,
                     const float* __restrict__ nb2,
                     float* __restrict__ nodes_out)
{
    extern __shared__ __align__(1024) char dsm[];

    const int tid  = threadIdx.x;
    const int wid  = tid >> 5;
    const int lane = tid & 31;
    const int mw   = wid & 3;
    const int nw   = wid >> 2;
    const int m0   = blockIdx.x * 128;

    const uint32_t sb = smem_u32(dsm);
    const uint32_t la_r  = lane & 15;
    const uint32_t la_kb = (lane >> 4) << 3;
    const uint32_t lb_r  = lane & 7;
    const uint32_t lb_kb = ((lane >> 3) & 1) << 3;

    const int gm = tid >> 2;
    const int gq = tid & 3;
    const int bn = tid >> 2;
    const int bq = tid & 3;
    const size_t grow = (size_t)m0 + gm;
    const bool gvalid = grow < N_NODES;

    // prefetch chunk 0
    {
        const __half* shi = g_nW1t_hi + (size_t)bn * 192 + bq * 16;
        const __half* slo = g_nW1t_lo + (size_t)bn * 192 + bq * 16;
#pragma unroll
        for (int j = 0; j < 2; j++) {
            uint32_t off = panel_off((uint32_t)bn, (uint32_t)(bq * 16 + j * 8));
            cp16(sb + 32768u + off, shi + j * 8);
            cp16(sb + 49152u + off, slo + j * 8);
        }
        CP_COMMIT();
    }
    float4 av[4];
    {
        const float4* rp = reinterpret_cast<const float4*>(xn + grow * NODE_C) + gq * 4;
#pragma unroll
        for (int i = 0; i < 4; i++)
            av[i] = gvalid ? rp[i] : make_float4(0.f, 0.f, 0.f, 0.f);
    }

    float c[2][4][4];
#pragma unroll
    for (int a = 0; a < 2; a++)
#pragma unroll
        for (int b = 0; b < 4; b++)
#pragma unroll
            for (int d = 0; d < 4; d++) c[a][b][d] = 0.f;

#pragma unroll 1
    for (int ch = 0; ch < 3; ch++) {
        __syncthreads();
#pragma unroll
        for (int i = 0; i < 2; i++) {
            uint4 hi, lo;
            split8(av[2 * i], av[2 * i + 1], hi, lo);
            uint32_t off = panel_off((uint32_t)gm, (uint32_t)(gq * 16 + i * 8));
            *(uint4*)(dsm + off)         = hi;
            *(uint4*)(dsm + 16384 + off) = lo;
        }
        if (ch < 2) {
            const int nc = ch + 1;
            uint32_t dhi = 32768u + (uint32_t)((nc & 1) * 32768);
            const __half* shi = g_nW1t_hi + (size_t)bn * 192 + nc * 64 + bq * 16;
            const __half* slo = g_nW1t_lo + (size_t)bn * 192 + nc * 64 + bq * 16;
#pragma unroll
            for (int j = 0; j < 2; j++) {
                uint32_t off = panel_off((uint32_t)bn, (uint32_t)(bq * 16 + j * 8));
                cp16(sb + dhi + off, shi + j * 8);
                cp16(sb + dhi + 16384u + off, slo + j * 8);
            }
            CP_COMMIT();
            const float* rowp = (nc < 2) ? xn + grow * NODE_C + nc * 64
                                         : g_aggr + grow * EDGE_C;
            const float4* rp = reinterpret_cast<const float4*>(rowp) + gq * 4;
#pragma unroll
            for (int i = 0; i < 4; i++)
                av[i] = gvalid ? rp[i] : make_float4(0.f, 0.f, 0.f, 0.f);
        } else {
            // prefetch B2 (nW2t 128x128): hi p0@64K p1@80K, lo p0@96K p1@112K
            const __half* shi = g_nW2t_hi + (size_t)bn * 128;
            const __half* slo = g_nW2t_lo + (size_t)bn * 128;
#pragma unroll
            for (int j = 0; j < 4; j++) {
                int seg = bq * 4 + j;
                uint32_t p = (uint32_t)(seg >> 3);
                uint32_t off = p * 16384u + panel_off((uint32_t)bn, (uint32_t)((seg & 7) * 8));
                cp16(sb + 65536u + off, shi + seg * 8);
                cp16(sb + 98304u + off, slo + seg * 8);
            }
            CP_COMMIT();
        }
        CP_WAIT(1);
        __syncthreads();

        const uint32_t Bhi = sb + 32768u + (uint32_t)((ch & 1) * 32768);
        const uint32_t Blo = Bhi + 16384u;
#pragma unroll
        for (int ks = 0; ks < 4; ks++) {
            const uint32_t kb = ks * 16;
            uint32_t ah[2][4], al[2][4];
#pragma unroll
            for (int mf = 0; mf < 2; mf++) {
                uint32_t r = (uint32_t)(mw * 32 + mf * 16) + la_r;
                uint32_t po = panel_off(r, kb + la_kb);
                ldsm_x4(ah[mf], sb + po);
                ldsm_x4(al[mf], sb + 16384u + po);
            }
#pragma unroll
            for (int nf = 0; nf < 4; nf++) {
                uint32_t n = (uint32_t)(nw * 32 + nf * 8) + lb_r;
                uint32_t po = panel_off(n, kb + lb_kb);
                uint32_t bh[2], bl[2];
                ldsm_x2(bh, Bhi + po);
                ldsm_x2(bl, Blo + po);
#pragma unroll
                for (int mf = 0; mf < 2; mf++) {
                    MMA16816(c[mf][nf], ah[mf], bh);
                    MMA16816(c[mf][nf], ah[mf], bl);
                    MMA16816(c[mf][nf], al[mf], bh);
                }
            }
        }
    }
    __syncthreads();

    // Epilogue1: bias + SiLU -> h split
    {
        const int l4 = lane >> 2;
        const int l2 = (lane & 3) * 2;
        const uint32_t p = (uint32_t)(nw >> 1);
        const uint32_t hb_hi = p * 16384u;
        const uint32_t hb_lo = 32768u + p * 16384u;
#pragma unroll
        for (int nf = 0; nf < 4; nf++) {
            int col = nw * 32 + nf * 8 + l2;
            float b0 = __ldg(nb1 + col), b1 = __ldg(nb1 + col + 1);
            uint32_t kk = (uint32_t)((nw & 1) * 32 + nf * 8 + l2);
#pragma unroll
            for (int mf = 0; mf < 2; mf++) {
                uint32_t m = (uint32_t)(mw * 32 + mf * 16 + l4);
                float x0 = silu_f(c[mf][nf][0] + b0);
                float x1 = silu_f(c[mf][nf][1] + b1);
                float x2 = silu_f(c[mf][nf][2] + b0);
                float x3 = silu_f(c[mf][nf][3] + b1);
                float h0 = h_round(x0), h1 = h_round(x1);
                float h2 = h_round(x2), h3 = h_round(x3);
                uint32_t o0 = panel_off(m, kk);
                uint32_t o1 = panel_off(m + 8, kk);
                *(uint32_t*)(dsm + hb_hi + o0) = f16x2(h0, h1);
                *(uint32_t*)(dsm + hb_lo + o0) = f16x2(x0 - h0, x1 - h1);
                *(uint32_t*)(dsm + hb_hi + o1) = f16x2(h2, h3);
                *(uint32_t*)(dsm + hb_lo + o1) = f16x2(x2 - h2, x3 - h3);
            }
        }
    }
    CP_WAIT(0);
    __syncthreads();

    // GEMM2: [128,128] @ nW2t^T -> [128,128]
    float c2[2][4][4];
#pragma unroll
    for (int a = 0; a < 2; a++)
#pragma unroll
        for (int b = 0; b < 4; b++)
#pragma unroll
            for (int d = 0; d < 4; d++) c2[a][b][d] = 0.f;

#pragma unroll
    for (int p = 0; p < 2; p++) {
        const uint32_t Ah = sb + (uint32_t)p * 16384u;
        const uint32_t Al = sb + 32768u + (uint32_t)p * 16384u;
        const uint32_t Bh = sb + 65536u + (uint32_t)p * 16384u;
        const uint32_t Bl = sb + 98304u + (uint32_t)p * 16384u;
#pragma unroll
        for (int ks = 0; ks < 4; ks++) {
            const uint32_t kb = ks * 16;
            uint32_t ah[2][4], al[2][4];
#pragma unroll
            for (int mf = 0; mf < 2; mf++) {
                uint32_t r = (uint32_t)(mw * 32 + mf * 16) + la_r;
                uint32_t po = panel_off(r, kb + la_kb);
                ldsm_x4(ah[mf], Ah + po);
                ldsm_x4(al[mf], Al + po);
            }
#pragma unroll
            for (int nf = 0; nf < 4; nf++) {
                uint32_t n = (uint32_t)(nw * 32 + nf * 8) + lb_r;
                uint32_t po = panel_off(n, kb + lb_kb);
                uint32_t bh[2], bl[2];
                ldsm_x2(bh, Bh + po);
                ldsm_x2(bl, Bl + po);
#pragma unroll
                for (int mf = 0; mf < 2; mf++) {
                    MMA16816(c2[mf][nf], ah[mf], bh);
                    MMA16816(c2[mf][nf], ah[mf], bl);
                    MMA16816(c2[mf][nf], al[mf], bh);
                }
            }
        }
    }

    // Epilogue2: + bias, store
    {
        const int l4 = lane >> 2;
        const int l2 = (lane & 3) * 2;
        float b0[4], b1[4];
#pragma unroll
        for (int nf = 0; nf < 4; nf++) {
            int col = nw * 32 + nf * 8 + l2;
            b0[nf] = __ldg(nb2 + col);
            b1[nf] = __ldg(nb2 + col + 1);
        }
#pragma unroll
        for (int mf = 0; mf < 2; mf++) {
#pragma unroll
            for (int half = 0; half < 2; half++) {
                size_t row = (size_t)m0 + mw * 32 + mf * 16 + l4 + half * 8;
                if (row < N_NODES) {
                    float* orow = nodes_out + row * NODE_C;
#pragma unroll
                    for (int nf = 0; nf < 4; nf++) {
                        int col = nw * 32 + nf * 8 + l2;
                        float2 ov;
                        ov.x = c2[mf][nf][half * 2]     + b0[nf];
                        ov.y = c2[mf][nf][half * 2 + 1] + b1[nf];
                        *reinterpret_cast<float2*>(orow + col) = ov;
                    }
                }
            }
        }
    }
}

// ---------------------------------------------------------------------------
extern "C" void kernel_launch(void* const* d_in, const int* in_sizes, int n_in,
                              void* d_out, int out_size)
{
    const float* xn   = (const float*)d_in[0];
    const float* xe   = (const float*)d_in[1];
    const void*  eidx =               d_in[2];
    const float* eW1  = (const float*)d_in[3];
    const float* eb1  = (const float*)d_in[4];
    const float* eW2  = (const float*)d_in[5];
    const float* eb2  = (const float*)d_in[6];
    const float* nW1  = (const float*)d_in[7];
    const float* nb1  = (const float*)d_in[8];
    const float* nW2  = (const float*)d_in[9];
    const float* nb2  = (const float*)d_in[10];

    float* nodes_out = (float*)d_out;
    float* edges_out = (float*)d_out + (size_t)N_NODES * NODE_C;

    cudaFuncSetAttribute(edge_mma_kernel, cudaFuncAttributeMaxDynamicSharedMemorySize, EDGE_SMEM);
    cudaFuncSetAttribute(node_mma_kernel, cudaFuncAttributeMaxDynamicSharedMemorySize, NODE_SMEM);

    prep_weights_kernel<<<160, 256>>>(eW1, eW2, nW1, nW2);
    zero_aggr_kernel<<<(N_NODES * EDGE_C / 4 + 255) / 256, 256>>>();
    edge_mma_kernel<<<N_EDGES / 128, 512, EDGE_SMEM>>>(xn, xe, eidx, eb1, eb2, edges_out);
    node_mma_kernel<<<(N_NODES + 127) / 128, 512, NODE_SMEM>>>(xn, nb1, nb2, nodes_out);
}

// round 5
// speedup vs baseline: 2.8937x; 1.0031x over previous
#include <cuda_runtime.h>
#include <cuda_fp16.h>
#include <cstdint>

#define N_NODES 50000
#define N_EDGES 800000
#define NODE_C  128
#define EDGE_C  64

// ---------------------------------------------------------------------------
// Device scratch (no cudaMalloc allowed)
// ---------------------------------------------------------------------------
__device__ float g_aggr[(size_t)N_NODES * EDGE_C];
// Pre-transposed, fp16 hi/lo-split weights: Wt[n][k] = W[k][n]
__device__ __align__(16) __half g_eW1t_hi[128 * 320];
__device__ __align__(16) __half g_eW1t_lo[128 * 320];
__device__ __align__(16) __half g_eW2t_hi[64 * 128];
__device__ __align__(16) __half g_eW2t_lo[64 * 128];
__device__ __align__(16) __half g_nW1t_hi[128 * 192];
__device__ __align__(16) __half g_nW1t_lo[128 * 192];
__device__ __align__(16) __half g_nW2t_hi[128 * 128];
__device__ __align__(16) __half g_nW2t_lo[128 * 128];

// ---------------------------------------------------------------------------
// Helpers
// ---------------------------------------------------------------------------
__device__ __forceinline__ uint32_t smem_u32(const void* p) {
    uint32_t a;
    asm("{ .reg .u64 t; cvta.to.shared.u64 t, %1; cvt.u32.u64 %0, t; }"
        : "=r"(a) : "l"(p));
    return a;
}

// Panels: [rows][64] fp16, 128-byte rows, XOR-swizzled 16B blocks.
__device__ __forceinline__ uint32_t panel_off(uint32_t r, uint32_t k) {
    return r * 128u + ((((k >> 3) ^ (r & 7u)) << 4) | ((k & 7u) << 1));
}

__device__ __forceinline__ void ldsm_x4(uint32_t* d, uint32_t a) {
    asm volatile("ldmatrix.sync.aligned.m8n8.x4.shared.b16 {%0,%1,%2,%3}, [%4];"
                 : "=r"(d[0]), "=r"(d[1]), "=r"(d[2]), "=r"(d[3]) : "r"(a));
}
__device__ __forceinline__ void ldsm_x2(uint32_t* d, uint32_t a) {
    asm volatile("ldmatrix.sync.aligned.m8n8.x2.shared.b16 {%0,%1}, [%2];"
                 : "=r"(d[0]), "=r"(d[1]) : "r"(a));
}

#define MMA16816(c, a, b) \
    asm volatile("mma.sync.aligned.m16n8k16.row.col.f32.f16.f16.f32 " \
        "{%0,%1,%2,%3},{%4,%5,%6,%7},{%8,%9},{%0,%1,%2,%3};" \
        : "+f"((c)[0]), "+f"((c)[1]), "+f"((c)[2]), "+f"((c)[3]) \
        : "r"((a)[0]), "r"((a)[1]), "r"((a)[2]), "r"((a)[3]), \
          "r"((b)[0]), "r"((b)[1]))

__device__ __forceinline__ void cp16(uint32_t dst, const void* src) {
    asm volatile("cp.async.cg.shared.global [%0], [%1], 16;"
                 :: "r"(dst), "l"(src) : "memory");
}
#define CP_COMMIT() asm volatile("cp.async.commit_group;" ::: "memory")
#define CP_WAIT(n)  asm volatile("cp.async.wait_group %0;" :: "n"(n) : "memory")

__device__ __forceinline__ uint32_t f16x2(float lo, float hi) {
    uint32_t r;
    asm("cvt.rn.f16x2.f32 %0, %1, %2;" : "=r"(r) : "f"(hi), "f"(lo));
    return r;
}
__device__ __forceinline__ float h_round(float x) {
    return __half2float(__float2half_rn(x));
}
__device__ __forceinline__ float silu_f(float x) {
    return x / (1.0f + __expf(-x));
}
__device__ __forceinline__ void split8(float4 v0, float4 v1, uint4& hi, uint4& lo) {
    float a0 = h_round(v0.x), a1 = h_round(v0.y), a2 = h_round(v0.z), a3 = h_round(v0.w);
    float a4 = h_round(v1.x), a5 = h_round(v1.y), a6 = h_round(v1.z), a7 = h_round(v1.w);
    hi.x = f16x2(a0, a1); hi.y = f16x2(a2, a3); hi.z = f16x2(a4, a5); hi.w = f16x2(a6, a7);
    lo.x = f16x2(v0.x - a0, v0.y - a1);
    lo.y = f16x2(v0.z - a2, v0.w - a3);
    lo.z = f16x2(v1.x - a4, v1.y - a5);
    lo.w = f16x2(v1.z - a6, v1.w - a7);
}

// ---------------------------------------------------------------------------
// Setup kernels
// ---------------------------------------------------------------------------
__global__ void zero_aggr_kernel() {
    size_t i = (size_t)blockIdx.x * blockDim.x + threadIdx.x;
    size_t n4 = (size_t)N_NODES * EDGE_C / 4;
    if (i < n4) reinterpret_cast<float4*>(g_aggr)[i] = make_float4(0.f, 0.f, 0.f, 0.f);
}

__global__ void prep_weights_kernel(const float* __restrict__ eW1,
                                    const float* __restrict__ eW2,
                                    const float* __restrict__ nW1,
                                    const float* __restrict__ nW2) {
    int i = blockIdx.x * 256 + threadIdx.x;
    if (i < 128 * 320) {
        int n = i / 320, k = i % 320;
        float v = eW1[(size_t)k * 128 + n];
        float h = h_round(v);
        g_eW1t_hi[i] = __float2half_rn(h);
        g_eW1t_lo[i] = __float2half_rn(v - h);
    }
    if (i < 64 * 128) {
        int n = i / 128, k = i % 128;
        float v = eW2[(size_t)k * 64 + n];
        float h = h_round(v);
        g_eW2t_hi[i] = __float2half_rn(h);
        g_eW2t_lo[i] = __float2half_rn(v - h);
    }
    if (i < 128 * 192) {
        int n = i / 192, k = i % 192;
        float v = nW1[(size_t)k * 128 + n];
        float h = h_round(v);
        g_nW1t_hi[i] = __float2half_rn(h);
        g_nW1t_lo[i] = __float2half_rn(v - h);
    }
    if (i < 128 * 128) {
        int n = i / 128, k = i % 128;
        float v = nW2[(size_t)k * 128 + n];
        float h = h_round(v);
        g_nW2t_hi[i] = __float2half_rn(h);
        g_nW2t_lo[i] = __float2half_rn(v - h);
    }
}

// ---------------------------------------------------------------------------
// Edge kernel: 128 edges / CTA, 512 threads (16 warps: 4 M-strips x 4 N-strips)
// SMEM (96KB dynamic):
//   GEMM1: A_hi@0, A_lo@16K, Bbuf0 hi@32K lo@48K, Bbuf1 hi@64K lo@80K
//   After: h_hi p0@0 p1@16K, h_lo p0@32K p1@48K,
//          B2 hi p0@64K p1@72K, lo p0@80K p1@88K  (prefetched during last chunk)
// ---------------------------------------------------------------------------
#define EDGE_SMEM 98304
#define NODE_SMEM 131072

__global__ __launch_bounds__(512, 1)
void edge_mma_kernel(const float* __restrict__ xn,
                     const float* __restrict__ xe,
                     const void*  __restrict__ eidx,
                     const float* __restrict__ eb1,
                     const float* __restrict__ eb2,
                     float* __restrict__ edges_out)
{
    extern __shared__ __align__(1024) char dsm[];
    __shared__ int s_snd[128], s_rcv[128];

    const int tid  = threadIdx.x;
    const int wid  = tid >> 5;
    const int lane = tid & 31;
    const int mw   = wid & 3;      // 32-row strip
    const int nw   = wid >> 2;     // 32-col strip (GEMM1) / 16-col (GEMM2)
    const int e0   = blockIdx.x * 128;

    const uint32_t sb = smem_u32(dsm);
    const uint32_t la_r  = lane & 15;
    const uint32_t la_kb = (lane >> 4) << 3;
    const uint32_t lb_r  = lane & 7;
    const uint32_t lb_kb = ((lane >> 3) & 1) << 3;

    // edge indices
    {
        const unsigned* w = reinterpret_cast<const unsigned*>(eidx);
        const bool is64 = ((w[1] | w[3] | w[5] | w[7] | w[9] | w[11] | w[13] | w[15]) == 0u);
        if (tid < 128) {
            size_t e = (size_t)e0 + tid;
            if (is64) {
                const long long* p = reinterpret_cast<const long long*>(eidx);
                s_snd[tid] = (int)p[e];
                s_rcv[tid] = (int)p[(size_t)N_EDGES + e];
            } else {
                const int* p = reinterpret_cast<const int*>(eidx);
                s_snd[tid] = p[e];
                s_rcv[tid] = p[(size_t)N_EDGES + e];
            }
        }
    }
    __syncthreads();

    const int gm = tid >> 2;      // gather row (0..127)
    const int gq = tid & 3;       // 16-float quarter of the 64-k chunk
    const int bn = tid >> 2;      // weight row
    const int bq = tid & 3;

    // --- prefetch chunk 0: B via cp.async, A via LDG into regs ---
    {
        const __half* shi = g_eW1t_hi + (size_t)bn * 320 + bq * 16;
        const __half* slo = g_eW1t_lo + (size_t)bn * 320 + bq * 16;
#pragma unroll
        for (int j = 0; j < 2; j++) {
            uint32_t off = panel_off((uint32_t)bn, (uint32_t)(bq * 16 + j * 8));
            cp16(sb + 32768u + off, shi + j * 8);
            cp16(sb + 49152u + off, slo + j * 8);
        }
        CP_COMMIT();
    }
    float4 av[4];
    {
        const float* rowp = xn + (size_t)s_snd[gm] * NODE_C;
        const float4* rp = reinterpret_cast<const float4*>(rowp) + gq * 4;
#pragma unroll
        for (int i = 0; i < 4; i++) av[i] = rp[i];
    }

    float c[2][4][4];
#pragma unroll
    for (int a = 0; a < 2; a++)
#pragma unroll
        for (int b = 0; b < 4; b++)
#pragma unroll
            for (int d = 0; d < 4; d++) c[a][b][d] = 0.f;

    // ---------------- GEMM1: 5 K-chunks of 64 ----------------
#pragma unroll 1
    for (int ch = 0; ch < 5; ch++) {
        __syncthreads();   // prev MMAs done with A panel & next B buffer
        // store A (split)
#pragma unroll
        for (int i = 0; i < 2; i++) {
            uint4 hi, lo;
            split8(av[2 * i], av[2 * i + 1], hi, lo);
            uint32_t off = panel_off((uint32_t)gm, (uint32_t)(gq * 16 + i * 8));
            *(uint4*)(dsm + off)         = hi;
            *(uint4*)(dsm + 16384 + off) = lo;
        }
        if (ch < 4) {
            // prefetch next B chunk + next A rows
            const int nc = ch + 1;
            uint32_t dhi = 32768u + (uint32_t)((nc & 1) * 32768);
            const __half* shi = g_eW1t_hi + (size_t)bn * 320 + nc * 64 + bq * 16;
            const __half* slo = g_eW1t_lo + (size_t)bn * 320 + nc * 64 + bq * 16;
#pragma unroll
            for (int j = 0; j < 2; j++) {
                uint32_t off = panel_off((uint32_t)bn, (uint32_t)(bq * 16 + j * 8));
                cp16(sb + dhi + off, shi + j * 8);
                cp16(sb + dhi + 16384u + off, slo + j * 8);
            }
            CP_COMMIT();
            const float* rowp;
            if (nc < 2)      rowp = xn + (size_t)s_snd[gm] * NODE_C + nc * 64;
            else if (nc < 4) rowp = xn + (size_t)s_rcv[gm] * NODE_C + (nc - 2) * 64;
            else             rowp = xe + (size_t)(e0 + gm) * EDGE_C;
            const float4* rp = reinterpret_cast<const float4*>(rowp) + gq * 4;
#pragma unroll
            for (int i = 0; i < 4; i++) av[i] = rp[i];
        } else {
            // prefetch B2 (eW2t 64x128) into [64K..96K): hi p0@64K p1@72K, lo p0@80K p1@88K
            const int n2 = tid >> 3;
            const int q2 = tid & 7;
            const __half* shi = g_eW2t_hi + (size_t)n2 * 128;
            const __half* slo = g_eW2t_lo + (size_t)n2 * 128;
#pragma unroll
            for (int j = 0; j < 2; j++) {
                int seg = q2 * 2 + j;
                uint32_t p = (uint32_t)(seg >> 3);
                uint32_t off = p * 8192u + panel_off((uint32_t)n2, (uint32_t)((seg & 7) * 8));
                cp16(sb + 65536u + off, shi + seg * 8);
                cp16(sb + 81920u + off, slo + seg * 8);
            }
            CP_COMMIT();
        }
        CP_WAIT(1);        // current chunk's B arrived
        __syncthreads();

        const uint32_t Bhi = sb + 32768u + (uint32_t)((ch & 1) * 32768);
        const uint32_t Blo = Bhi + 16384u;
#pragma unroll
        for (int ks = 0; ks < 4; ks++) {
            const uint32_t kb = ks * 16;
            uint32_t ah[2][4], al[2][4];
#pragma unroll
            for (int mf = 0; mf < 2; mf++) {
                uint32_t r = (uint32_t)(mw * 32 + mf * 16) + la_r;
                uint32_t po = panel_off(r, kb + la_kb);
                ldsm_x4(ah[mf], sb + po);
                ldsm_x4(al[mf], sb + 16384u + po);
            }
#pragma unroll
            for (int nf = 0; nf < 4; nf++) {
                uint32_t n = (uint32_t)(nw * 32 + nf * 8) + lb_r;
                uint32_t po = panel_off(n, kb + lb_kb);
                uint32_t bh[2], bl[2];
                ldsm_x2(bh, Bhi + po);
                ldsm_x2(bl, Blo + po);
#pragma unroll
                for (int mf = 0; mf < 2; mf++) {
                    MMA16816(c[mf][nf], ah[mf], bh);
                    MMA16816(c[mf][nf], ah[mf], bl);
                    MMA16816(c[mf][nf], al[mf], bh);
                }
            }
        }
    }
    __syncthreads();

    // ------------- Epilogue1: bias + SiLU -> h split panels (reuse [0..64K)) -------------
    {
        const int l4 = lane >> 2;
        const int l2 = (lane & 3) * 2;
        const uint32_t p = (uint32_t)(nw >> 1);
        const uint32_t hb_hi = p * 16384u;
        const uint32_t hb_lo = 32768u + p * 16384u;
#pragma unroll
        for (int nf = 0; nf < 4; nf++) {
            int col = nw * 32 + nf * 8 + l2;
            float b0 = __ldg(eb1 + col), b1 = __ldg(eb1 + col + 1);
            uint32_t kk = (uint32_t)((nw & 1) * 32 + nf * 8 + l2);
#pragma unroll
            for (int mf = 0; mf < 2; mf++) {
                uint32_t m = (uint32_t)(mw * 32 + mf * 16 + l4);
                float x0 = silu_f(c[mf][nf][0] + b0);
                float x1 = silu_f(c[mf][nf][1] + b1);
                float x2 = silu_f(c[mf][nf][2] + b0);
                float x3 = silu_f(c[mf][nf][3] + b1);
                float h0 = h_round(x0), h1 = h_round(x1);
                float h2 = h_round(x2), h3 = h_round(x3);
                uint32_t o0 = panel_off(m, kk);
                uint32_t o1 = panel_off(m + 8, kk);
                *(uint32_t*)(dsm + hb_hi + o0) = f16x2(h0, h1);
                *(uint32_t*)(dsm + hb_lo + o0) = f16x2(x0 - h0, x1 - h1);
                *(uint32_t*)(dsm + hb_hi + o1) = f16x2(h2, h3);
                *(uint32_t*)(dsm + hb_lo + o1) = f16x2(x2 - h2, x3 - h3);
            }
        }
    }
    CP_WAIT(0);            // B2 arrived
    __syncthreads();

    // ---------------- GEMM2: h[128,128] @ eW2t^T -> [128,64] ----------------
    float c2[2][2][4];
#pragma unroll
    for (int a = 0; a < 2; a++)
#pragma unroll
        for (int b = 0; b < 2; b++)
#pragma unroll
            for (int d = 0; d < 4; d++) c2[a][b][d] = 0.f;

#pragma unroll
    for (int p = 0; p < 2; p++) {
        const uint32_t Ah = sb + (uint32_t)p * 16384u;
        const uint32_t Al = sb + 32768u + (uint32_t)p * 16384u;
        const uint32_t Bh = sb + 65536u + (uint32_t)p * 8192u;
        const uint32_t Bl = sb + 81920u + (uint32_t)p * 8192u;
#pragma unroll
        for (int ks = 0; ks < 4; ks++) {
            const uint32_t kb = ks * 16;
            uint32_t ah[2][4], al[2][4];
#pragma unroll
            for (int mf = 0; mf < 2; mf++) {
                uint32_t r = (uint32_t)(mw * 32 + mf * 16) + la_r;
                uint32_t po = panel_off(r, kb + la_kb);
                ldsm_x4(ah[mf], Ah + po);
                ldsm_x4(al[mf], Al + po);
            }
#pragma unroll
            for (int nf = 0; nf < 2; nf++) {
                uint32_t n = (uint32_t)(nw * 16 + nf * 8) + lb_r;
                uint32_t po = panel_off(n, kb + lb_kb);
                uint32_t bh[2], bl[2];
                ldsm_x2(bh, Bh + po);
                ldsm_x2(bl, Bl + po);
#pragma unroll
                for (int mf = 0; mf < 2; mf++) {
                    MMA16816(c2[mf][nf], ah[mf], bh);
                    MMA16816(c2[mf][nf], ah[mf], bl);
                    MMA16816(c2[mf][nf], al[mf], bh);
                }
            }
        }
    }

    // ------------- Epilogue2: SiLU, store, scatter-add -------------
    {
        const int l4 = lane >> 2;
        const int l2 = (lane & 3) * 2;
        float b0[2], b1[2];
#pragma unroll
        for (int nf = 0; nf < 2; nf++) {
            int col = nw * 16 + nf * 8 + l2;
            b0[nf] = __ldg(eb2 + col);
            b1[nf] = __ldg(eb2 + col + 1);
        }
#pragma unroll
        for (int mf = 0; mf < 2; mf++) {
#pragma unroll
            for (int half = 0; half < 2; half++) {
                int m = mw * 32 + mf * 16 + l4 + half * 8;
                int rcv = s_rcv[m];
                float* orow = edges_out + (size_t)(e0 + m) * EDGE_C;
                float* arow = g_aggr + (size_t)rcv * EDGE_C;
#pragma unroll
                for (int nf = 0; nf < 2; nf++) {
                    int col = nw * 16 + nf * 8 + l2;
                    float o0 = silu_f(c2[mf][nf][half * 2]     + b0[nf]);
                    float o1 = silu_f(c2[mf][nf][half * 2 + 1] + b1[nf]);
                    float2 ov = {o0, o1};
                    *reinterpret_cast<float2*>(orow + col) = ov;
                    atomicAdd(arow + col,     o0);
                    atomicAdd(arow + col + 1, o1);
                }
            }
        }
    }
}

// ---------------------------------------------------------------------------
// Node kernel: 128 nodes / CTA, 512 threads
// SMEM (128KB): GEMM1 as edge; h@[0..64K); B2 hi p0@64K p1@80K, lo p0@96K p1@112K
// ---------------------------------------------------------------------------
__global__ __launch_bounds__(512, 1)
void node_mma_kernel(const float* __restrict__ xn,
                     const float* __restrict__ nb1,
                     const float* __restrict__ nb2,
                     float* __restrict__ nodes_out)
{
    extern __shared__ __align__(1024) char dsm[];

    const int tid  = threadIdx.x;
    const int wid  = tid >> 5;
    const int lane = tid & 31;
    const int mw   = wid & 3;
    const int nw   = wid >> 2;
    const int m0   = blockIdx.x * 128;

    const uint32_t sb = smem_u32(dsm);
    const uint32_t la_r  = lane & 15;
    const uint32_t la_kb = (lane >> 4) << 3;
    const uint32_t lb_r  = lane & 7;
    const uint32_t lb_kb = ((lane >> 3) & 1) << 3;

    const int gm = tid >> 2;
    const int gq = tid & 3;
    const int bn = tid >> 2;
    const int bq = tid & 3;
    const size_t grow = (size_t)m0 + gm;
    const bool gvalid = grow < N_NODES;

    // prefetch chunk 0
    {
        const __half* shi = g_nW1t_hi + (size_t)bn * 192 + bq * 16;
        const __half* slo = g_nW1t_lo + (size_t)bn * 192 + bq * 16;
#pragma unroll
        for (int j = 0; j < 2; j++) {
            uint32_t off = panel_off((uint32_t)bn, (uint32_t)(bq * 16 + j * 8));
            cp16(sb + 32768u + off, shi + j * 8);
            cp16(sb + 49152u + off, slo + j * 8);
        }
        CP_COMMIT();
    }
    float4 av[4];
    {
        const float4* rp = reinterpret_cast<const float4*>(xn + grow * NODE_C) + gq * 4;
#pragma unroll
        for (int i = 0; i < 4; i++)
            av[i] = gvalid ? rp[i] : make_float4(0.f, 0.f, 0.f, 0.f);
    }

    float c[2][4][4];
#pragma unroll
    for (int a = 0; a < 2; a++)
#pragma unroll
        for (int b = 0; b < 4; b++)
#pragma unroll
            for (int d = 0; d < 4; d++) c[a][b][d] = 0.f;

#pragma unroll 1
    for (int ch = 0; ch < 3; ch++) {
        __syncthreads();
#pragma unroll
        for (int i = 0; i < 2; i++) {
            uint4 hi, lo;
            split8(av[2 * i], av[2 * i + 1], hi, lo);
            uint32_t off = panel_off((uint32_t)gm, (uint32_t)(gq * 16 + i * 8));
            *(uint4*)(dsm + off)         = hi;
            *(uint4*)(dsm + 16384 + off) = lo;
        }
        if (ch < 2) {
            const int nc = ch + 1;
            uint32_t dhi = 32768u + (uint32_t)((nc & 1) * 32768);
            const __half* shi = g_nW1t_hi + (size_t)bn * 192 + nc * 64 + bq * 16;
            const __half* slo = g_nW1t_lo + (size_t)bn * 192 + nc * 64 + bq * 16;
#pragma unroll
            for (int j = 0; j < 2; j++) {
                uint32_t off = panel_off((uint32_t)bn, (uint32_t)(bq * 16 + j * 8));
                cp16(sb + dhi + off, shi + j * 8);
                cp16(sb + dhi + 16384u + off, slo + j * 8);
            }
            CP_COMMIT();
            const float* rowp = (nc < 2) ? xn + grow * NODE_C + nc * 64
                                         : g_aggr + grow * EDGE_C;
            const float4* rp = reinterpret_cast<const float4*>(rowp) + gq * 4;
#pragma unroll
            for (int i = 0; i < 4; i++)
                av[i] = gvalid ? rp[i] : make_float4(0.f, 0.f, 0.f, 0.f);
        } else {
            // prefetch B2 (nW2t 128x128): hi p0@64K p1@80K, lo p0@96K p1@112K
            const __half* shi = g_nW2t_hi + (size_t)bn * 128;
            const __half* slo = g_nW2t_lo + (size_t)bn * 128;
#pragma unroll
            for (int j = 0; j < 4; j++) {
                int seg = bq * 4 + j;
                uint32_t p = (uint32_t)(seg >> 3);
                uint32_t off = p * 16384u + panel_off((uint32_t)bn, (uint32_t)((seg & 7) * 8));
                cp16(sb + 65536u + off, shi + seg * 8);
                cp16(sb + 98304u + off, slo + seg * 8);
            }
            CP_COMMIT();
        }
        CP_WAIT(1);
        __syncthreads();

        const uint32_t Bhi = sb + 32768u + (uint32_t)((ch & 1) * 32768);
        const uint32_t Blo = Bhi + 16384u;
#pragma unroll
        for (int ks = 0; ks < 4; ks++) {
            const uint32_t kb = ks * 16;
            uint32_t ah[2][4], al[2][4];
#pragma unroll
            for (int mf = 0; mf < 2; mf++) {
                uint32_t r = (uint32_t)(mw * 32 + mf * 16) + la_r;
                uint32_t po = panel_off(r, kb + la_kb);
                ldsm_x4(ah[mf], sb + po);
                ldsm_x4(al[mf], sb + 16384u + po);
            }
#pragma unroll
            for (int nf = 0; nf < 4; nf++) {
                uint32_t n = (uint32_t)(nw * 32 + nf * 8) + lb_r;
                uint32_t po = panel_off(n, kb + lb_kb);
                uint32_t bh[2], bl[2];
                ldsm_x2(bh, Bhi + po);
                ldsm_x2(bl, Blo + po);
#pragma unroll
                for (int mf = 0; mf < 2; mf++) {
                    MMA16816(c[mf][nf], ah[mf], bh);
                    MMA16816(c[mf][nf], ah[mf], bl);
                    MMA16816(c[mf][nf], al[mf], bh);
                }
            }
        }
    }
    __syncthreads();

    // Epilogue1: bias + SiLU -> h split
    {
        const int l4 = lane >> 2;
        const int l2 = (lane & 3) * 2;
        const uint32_t p = (uint32_t)(nw >> 1);
        const uint32_t hb_hi = p * 16384u;
        const uint32_t hb_lo = 32768u + p * 16384u;
#pragma unroll
        for (int nf = 0; nf < 4; nf++) {
            int col = nw * 32 + nf * 8 + l2;
            float b0 = __ldg(nb1 + col), b1 = __ldg(nb1 + col + 1);
            uint32_t kk = (uint32_t)((nw & 1) * 32 + nf * 8 + l2);
#pragma unroll
            for (int mf = 0; mf < 2; mf++) {
                uint32_t m = (uint32_t)(mw * 32 + mf * 16 + l4);
                float x0 = silu_f(c[mf][nf][0] + b0);
                float x1 = silu_f(c[mf][nf][1] + b1);
                float x2 = silu_f(c[mf][nf][2] + b0);
                float x3 = silu_f(c[mf][nf][3] + b1);
                float h0 = h_round(x0), h1 = h_round(x1);
                float h2 = h_round(x2), h3 = h_round(x3);
                uint32_t o0 = panel_off(m, kk);
                uint32_t o1 = panel_off(m + 8, kk);
                *(uint32_t*)(dsm + hb_hi + o0) = f16x2(h0, h1);
                *(uint32_t*)(dsm + hb_lo + o0) = f16x2(x0 - h0, x1 - h1);
                *(uint32_t*)(dsm + hb_hi + o1) = f16x2(h2, h3);
                *(uint32_t*)(dsm + hb_lo + o1) = f16x2(x2 - h2, x3 - h3);
            }
        }
    }
    CP_WAIT(0);
    __syncthreads();

    // GEMM2: [128,128] @ nW2t^T -> [128,128]
    float c2[2][4][4];
#pragma unroll
    for (int a = 0; a < 2; a++)
#pragma unroll
        for (int b = 0; b < 4; b++)
#pragma unroll
            for (int d = 0; d < 4; d++) c2[a][b][d] = 0.f;

#pragma unroll
    for (int p = 0; p < 2; p++) {
        const uint32_t Ah = sb + (uint32_t)p * 16384u;
        const uint32_t Al = sb + 32768u + (uint32_t)p * 16384u;
        const uint32_t Bh = sb + 65536u + (uint32_t)p * 16384u;
        const uint32_t Bl = sb + 98304u + (uint32_t)p * 16384u;
#pragma unroll
        for (int ks = 0; ks < 4; ks++) {
            const uint32_t kb = ks * 16;
            uint32_t ah[2][4], al[2][4];
#pragma unroll
            for (int mf = 0; mf < 2; mf++) {
                uint32_t r = (uint32_t)(mw * 32 + mf * 16) + la_r;
                uint32_t po = panel_off(r, kb + la_kb);
                ldsm_x4(ah[mf], Ah + po);
                ldsm_x4(al[mf], Al + po);
            }
#pragma unroll
            for (int nf = 0; nf < 4; nf++) {
                uint32_t n = (uint32_t)(nw * 32 + nf * 8) + lb_r;
                uint32_t po = panel_off(n, kb + lb_kb);
                uint32_t bh[2], bl[2];
                ldsm_x2(bh, Bh + po);
                ldsm_x2(bl, Bl + po);
#pragma unroll
                for (int mf = 0; mf < 2; mf++) {
                    MMA16816(c2[mf][nf], ah[mf], bh);
                    MMA16816(c2[mf][nf], ah[mf], bl);
                    MMA16816(c2[mf][nf], al[mf], bh);
                }
            }
        }
    }

    // Epilogue2: + bias, store
    {
        const int l4 = lane >> 2;
        const int l2 = (lane & 3) * 2;
        float b0[4], b1[4];
#pragma unroll
        for (int nf = 0; nf < 4; nf++) {
            int col = nw * 32 + nf * 8 + l2;
            b0[nf] = __ldg(nb2 + col);
            b1[nf] = __ldg(nb2 + col + 1);
        }
#pragma unroll
        for (int mf = 0; mf < 2; mf++) {
#pragma unroll
            for (int half = 0; half < 2; half++) {
                size_t row = (size_t)m0 + mw * 32 + mf * 16 + l4 + half * 8;
                if (row < N_NODES) {
                    float* orow = nodes_out + row * NODE_C;
#pragma unroll
                    for (int nf = 0; nf < 4; nf++) {
                        int col = nw * 32 + nf * 8 + l2;
                        float2 ov;
                        ov.x = c2[mf][nf][half * 2]     + b0[nf];
                        ov.y = c2[mf][nf][half * 2 + 1] + b1[nf];
                        *reinterpret_cast<float2*>(orow + col) = ov;
                    }
                }
            }
        }
    }
}

// ---------------------------------------------------------------------------
extern "C" void kernel_launch(void* const* d_in, const int* in_sizes, int n_in,
                              void* d_out, int out_size)
{
    const float* xn   = (const float*)d_in[0];
    const float* xe   = (const float*)d_in[1];
    const void*  eidx =               d_in[2];
    const float* eW1  = (const float*)d_in[3];
    const float* eb1  = (const float*)d_in[4];
    const float* eW2  = (const float*)d_in[5];
    const float* eb2  = (const float*)d_in[6];
    const float* nW1  = (const float*)d_in[7];
    const float* nb1  = (const float*)d_in[8];
    const float* nW2  = (const float*)d_in[9];
    const float* nb2  = (const float*)d_in[10];

    float* nodes_out = (float*)d_out;
    float* edges_out = (float*)d_out + (size_t)N_NODES * NODE_C;

    cudaFuncSetAttribute(edge_mma_kernel, cudaFuncAttributeMaxDynamicSharedMemorySize, EDGE_SMEM);
    cudaFuncSetAttribute(node_mma_kernel, cudaFuncAttributeMaxDynamicSharedMemorySize, NODE_SMEM);

    prep_weights_kernel<<<160, 256>>>(eW1, eW2, nW1, nW2);
    zero_aggr_kernel<<<(N_NODES * EDGE_C / 4 + 255) / 256, 256>>>();
    edge_mma_kernel<<<N_EDGES / 128, 512, EDGE_SMEM>>>(xn, xe, eidx, eb1, eb2, edges_out);
    node_mma_kernel<<<(N_NODES + 127) / 128, 512, NODE_SMEM>>>(xn, nb1, nb2, nodes_out);
}

// round 6
// speedup vs baseline: 2.9870x; 1.0323x over previous
#include <cuda_runtime.h>
#include <cuda_fp16.h>
#include <cstdint>

#define N_NODES 50000
#define N_EDGES 800000
#define NODE_C  128
#define EDGE_C  64

// ---------------------------------------------------------------------------
// Device scratch (no cudaMalloc allowed)
// ---------------------------------------------------------------------------
__device__ float g_aggr[(size_t)N_NODES * EDGE_C];
// Pre-transposed, fp16 hi/lo-split weights: Wt[n][k] = W[k][n]
__device__ __align__(16) __half g_eW1t_hi[128 * 320];
__device__ __align__(16) __half g_eW1t_lo[128 * 320];
__device__ __align__(16) __half g_eW2t_hi[64 * 128];
__device__ __align__(16) __half g_eW2t_lo[64 * 128];
__device__ __align__(16) __half g_nW1t_hi[128 * 192];
__device__ __align__(16) __half g_nW1t_lo[128 * 192];
__device__ __align__(16) __half g_nW2t_hi[128 * 128];
__device__ __align__(16) __half g_nW2t_lo[128 * 128];

// ---------------------------------------------------------------------------
// Helpers
// ---------------------------------------------------------------------------
__device__ __forceinline__ uint32_t smem_u32(const void* p) {
    uint32_t a;
    asm("{ .reg .u64 t; cvta.to.shared.u64 t, %1; cvt.u32.u64 %0, t; }"
        : "=r"(a) : "l"(p));
    return a;
}

// Panels: [rows][64] fp16, 128-byte rows, XOR-swizzled 16B blocks.
__device__ __forceinline__ uint32_t panel_off(uint32_t r, uint32_t k) {
    return r * 128u + ((((k >> 3) ^ (r & 7u)) << 4) | ((k & 7u) << 1));
}

__device__ __forceinline__ void ldsm_x4(uint32_t* d, uint32_t a) {
    asm volatile("ldmatrix.sync.aligned.m8n8.x4.shared.b16 {%0,%1,%2,%3}, [%4];"
                 : "=r"(d[0]), "=r"(d[1]), "=r"(d[2]), "=r"(d[3]) : "r"(a));
}
__device__ __forceinline__ void ldsm_x2(uint32_t* d, uint32_t a) {
    asm volatile("ldmatrix.sync.aligned.m8n8.x2.shared.b16 {%0,%1}, [%2];"
                 : "=r"(d[0]), "=r"(d[1]) : "r"(a));
}

#define MMA16816(c, a, b) \
    asm volatile("mma.sync.aligned.m16n8k16.row.col.f32.f16.f16.f32 " \
        "{%0,%1,%2,%3},{%4,%5,%6,%7},{%8,%9},{%0,%1,%2,%3};" \
        : "+f"((c)[0]), "+f"((c)[1]), "+f"((c)[2]), "+f"((c)[3]) \
        : "r"((a)[0]), "r"((a)[1]), "r"((a)[2]), "r"((a)[3]), \
          "r"((b)[0]), "r"((b)[1]))

__device__ __forceinline__ void cp16(uint32_t dst, const void* src) {
    asm volatile("cp.async.cg.shared.global [%0], [%1], 16;"
                 :: "r"(dst), "l"(src) : "memory");
}
#define CP_COMMIT() asm volatile("cp.async.commit_group;" ::: "memory")
#define CP_WAIT(n)  asm volatile("cp.async.wait_group %0;" :: "n"(n) : "memory")

__device__ __forceinline__ uint32_t f16x2(float lo, float hi) {
    uint32_t r;
    asm("cvt.rn.f16x2.f32 %0, %1, %2;" : "=r"(r) : "f"(hi), "f"(lo));
    return r;
}
__device__ __forceinline__ float h_round(float x) {
    return __half2float(__float2half_rn(x));
}
__device__ __forceinline__ float silu_f(float x) {
    return x / (1.0f + __expf(-x));
}
__device__ __forceinline__ void split8(float4 v0, float4 v1, uint4& hi, uint4& lo) {
    float a0 = h_round(v0.x), a1 = h_round(v0.y), a2 = h_round(v0.z), a3 = h_round(v0.w);
    float a4 = h_round(v1.x), a5 = h_round(v1.y), a6 = h_round(v1.z), a7 = h_round(v1.w);
    hi.x = f16x2(a0, a1); hi.y = f16x2(a2, a3); hi.z = f16x2(a4, a5); hi.w = f16x2(a6, a7);
    lo.x = f16x2(v0.x - a0, v0.y - a1);
    lo.y = f16x2(v0.z - a2, v0.w - a3);
    lo.z = f16x2(v1.x - a4, v1.y - a5);
    lo.w = f16x2(v1.z - a6, v1.w - a7);
}

// ---------------------------------------------------------------------------
// Setup kernels
// ---------------------------------------------------------------------------
__global__ void zero_aggr_kernel() {
    size_t i = (size_t)blockIdx.x * blockDim.x + threadIdx.x;
    size_t n4 = (size_t)N_NODES * EDGE_C / 4;
    if (i < n4) reinterpret_cast<float4*>(g_aggr)[i] = make_float4(0.f, 0.f, 0.f, 0.f);
}

__global__ void prep_weights_kernel(const float* __restrict__ eW1,
                                    const float* __restrict__ eW2,
                                    const float* __restrict__ nW1,
                                    const float* __restrict__ nW2) {
    int i = blockIdx.x * 256 + threadIdx.x;
    if (i < 128 * 320) {
        int n = i / 320, k = i % 320;
        float v = eW1[(size_t)k * 128 + n];
        float h = h_round(v);
        g_eW1t_hi[i] = __float2half_rn(h);
        g_eW1t_lo[i] = __float2half_rn(v - h);
    }
    if (i < 64 * 128) {
        int n = i / 128, k = i % 128;
        float v = eW2[(size_t)k * 64 + n];
        float h = h_round(v);
        g_eW2t_hi[i] = __float2half_rn(h);
        g_eW2t_lo[i] = __float2half_rn(v - h);
    }
    if (i < 128 * 192) {
        int n = i / 192, k = i % 192;
        float v = nW1[(size_t)k * 128 + n];
        float h = h_round(v);
        g_nW1t_hi[i] = __float2half_rn(h);
        g_nW1t_lo[i] = __float2half_rn(v - h);
    }
    if (i < 128 * 128) {
        int n = i / 128, k = i % 128;
        float v = nW2[(size_t)k * 128 + n];
        float h = h_round(v);
        g_nW2t_hi[i] = __float2half_rn(h);
        g_nW2t_lo[i] = __float2half_rn(v - h);
    }
}

// ---------------------------------------------------------------------------
// Edge kernel: 64 edges / CTA, 256 threads (8 warps: 2 M-strips x 4 N-strips)
// 2 CTAs per SM (regs <=128, SMEM 80KB).
// SMEM map (80KB dynamic):
//   A_hi@0 (8K), A_lo@8K (8K)
//   B buf0: hi@16K lo@32K;  buf1: hi@48K lo@64K   (16K each)
//   After GEMM1:
//     h_hi p0@0 p1@8K, h_lo p0@16K p1@24K  (overwrites A + B0_hi)
//     B2 (eW2t 64x128): hi p0@48K p1@56K, lo p0@64K p1@72K (prefetched into
//     B1 region during last chunk, which uses buf0)
// ---------------------------------------------------------------------------
#define EDGE_SMEM  81920
#define NODE_SMEM 114688

__global__ __launch_bounds__(256, 2)
void edge_mma_kernel(const float* __restrict__ xn,
                     const float* __restrict__ xe,
                     const void*  __restrict__ eidx,
                     const float* __restrict__ eb1,
                     const float* __restrict__ eb2,
                     float* __restrict__ edges_out)
{
    extern __shared__ __align__(1024) char dsm[];
    __shared__ int s_snd[64], s_rcv[64];

    const int tid  = threadIdx.x;
    const int wid  = tid >> 5;
    const int lane = tid & 31;
    const int mw   = wid & 1;      // 32-row strip
    const int nw   = wid >> 1;     // 32-col strip (GEMM1) / 16-col (GEMM2)
    const int e0   = blockIdx.x * 64;

    const uint32_t sb = smem_u32(dsm);
    const uint32_t la_r  = lane & 15;
    const uint32_t la_kb = (lane >> 4) << 3;
    const uint32_t lb_r  = lane & 7;
    const uint32_t lb_kb = ((lane >> 3) & 1) << 3;

    // edge indices
    {
        const unsigned* w = reinterpret_cast<const unsigned*>(eidx);
        const bool is64 = ((w[1] | w[3] | w[5] | w[7] | w[9] | w[11] | w[13] | w[15]) == 0u);
        if (tid < 64) {
            size_t e = (size_t)e0 + tid;
            if (is64) {
                const long long* p = reinterpret_cast<const long long*>(eidx);
                s_snd[tid] = (int)p[e];
                s_rcv[tid] = (int)p[(size_t)N_EDGES + e];
            } else {
                const int* p = reinterpret_cast<const int*>(eidx);
                s_snd[tid] = p[e];
                s_rcv[tid] = p[(size_t)N_EDGES + e];
            }
        }
    }
    __syncthreads();

    const int gm = tid >> 2;      // gather row (0..63)
    const int gq = tid & 3;       // 16-float quarter of the 64-k chunk
    const int bn = tid >> 1;      // weight row (0..127)
    const int bq = tid & 1;       // 32-k half

    // prefetch chunk 0 B
    {
        const __half* shi = g_eW1t_hi + (size_t)bn * 320 + bq * 32;
        const __half* slo = g_eW1t_lo + (size_t)bn * 320 + bq * 32;
#pragma unroll
        for (int j = 0; j < 4; j++) {
            uint32_t off = panel_off((uint32_t)bn, (uint32_t)(bq * 32 + j * 8));
            cp16(sb + 16384u + off, shi + j * 8);
            cp16(sb + 32768u + off, slo + j * 8);
        }
        CP_COMMIT();
    }
    float4 av[4];
    {
        const float4* rp = reinterpret_cast<const float4*>(xn + (size_t)s_snd[gm] * NODE_C) + gq * 4;
#pragma unroll
        for (int i = 0; i < 4; i++) av[i] = rp[i];
    }

    float c[2][4][4];
#pragma unroll
    for (int a = 0; a < 2; a++)
#pragma unroll
        for (int b = 0; b < 4; b++)
#pragma unroll
            for (int d = 0; d < 4; d++) c[a][b][d] = 0.f;

    // ---------------- GEMM1: 5 K-chunks of 64 ----------------
#pragma unroll 1
    for (int ch = 0; ch < 5; ch++) {
        __syncthreads();
#pragma unroll
        for (int i = 0; i < 2; i++) {
            uint4 hi, lo;
            split8(av[2 * i], av[2 * i + 1], hi, lo);
            uint32_t off = panel_off((uint32_t)gm, (uint32_t)(gq * 16 + i * 8));
            *(uint4*)(dsm + off)        = hi;
            *(uint4*)(dsm + 8192 + off) = lo;
        }
        if (ch < 4) {
            const int nc = ch + 1;
            uint32_t dhi = 16384u + (uint32_t)((nc & 1) * 32768);
            const __half* shi = g_eW1t_hi + (size_t)bn * 320 + nc * 64 + bq * 32;
            const __half* slo = g_eW1t_lo + (size_t)bn * 320 + nc * 64 + bq * 32;
#pragma unroll
            for (int j = 0; j < 4; j++) {
                uint32_t off = panel_off((uint32_t)bn, (uint32_t)(bq * 32 + j * 8));
                cp16(sb + dhi + off, shi + j * 8);
                cp16(sb + dhi + 16384u + off, slo + j * 8);
            }
            CP_COMMIT();
            const float* rowp;
            if (nc < 2)      rowp = xn + (size_t)s_snd[gm] * NODE_C + nc * 64;
            else if (nc < 4) rowp = xn + (size_t)s_rcv[gm] * NODE_C + (nc - 2) * 64;
            else             rowp = xe + (size_t)(e0 + gm) * EDGE_C;
            const float4* rp = reinterpret_cast<const float4*>(rowp) + gq * 4;
#pragma unroll
            for (int i = 0; i < 4; i++) av[i] = rp[i];
        } else {
            // prefetch B2 (eW2t 64x128) into B1 region:
            //   hi p0@48K p1@56K, lo p0@64K p1@72K
            const int n2 = tid >> 2;
            const int q2 = tid & 3;
            const __half* shi = g_eW2t_hi + (size_t)n2 * 128;
            const __half* slo = g_eW2t_lo + (size_t)n2 * 128;
#pragma unroll
            for (int j = 0; j < 4; j++) {
                int seg = q2 * 4 + j;
                uint32_t p = (uint32_t)(seg >> 3);
                uint32_t off = p * 8192u + panel_off((uint32_t)n2, (uint32_t)((seg & 7) * 8));
                cp16(sb + 49152u + off, shi + seg * 8);
                cp16(sb + 65536u + off, slo + seg * 8);
            }
            CP_COMMIT();
        }
        CP_WAIT(1);
        __syncthreads();

        const uint32_t Bhi = sb + 16384u + (uint32_t)((ch & 1) * 32768);
        const uint32_t Blo = Bhi + 16384u;
#pragma unroll
        for (int ks = 0; ks < 4; ks++) {
            const uint32_t kb = ks * 16;
            uint32_t ah[2][4], al[2][4];
#pragma unroll
            for (int mf = 0; mf < 2; mf++) {
                uint32_t r = (uint32_t)(mw * 32 + mf * 16) + la_r;
                uint32_t po = panel_off(r, kb + la_kb);
                ldsm_x4(ah[mf], sb + po);
                ldsm_x4(al[mf], sb + 8192u + po);
            }
#pragma unroll
            for (int nf = 0; nf < 4; nf++) {
                uint32_t n = (uint32_t)(nw * 32 + nf * 8) + lb_r;
                uint32_t po = panel_off(n, kb + lb_kb);
                uint32_t bh[2], bl[2];
                ldsm_x2(bh, Bhi + po);
                ldsm_x2(bl, Blo + po);
#pragma unroll
                for (int mf = 0; mf < 2; mf++) {
                    MMA16816(c[mf][nf], ah[mf], bh);
                    MMA16816(c[mf][nf], ah[mf], bl);
                    MMA16816(c[mf][nf], al[mf], bh);
                }
            }
        }
    }
    __syncthreads();

    // ------------- Epilogue1: bias + SiLU -> h split panels -------------
    {
        const int l4 = lane >> 2;
        const int l2 = (lane & 3) * 2;
        const uint32_t p = (uint32_t)(nw >> 1);
        const uint32_t hb_hi = p * 8192u;
        const uint32_t hb_lo = 16384u + p * 8192u;
#pragma unroll
        for (int nf = 0; nf < 4; nf++) {
            int col = nw * 32 + nf * 8 + l2;
            float b0 = __ldg(eb1 + col), b1 = __ldg(eb1 + col + 1);
            uint32_t kk = (uint32_t)((nw & 1) * 32 + nf * 8 + l2);
#pragma unroll
            for (int mf = 0; mf < 2; mf++) {
                uint32_t m = (uint32_t)(mw * 32 + mf * 16 + l4);
                float x0 = silu_f(c[mf][nf][0] + b0);
                float x1 = silu_f(c[mf][nf][1] + b1);
                float x2 = silu_f(c[mf][nf][2] + b0);
                float x3 = silu_f(c[mf][nf][3] + b1);
                float h0 = h_round(x0), h1 = h_round(x1);
                float h2 = h_round(x2), h3 = h_round(x3);
                uint32_t o0 = panel_off(m, kk);
                uint32_t o1 = panel_off(m + 8, kk);
                *(uint32_t*)(dsm + hb_hi + o0) = f16x2(h0, h1);
                *(uint32_t*)(dsm + hb_lo + o0) = f16x2(x0 - h0, x1 - h1);
                *(uint32_t*)(dsm + hb_hi + o1) = f16x2(h2, h3);
                *(uint32_t*)(dsm + hb_lo + o1) = f16x2(x2 - h2, x3 - h3);
            }
        }
    }
    CP_WAIT(0);
    __syncthreads();

    // ---------------- GEMM2: h[64,128] @ eW2t^T -> [64,64] ----------------
    float c2[2][2][4];
#pragma unroll
    for (int a = 0; a < 2; a++)
#pragma unroll
        for (int b = 0; b < 2; b++)
#pragma unroll
            for (int d = 0; d < 4; d++) c2[a][b][d] = 0.f;

#pragma unroll
    for (int p = 0; p < 2; p++) {
        const uint32_t Ah = sb + (uint32_t)p * 8192u;
        const uint32_t Al = sb + 16384u + (uint32_t)p * 8192u;
        const uint32_t Bh = sb + 49152u + (uint32_t)p * 8192u;
        const uint32_t Bl = sb + 65536u + (uint32_t)p * 8192u;
#pragma unroll
        for (int ks = 0; ks < 4; ks++) {
            const uint32_t kb = ks * 16;
            uint32_t ah[2][4], al[2][4];
#pragma unroll
            for (int mf = 0; mf < 2; mf++) {
                uint32_t r = (uint32_t)(mw * 32 + mf * 16) + la_r;
                uint32_t po = panel_off(r, kb + la_kb);
                ldsm_x4(ah[mf], Ah + po);
                ldsm_x4(al[mf], Al + po);
            }
#pragma unroll
            for (int nf = 0; nf < 2; nf++) {
                uint32_t n = (uint32_t)(nw * 16 + nf * 8) + lb_r;
                uint32_t po = panel_off(n, kb + lb_kb);
                uint32_t bh[2], bl[2];
                ldsm_x2(bh, Bh + po);
                ldsm_x2(bl, Bl + po);
#pragma unroll
                for (int mf = 0; mf < 2; mf++) {
                    MMA16816(c2[mf][nf], ah[mf], bh);
                    MMA16816(c2[mf][nf], ah[mf], bl);
                    MMA16816(c2[mf][nf], al[mf], bh);
                }
            }
        }
    }

    // ------------- Epilogue2: SiLU, store, scatter-add -------------
    {
        const int l4 = lane >> 2;
        const int l2 = (lane & 3) * 2;
        float b0[2], b1[2];
#pragma unroll
        for (int nf = 0; nf < 2; nf++) {
            int col = nw * 16 + nf * 8 + l2;
            b0[nf] = __ldg(eb2 + col);
            b1[nf] = __ldg(eb2 + col + 1);
        }
#pragma unroll
        for (int mf = 0; mf < 2; mf++) {
#pragma unroll
            for (int half = 0; half < 2; half++) {
                int m = mw * 32 + mf * 16 + l4 + half * 8;
                int rcv = s_rcv[m];
                float* orow = edges_out + (size_t)(e0 + m) * EDGE_C;
                float* arow = g_aggr + (size_t)rcv * EDGE_C;
#pragma unroll
                for (int nf = 0; nf < 2; nf++) {
                    int col = nw * 16 + nf * 8 + l2;
                    float o0 = silu_f(c2[mf][nf][half * 2]     + b0[nf]);
                    float o1 = silu_f(c2[mf][nf][half * 2 + 1] + b1[nf]);
                    float2 ov = {o0, o1};
                    *reinterpret_cast<float2*>(orow + col) = ov;
                    atomicAdd(arow + col,     o0);
                    atomicAdd(arow + col + 1, o1);
                }
            }
        }
    }
}

// ---------------------------------------------------------------------------
// Node kernel: 64 nodes / CTA, 256 threads, 2 CTAs/SM (SMEM 112KB)
// SMEM map: GEMM1 as edge (80K). After GEMM1:
//   h_hi p0@0 p1@8K, h_lo p0@16K p1@24K
//   B2 (nW2t 128x128): hi p0@48K p1@64K, lo p0@80K p1@96K
//   (B2 hi fits in B1 region free during last chunk; lo beyond 80K)
// ---------------------------------------------------------------------------
__global__ __launch_bounds__(256, 2)
void node_mma_kernel(const float* __restrict__ xn,
                     const float* __restrict__ nb1,
                     const float* __restrict__ nb2,
                     float* __restrict__ nodes_out)
{
    extern __shared__ __align__(1024) char dsm[];

    const int tid  = threadIdx.x;
    const int wid  = tid >> 5;
    const int lane = tid & 31;
    const int mw   = wid & 1;
    const int nw   = wid >> 1;
    const int m0   = blockIdx.x * 64;

    const uint32_t sb = smem_u32(dsm);
    const uint32_t la_r  = lane & 15;
    const uint32_t la_kb = (lane >> 4) << 3;
    const uint32_t lb_r  = lane & 7;
    const uint32_t lb_kb = ((lane >> 3) & 1) << 3;

    const int gm = tid >> 2;
    const int gq = tid & 3;
    const int bn = tid >> 1;
    const int bq = tid & 1;
    const size_t grow = (size_t)m0 + gm;
    const bool gvalid = grow < N_NODES;

    // prefetch chunk 0 B
    {
        const __half* shi = g_nW1t_hi + (size_t)bn * 192 + bq * 32;
        const __half* slo = g_nW1t_lo + (size_t)bn * 192 + bq * 32;
#pragma unroll
        for (int j = 0; j < 4; j++) {
            uint32_t off = panel_off((uint32_t)bn, (uint32_t)(bq * 32 + j * 8));
            cp16(sb + 16384u + off, shi + j * 8);
            cp16(sb + 32768u + off, slo + j * 8);
        }
        CP_COMMIT();
    }
    float4 av[4];
    {
        const float4* rp = reinterpret_cast<const float4*>(xn + grow * NODE_C) + gq * 4;
#pragma unroll
        for (int i = 0; i < 4; i++)
            av[i] = gvalid ? rp[i] : make_float4(0.f, 0.f, 0.f, 0.f);
    }

    float c[2][4][4];
#pragma unroll
    for (int a = 0; a < 2; a++)
#pragma unroll
        for (int b = 0; b < 4; b++)
#pragma unroll
            for (int d = 0; d < 4; d++) c[a][b][d] = 0.f;

#pragma unroll 1
    for (int ch = 0; ch < 3; ch++) {
        __syncthreads();
#pragma unroll
        for (int i = 0; i < 2; i++) {
            uint4 hi, lo;
            split8(av[2 * i], av[2 * i + 1], hi, lo);
            uint32_t off = panel_off((uint32_t)gm, (uint32_t)(gq * 16 + i * 8));
            *(uint4*)(dsm + off)        = hi;
            *(uint4*)(dsm + 8192 + off) = lo;
        }
        if (ch < 2) {
            const int nc = ch + 1;
            uint32_t dhi = 16384u + (uint32_t)((nc & 1) * 32768);
            const __half* shi = g_nW1t_hi + (size_t)bn * 192 + nc * 64 + bq * 32;
            const __half* slo = g_nW1t_lo + (size_t)bn * 192 + nc * 64 + bq * 32;
#pragma unroll
            for (int j = 0; j < 4; j++) {
                uint32_t off = panel_off((uint32_t)bn, (uint32_t)(bq * 32 + j * 8));
                cp16(sb + dhi + off, shi + j * 8);
                cp16(sb + dhi + 16384u + off, slo + j * 8);
            }
            CP_COMMIT();
            const float* rowp = (nc < 2) ? xn + grow * NODE_C + nc * 64
                                         : g_aggr + grow * EDGE_C;
            const float4* rp = reinterpret_cast<const float4*>(rowp) + gq * 4;
#pragma unroll
            for (int i = 0; i < 4; i++)
                av[i] = gvalid ? rp[i] : make_float4(0.f, 0.f, 0.f, 0.f);
        } else {
            // prefetch B2 (nW2t 128x128): hi p0@48K p1@64K, lo p0@80K p1@96K
            const __half* shi = g_nW2t_hi + (size_t)bn * 128;
            const __half* slo = g_nW2t_lo + (size_t)bn * 128;
#pragma unroll
            for (int j = 0; j < 8; j++) {
                int seg = bq * 8 + j;
                uint32_t p = (uint32_t)(seg >> 3);
                uint32_t off = p * 16384u + panel_off((uint32_t)bn, (uint32_t)((seg & 7) * 8));
                cp16(sb + 49152u + off, shi + seg * 8);
                cp16(sb + 81920u + off, slo + seg * 8);
            }
            CP_COMMIT();
        }
        CP_WAIT(1);
        __syncthreads();

        const uint32_t Bhi = sb + 16384u + (uint32_t)((ch & 1) * 32768);
        const uint32_t Blo = Bhi + 16384u;
#pragma unroll
        for (int ks = 0; ks < 4; ks++) {
            const uint32_t kb = ks * 16;
            uint32_t ah[2][4], al[2][4];
#pragma unroll
            for (int mf = 0; mf < 2; mf++) {
                uint32_t r = (uint32_t)(mw * 32 + mf * 16) + la_r;
                uint32_t po = panel_off(r, kb + la_kb);
                ldsm_x4(ah[mf], sb + po);
                ldsm_x4(al[mf], sb + 8192u + po);
            }
#pragma unroll
            for (int nf = 0; nf < 4; nf++) {
                uint32_t n = (uint32_t)(nw * 32 + nf * 8) + lb_r;
                uint32_t po = panel_off(n, kb + lb_kb);
                uint32_t bh[2], bl[2];
                ldsm_x2(bh, Bhi + po);
                ldsm_x2(bl, Blo + po);
#pragma unroll
                for (int mf = 0; mf < 2; mf++) {
                    MMA16816(c[mf][nf], ah[mf], bh);
                    MMA16816(c[mf][nf], ah[mf], bl);
                    MMA16816(c[mf][nf], al[mf], bh);
                }
            }
        }
    }
    __syncthreads();

    // Epilogue1: bias + SiLU -> h split
    {
        const int l4 = lane >> 2;
        const int l2 = (lane & 3) * 2;
        const uint32_t p = (uint32_t)(nw >> 1);
        const uint32_t hb_hi = p * 8192u;
        const uint32_t hb_lo = 16384u + p * 8192u;
#pragma unroll
        for (int nf = 0; nf < 4; nf++) {
            int col = nw * 32 + nf * 8 + l2;
            float b0 = __ldg(nb1 + col), b1 = __ldg(nb1 + col + 1);
            uint32_t kk = (uint32_t)((nw & 1) * 32 + nf * 8 + l2);
#pragma unroll
            for (int mf = 0; mf < 2; mf++) {
                uint32_t m = (uint32_t)(mw * 32 + mf * 16 + l4);
                float x0 = silu_f(c[mf][nf][0] + b0);
                float x1 = silu_f(c[mf][nf][1] + b1);
                float x2 = silu_f(c[mf][nf][2] + b0);
                float x3 = silu_f(c[mf][nf][3] + b1);
                float h0 = h_round(x0), h1 = h_round(x1);
                float h2 = h_round(x2), h3 = h_round(x3);
                uint32_t o0 = panel_off(m, kk);
                uint32_t o1 = panel_off(m + 8, kk);
                *(uint32_t*)(dsm + hb_hi + o0) = f16x2(h0, h1);
                *(uint32_t*)(dsm + hb_lo + o0) = f16x2(x0 - h0, x1 - h1);
                *(uint32_t*)(dsm + hb_hi + o1) = f16x2(h2, h3);
                *(uint32_t*)(dsm + hb_lo + o1) = f16x2(x2 - h2, x3 - h3);
            }
        }
    }
    CP_WAIT(0);
    __syncthreads();

    // GEMM2: h[64,128] @ nW2t^T -> [64,128]
    float c2[2][4][4];
#pragma unroll
    for (int a = 0; a < 2; a++)
#pragma unroll
        for (int b = 0; b < 4; b++)
#pragma unroll
            for (int d = 0; d < 4; d++) c2[a][b][d] = 0.f;

#pragma unroll
    for (int p = 0; p < 2; p++) {
        const uint32_t Ah = sb + (uint32_t)p * 8192u;
        const uint32_t Al = sb + 16384u + (uint32_t)p * 8192u;
        const uint32_t Bh = sb + 49152u + (uint32_t)p * 16384u;
        const uint32_t Bl = sb + 81920u + (uint32_t)p * 16384u;
#pragma unroll
        for (int ks = 0; ks < 4; ks++) {
            const uint32_t kb = ks * 16;
            uint32_t ah[2][4], al[2][4];
#pragma unroll
            for (int mf = 0; mf < 2; mf++) {
                uint32_t r = (uint32_t)(mw * 32 + mf * 16) + la_r;
                uint32_t po = panel_off(r, kb + la_kb);
                ldsm_x4(ah[mf], Ah + po);
                ldsm_x4(al[mf], Al + po);
            }
#pragma unroll
            for (int nf = 0; nf < 4; nf++) {
                uint32_t n = (uint32_t)(nw * 32 + nf * 8) + lb_r;
                uint32_t po = panel_off(n, kb + lb_kb);
                uint32_t bh[2], bl[2];
                ldsm_x2(bh, Bh + po);
                ldsm_x2(bl, Bl + po);
#pragma unroll
                for (int mf = 0; mf < 2; mf++) {
                    MMA16816(c2[mf][nf], ah[mf], bh);
                    MMA16816(c2[mf][nf], ah[mf], bl);
                    MMA16816(c2[mf][nf], al[mf], bh);
                }
            }
        }
    }

    // Epilogue2: + bias, store
    {
        const int l4 = lane >> 2;
        const int l2 = (lane & 3) * 2;
        float b0[4], b1[4];
#pragma unroll
        for (int nf = 0; nf < 4; nf++) {
            int col = nw * 32 + nf * 8 + l2;
            b0[nf] = __ldg(nb2 + col);
            b1[nf] = __ldg(nb2 + col + 1);
        }
#pragma unroll
        for (int mf = 0; mf < 2; mf++) {
#pragma unroll
            for (int half = 0; half < 2; half++) {
                size_t row = (size_t)m0 + mw * 32 + mf * 16 + l4 + half * 8;
                if (row < N_NODES) {
                    float* orow = nodes_out + row * NODE_C;
#pragma unroll
                    for (int nf = 0; nf < 4; nf++) {
                        int col = nw * 32 + nf * 8 + l2;
                        float2 ov;
                        ov.x = c2[mf][nf][half * 2]     + b0[nf];
                        ov.y = c2[mf][nf][half * 2 + 1] + b1[nf];
                        *reinterpret_cast<float2*>(orow + col) = ov;
                    }
                }
            }
        }
    }
}

// ---------------------------------------------------------------------------
extern "C" void kernel_launch(void* const* d_in, const int* in_sizes, int n_in,
                              void* d_out, int out_size)
{
    const float* xn   = (const float*)d_in[0];
    const float* xe   = (const float*)d_in[1];
    const void*  eidx =               d_in[2];
    const float* eW1  = (const float*)d_in[3];
    const float* eb1  = (const float*)d_in[4];
    const float* eW2  = (const float*)d_in[5];
    const float* eb2  = (const float*)d_in[6];
    const float* nW1  = (const float*)d_in[7];
    const float* nb1  = (const float*)d_in[8];
    const float* nW2  = (const float*)d_in[9];
    const float* nb2  = (const float*)d_in[10];

    float* nodes_out = (float*)d_out;
    float* edges_out = (float*)d_out + (size_t)N_NODES * NODE_C;

    cudaFuncSetAttribute(edge_mma_kernel, cudaFuncAttributeMaxDynamicSharedMemorySize, EDGE_SMEM);
    cudaFuncSetAttribute(node_mma_kernel, cudaFuncAttributeMaxDynamicSharedMemorySize, NODE_SMEM);

    prep_weights_kernel<<<160, 256>>>(eW1, eW2, nW1, nW2);
    zero_aggr_kernel<<<(N_NODES * EDGE_C / 4 + 255) / 256, 256>>>();
    edge_mma_kernel<<<N_EDGES / 64, 256, EDGE_SMEM>>>(xn, xe, eidx, eb1, eb2, edges_out);
    node_mma_kernel<<<(N_NODES + 63) / 64, 256, NODE_SMEM>>>(xn, nb1, nb2, nodes_out);
}

// round 7
// speedup vs baseline: 3.1076x; 1.0404x over previous
#include <cuda_runtime.h>
#include <cuda_fp16.h>
#include <cstdint>

#define N_NODES 50000
#define N_EDGES 800000
#define NODE_C  128
#define EDGE_C  64

// ---------------------------------------------------------------------------
// Device scratch (no cudaMalloc allowed)
// ---------------------------------------------------------------------------
__device__ float g_aggr[(size_t)N_NODES * EDGE_C];
// Pre-transposed, fp16 hi/lo-split weights: Wt[n][k] = W[k][n]
__device__ __align__(16) __half g_eW1t_hi[128 * 320];
__device__ __align__(16) __half g_eW1t_lo[128 * 320];
__device__ __align__(16) __half g_eW2t_hi[64 * 128];
__device__ __align__(16) __half g_eW2t_lo[64 * 128];
__device__ __align__(16) __half g_nW1t_hi[128 * 192];
__device__ __align__(16) __half g_nW1t_lo[128 * 192];
__device__ __align__(16) __half g_nW2t_hi[128 * 128];
__device__ __align__(16) __half g_nW2t_lo[128 * 128];

// ---------------------------------------------------------------------------
// Helpers
// ---------------------------------------------------------------------------
__device__ __forceinline__ uint32_t smem_u32(const void* p) {
    uint32_t a;
    asm("{ .reg .u64 t; cvta.to.shared.u64 t, %1; cvt.u32.u64 %0, t; }"
        : "=r"(a) : "l"(p));
    return a;
}

// Panels: [rows][64] fp16, 128-byte rows, XOR-swizzled 16B blocks.
__device__ __forceinline__ uint32_t panel_off(uint32_t r, uint32_t k) {
    return r * 128u + ((((k >> 3) ^ (r & 7u)) << 4) | ((k & 7u) << 1));
}

__device__ __forceinline__ void ldsm_x4(uint32_t* d, uint32_t a) {
    asm volatile("ldmatrix.sync.aligned.m8n8.x4.shared.b16 {%0,%1,%2,%3}, [%4];"
                 : "=r"(d[0]), "=r"(d[1]), "=r"(d[2]), "=r"(d[3]) : "r"(a));
}
__device__ __forceinline__ void ldsm_x2(uint32_t* d, uint32_t a) {
    asm volatile("ldmatrix.sync.aligned.m8n8.x2.shared.b16 {%0,%1}, [%2];"
                 : "=r"(d[0]), "=r"(d[1]) : "r"(a));
}

#define MMA16816(c, a, b) \
    asm volatile("mma.sync.aligned.m16n8k16.row.col.f32.f16.f16.f32 " \
        "{%0,%1,%2,%3},{%4,%5,%6,%7},{%8,%9},{%0,%1,%2,%3};" \
        : "+f"((c)[0]), "+f"((c)[1]), "+f"((c)[2]), "+f"((c)[3]) \
        : "r"((a)[0]), "r"((a)[1]), "r"((a)[2]), "r"((a)[3]), \
          "r"((b)[0]), "r"((b)[1]))

__device__ __forceinline__ void cp16(uint32_t dst, const void* src) {
    asm volatile("cp.async.cg.shared.global [%0], [%1], 16;"
                 :: "r"(dst), "l"(src) : "memory");
}
#define CP_COMMIT() asm volatile("cp.async.commit_group;" ::: "memory")
#define CP_WAIT(n)  asm volatile("cp.async.wait_group %0;" :: "n"(n) : "memory")

__device__ __forceinline__ uint32_t f16x2(float lo, float hi) {
    uint32_t r;
    asm("cvt.rn.f16x2.f32 %0, %1, %2;" : "=r"(r) : "f"(hi), "f"(lo));
    return r;
}
__device__ __forceinline__ float h_round(float x) {
    return __half2float(__float2half_rn(x));
}
__device__ __forceinline__ float silu_f(float x) {
    return x / (1.0f + __expf(-x));
}
__device__ __forceinline__ void split8(float4 v0, float4 v1, uint4& hi, uint4& lo) {
    float a0 = h_round(v0.x), a1 = h_round(v0.y), a2 = h_round(v0.z), a3 = h_round(v0.w);
    float a4 = h_round(v1.x), a5 = h_round(v1.y), a6 = h_round(v1.z), a7 = h_round(v1.w);
    hi.x = f16x2(a0, a1); hi.y = f16x2(a2, a3); hi.z = f16x2(a4, a5); hi.w = f16x2(a6, a7);
    lo.x = f16x2(v0.x - a0, v0.y - a1);
    lo.y = f16x2(v0.z - a2, v0.w - a3);
    lo.z = f16x2(v1.x - a4, v1.y - a5);
    lo.w = f16x2(v1.z - a6, v1.w - a7);
}

// ---------------------------------------------------------------------------
// Setup kernels
// ---------------------------------------------------------------------------
__global__ void zero_aggr_kernel() {
    size_t i = (size_t)blockIdx.x * blockDim.x + threadIdx.x;
    size_t n4 = (size_t)N_NODES * EDGE_C / 4;
    if (i < n4) reinterpret_cast<float4*>(g_aggr)[i] = make_float4(0.f, 0.f, 0.f, 0.f);
}

__global__ void prep_weights_kernel(const float* __restrict__ eW1,
                                    const float* __restrict__ eW2,
                                    const float* __restrict__ nW1,
                                    const float* __restrict__ nW2) {
    int i = blockIdx.x * 256 + threadIdx.x;
    if (i < 128 * 320) {
        int n = i / 320, k = i % 320;
        float v = eW1[(size_t)k * 128 + n];
        float h = h_round(v);
        g_eW1t_hi[i] = __float2half_rn(h);
        g_eW1t_lo[i] = __float2half_rn(v - h);
    }
    if (i < 64 * 128) {
        int n = i / 128, k = i % 128;
        float v = eW2[(size_t)k * 64 + n];
        float h = h_round(v);
        g_eW2t_hi[i] = __float2half_rn(h);
        g_eW2t_lo[i] = __float2half_rn(v - h);
    }
    if (i < 128 * 192) {
        int n = i / 192, k = i % 192;
        float v = nW1[(size_t)k * 128 + n];
        float h = h_round(v);
        g_nW1t_hi[i] = __float2half_rn(h);
        g_nW1t_lo[i] = __float2half_rn(v - h);
    }
    if (i < 128 * 128) {
        int n = i / 128, k = i % 128;
        float v = nW2[(size_t)k * 128 + n];
        float h = h_round(v);
        g_nW2t_hi[i] = __float2half_rn(h);
        g_nW2t_lo[i] = __float2half_rn(v - h);
    }
}

// ---------------------------------------------------------------------------
// Edge kernel: 128 edges / CTA, 256 threads, 8 warps = 4 M-strips x 2 N-strips
// Warp tile 32x64 (GEMM1). 2 CTAs/SM. SMEM 96KB:
//   A_hi@0 (16K), A_lo@16K (16K)
//   B buf0: hi@32K lo@48K;  buf1: hi@64K lo@80K
//   After GEMM1:
//     h_hi p0@0 p1@16K, h_lo p0@32K p1@48K
//     B2 (eW2t 64x128): hi p0@64K p1@72K, lo p0@80K p1@88K
// ---------------------------------------------------------------------------
#define EDGE_SMEM  98304
#define NODE_SMEM 114688

__global__ __launch_bounds__(256, 2)
void edge_mma_kernel(const float* __restrict__ xn,
                     const float* __restrict__ xe,
                     const void*  __restrict__ eidx,
                     const float* __restrict__ eb1,
                     const float* __restrict__ eb2,
                     float* __restrict__ edges_out)
{
    extern __shared__ __align__(1024) char dsm[];
    __shared__ int s_snd[128], s_rcv[128];

    const int tid  = threadIdx.x;
    const int wid  = tid >> 5;
    const int lane = tid & 31;
    const int mw   = wid & 3;      // 32-row strip (4 strips over 128 rows)
    const int nw   = wid >> 2;     // 64-col strip (GEMM1) / 32-col (GEMM2)
    const int e0   = blockIdx.x * 128;

    const uint32_t sb = smem_u32(dsm);
    // A ldmatrix.x4 lanes: 16 rows x 2 k-blocks
    const uint32_t la_r  = lane & 15;
    const uint32_t la_kb = (lane >> 4) << 3;
    // B ldmatrix.x4 lanes: (n, n+8) pair x 2 k-blocks
    const uint32_t lb_r  = (lane & 7) | ((lane >> 4) << 3);
    const uint32_t lb_kb = ((lane >> 3) & 1) << 3;

    // edge indices
    {
        const unsigned* w = reinterpret_cast<const unsigned*>(eidx);
        const bool is64 = ((w[1] | w[3] | w[5] | w[7] | w[9] | w[11] | w[13] | w[15]) == 0u);
        if (tid < 128) {
            size_t e = (size_t)e0 + tid;
            if (is64) {
                const long long* p = reinterpret_cast<const long long*>(eidx);
                s_snd[tid] = (int)p[e];
                s_rcv[tid] = (int)p[(size_t)N_EDGES + e];
            } else {
                const int* p = reinterpret_cast<const int*>(eidx);
                s_snd[tid] = p[e];
                s_rcv[tid] = p[(size_t)N_EDGES + e];
            }
        }
    }
    __syncthreads();

    const int gm = tid >> 1;      // gather row (0..127), 2 threads/row
    const int gh = tid & 1;       // 32-float half of the 64-k chunk
    const int bn = tid >> 1;      // weight row (0..127)
    const int bq = tid & 1;       // 32-k half
    const int my_snd = s_snd[gm];
    const int my_rcv = s_rcv[gm];

    // prefetch chunk 0 B
    {
        const __half* shi = g_eW1t_hi + (size_t)bn * 320 + bq * 32;
        const __half* slo = g_eW1t_lo + (size_t)bn * 320 + bq * 32;
#pragma unroll
        for (int j = 0; j < 4; j++) {
            uint32_t off = panel_off((uint32_t)bn, (uint32_t)(bq * 32 + j * 8));
            cp16(sb + 32768u + off, shi + j * 8);
            cp16(sb + 49152u + off, slo + j * 8);
        }
        CP_COMMIT();
    }
    // prefetch chunk 0 A first half (16 of my 32 floats)
    const float4* cur_rp = reinterpret_cast<const float4*>(xn + (size_t)my_snd * NODE_C) + gh * 8;
    float4 av[4];
#pragma unroll
    for (int i = 0; i < 4; i++) av[i] = cur_rp[i];

    float c[2][8][4];
#pragma unroll
    for (int a = 0; a < 2; a++)
#pragma unroll
        for (int b = 0; b < 8; b++)
#pragma unroll
            for (int d = 0; d < 4; d++) c[a][b][d] = 0.f;

    // ---------------- GEMM1: 5 K-chunks of 64 ----------------
#pragma unroll 1
    for (int ch = 0; ch < 5; ch++) {
        __syncthreads();   // prev MMAs done with A panel & the B buffer being filled
        // issue second-half A loads now (latency hides under STS + cp.async below)
        float4 av2[4];
#pragma unroll
        for (int i = 0; i < 4; i++) av2[i] = cur_rp[4 + i];
        // store first half
#pragma unroll
        for (int i = 0; i < 2; i++) {
            uint4 hi, lo;
            split8(av[2 * i], av[2 * i + 1], hi, lo);
            uint32_t off = panel_off((uint32_t)gm, (uint32_t)(gh * 32 + i * 8));
            *(uint4*)(dsm + off)         = hi;
            *(uint4*)(dsm + 16384 + off) = lo;
        }
        if (ch < 4) {
            const int nc = ch + 1;
            uint32_t dhi = 32768u + (uint32_t)((nc & 1) * 32768);
            const __half* shi = g_eW1t_hi + (size_t)bn * 320 + nc * 64 + bq * 32;
            const __half* slo = g_eW1t_lo + (size_t)bn * 320 + nc * 64 + bq * 32;
#pragma unroll
            for (int j = 0; j < 4; j++) {
                uint32_t off = panel_off((uint32_t)bn, (uint32_t)(bq * 32 + j * 8));
                cp16(sb + dhi + off, shi + j * 8);
                cp16(sb + dhi + 16384u + off, slo + j * 8);
            }
            CP_COMMIT();
            // next chunk's A row pointer + first-half prefetch
            const float* rowp;
            if (nc < 2)      rowp = xn + (size_t)my_snd * NODE_C + nc * 64;
            else if (nc < 4) rowp = xn + (size_t)my_rcv * NODE_C + (nc - 2) * 64;
            else             rowp = xe + (size_t)(e0 + gm) * EDGE_C;
            cur_rp = reinterpret_cast<const float4*>(rowp) + gh * 8;
#pragma unroll
            for (int i = 0; i < 4; i++) av[i] = cur_rp[i];
        } else {
            // prefetch B2 (eW2t 64x128): hi p0@64K p1@72K, lo p0@80K p1@88K
            const int n2 = tid >> 2;
            const int q2 = tid & 3;
            const __half* shi = g_eW2t_hi + (size_t)n2 * 128;
            const __half* slo = g_eW2t_lo + (size_t)n2 * 128;
#pragma unroll
            for (int j = 0; j < 4; j++) {
                int seg = q2 * 4 + j;
                uint32_t p = (uint32_t)(seg >> 3);
                uint32_t off = p * 8192u + panel_off((uint32_t)n2, (uint32_t)((seg & 7) * 8));
                cp16(sb + 65536u + off, shi + seg * 8);
                cp16(sb + 81920u + off, slo + seg * 8);
            }
            CP_COMMIT();
        }
        // store second half
#pragma unroll
        for (int i = 0; i < 2; i++) {
            uint4 hi, lo;
            split8(av2[2 * i], av2[2 * i + 1], hi, lo);
            uint32_t off = panel_off((uint32_t)gm, (uint32_t)(gh * 32 + 16 + i * 8));
            *(uint4*)(dsm + off)         = hi;
            *(uint4*)(dsm + 16384 + off) = lo;
        }
        CP_WAIT(1);
        __syncthreads();

        const uint32_t Bhi = sb + 32768u + (uint32_t)((ch & 1) * 32768);
        const uint32_t Blo = Bhi + 16384u;
#pragma unroll
        for (int ks = 0; ks < 4; ks++) {
            const uint32_t kb = ks * 16;
            uint32_t ah[2][4], al[2][4];
#pragma unroll
            for (int mf = 0; mf < 2; mf++) {
                uint32_t r = (uint32_t)(mw * 32 + mf * 16) + la_r;
                uint32_t po = panel_off(r, kb + la_kb);
                ldsm_x4(ah[mf], sb + po);
                ldsm_x4(al[mf], sb + 16384u + po);
            }
#pragma unroll
            for (int np = 0; np < 4; np++) {   // 4 n-frag pairs = 64 cols
                uint32_t n = (uint32_t)(nw * 64 + np * 16) + lb_r;
                uint32_t po = panel_off(n, kb + lb_kb);
                uint32_t bh4[4], bl4[4];
                ldsm_x4(bh4, Bhi + po);
                ldsm_x4(bl4, Blo + po);
#pragma unroll
                for (int mf = 0; mf < 2; mf++) {
                    MMA16816(c[mf][np * 2],     ah[mf], bh4);
                    MMA16816(c[mf][np * 2],     ah[mf], bl4);
                    MMA16816(c[mf][np * 2],     al[mf], bh4);
                    MMA16816(c[mf][np * 2 + 1], ah[mf], bh4 + 2);
                    MMA16816(c[mf][np * 2 + 1], ah[mf], bl4 + 2);
                    MMA16816(c[mf][np * 2 + 1], al[mf], bh4 + 2);
                }
            }
        }
    }
    __syncthreads();

    // ------------- Epilogue1: bias + SiLU -> h split panels -------------
    {
        const int l4 = lane >> 2;
        const int l2 = (lane & 3) * 2;
        const uint32_t hb_hi = (uint32_t)nw * 16384u;           // p = nw
        const uint32_t hb_lo = 32768u + (uint32_t)nw * 16384u;
#pragma unroll
        for (int nf = 0; nf < 8; nf++) {
            int col = nw * 64 + nf * 8 + l2;
            float b0 = __ldg(eb1 + col), b1 = __ldg(eb1 + col + 1);
            uint32_t kk = (uint32_t)(nf * 8 + l2);
#pragma unroll
            for (int mf = 0; mf < 2; mf++) {
                uint32_t m = (uint32_t)(mw * 32 + mf * 16 + l4);
                float x0 = silu_f(c[mf][nf][0] + b0);
                float x1 = silu_f(c[mf][nf][1] + b1);
                float x2 = silu_f(c[mf][nf][2] + b0);
                float x3 = silu_f(c[mf][nf][3] + b1);
                float h0 = h_round(x0), h1 = h_round(x1);
                float h2 = h_round(x2), h3 = h_round(x3);
                uint32_t o0 = panel_off(m, kk);
                uint32_t o1 = panel_off(m + 8, kk);
                *(uint32_t*)(dsm + hb_hi + o0) = f16x2(h0, h1);
                *(uint32_t*)(dsm + hb_lo + o0) = f16x2(x0 - h0, x1 - h1);
                *(uint32_t*)(dsm + hb_hi + o1) = f16x2(h2, h3);
                *(uint32_t*)(dsm + hb_lo + o1) = f16x2(x2 - h2, x3 - h3);
            }
        }
    }
    CP_WAIT(0);
    __syncthreads();

    // ---------------- GEMM2: h[128,128] @ eW2t^T -> [128,64] ----------------
    float c2[2][4][4];
#pragma unroll
    for (int a = 0; a < 2; a++)
#pragma unroll
        for (int b = 0; b < 4; b++)
#pragma unroll
            for (int d = 0; d < 4; d++) c2[a][b][d] = 0.f;

#pragma unroll
    for (int p = 0; p < 2; p++) {
        const uint32_t Ah = sb + (uint32_t)p * 16384u;
        const uint32_t Al = sb + 32768u + (uint32_t)p * 16384u;
        const uint32_t Bh = sb + 65536u + (uint32_t)p * 8192u;
        const uint32_t Bl = sb + 81920u + (uint32_t)p * 8192u;
#pragma unroll
        for (int ks = 0; ks < 4; ks++) {
            const uint32_t kb = ks * 16;
            uint32_t ah[2][4], al[2][4];
#pragma unroll
            for (int mf = 0; mf < 2; mf++) {
                uint32_t r = (uint32_t)(mw * 32 + mf * 16) + la_r;
                uint32_t po = panel_off(r, kb + la_kb);
                ldsm_x4(ah[mf], Ah + po);
                ldsm_x4(al[mf], Al + po);
            }
#pragma unroll
            for (int np = 0; np < 2; np++) {   // 2 n-frag pairs = 32 cols
                uint32_t n = (uint32_t)(nw * 32 + np * 16) + lb_r;
                uint32_t po = panel_off(n, kb + lb_kb);
                uint32_t bh4[4], bl4[4];
                ldsm_x4(bh4, Bh + po);
                ldsm_x4(bl4, Bl + po);
#pragma unroll
                for (int mf = 0; mf < 2; mf++) {
                    MMA16816(c2[mf][np * 2],     ah[mf], bh4);
                    MMA16816(c2[mf][np * 2],     ah[mf], bl4);
                    MMA16816(c2[mf][np * 2],     al[mf], bh4);
                    MMA16816(c2[mf][np * 2 + 1], ah[mf], bh4 + 2);
                    MMA16816(c2[mf][np * 2 + 1], ah[mf], bl4 + 2);
                    MMA16816(c2[mf][np * 2 + 1], al[mf], bh4 + 2);
                }
            }
        }
    }

    // ------------- Epilogue2: SiLU, store, scatter-add -------------
    {
        const int l4 = lane >> 2;
        const int l2 = (lane & 3) * 2;
        float b0[4], b1[4];
#pragma unroll
        for (int nf = 0; nf < 4; nf++) {
            int col = nw * 32 + nf * 8 + l2;
            b0[nf] = __ldg(eb2 + col);
            b1[nf] = __ldg(eb2 + col + 1);
        }
#pragma unroll
        for (int mf = 0; mf < 2; mf++) {
#pragma unroll
            for (int half = 0; half < 2; half++) {
                int m = mw * 32 + mf * 16 + l4 + half * 8;
                int rcv = s_rcv[m];
                float* orow = edges_out + (size_t)(e0 + m) * EDGE_C;
                float* arow = g_aggr + (size_t)rcv * EDGE_C;
#pragma unroll
                for (int nf = 0; nf < 4; nf++) {
                    int col = nw * 32 + nf * 8 + l2;
                    float o0 = silu_f(c2[mf][nf][half * 2]     + b0[nf]);
                    float o1 = silu_f(c2[mf][nf][half * 2 + 1] + b1[nf]);
                    float2 ov = {o0, o1};
                    *reinterpret_cast<float2*>(orow + col) = ov;
                    atomicAdd(arow + col,     o0);
                    atomicAdd(arow + col + 1, o1);
                }
            }
        }
    }
}

// ---------------------------------------------------------------------------
// Node kernel: 64 nodes / CTA, 256 threads, 2 CTAs/SM (unchanged from R6)
// ---------------------------------------------------------------------------
__global__ __launch_bounds__(256, 2)
void node_mma_kernel(const float* __restrict__ xn,
                     const float* __restrict__ nb1,
                     const float* __restrict__ nb2,
                     float* __restrict__ nodes_out)
{
    extern __shared__ __align__(1024) char dsm[];

    const int tid  = threadIdx.x;
    const int wid  = tid >> 5;
    const int lane = tid & 31;
    const int mw   = wid & 1;
    const int nw   = wid >> 1;
    const int m0   = blockIdx.x * 64;

    const uint32_t sb = smem_u32(dsm);
    const uint32_t la_r  = lane & 15;
    const uint32_t la_kb = (lane >> 4) << 3;
    const uint32_t lb_r  = lane & 7;
    const uint32_t lb_kb = ((lane >> 3) & 1) << 3;

    const int gm = tid >> 2;
    const int gq = tid & 3;
    const int bn = tid >> 1;
    const int bq = tid & 1;
    const size_t grow = (size_t)m0 + gm;
    const bool gvalid = grow < N_NODES;

    {
        const __half* shi = g_nW1t_hi + (size_t)bn * 192 + bq * 32;
        const __half* slo = g_nW1t_lo + (size_t)bn * 192 + bq * 32;
#pragma unroll
        for (int j = 0; j < 4; j++) {
            uint32_t off = panel_off((uint32_t)bn, (uint32_t)(bq * 32 + j * 8));
            cp16(sb + 16384u + off, shi + j * 8);
            cp16(sb + 32768u + off, slo + j * 8);
        }
        CP_COMMIT();
    }
    float4 av[4];
    {
        const float4* rp = reinterpret_cast<const float4*>(xn + grow * NODE_C) + gq * 4;
#pragma unroll
        for (int i = 0; i < 4; i++)
            av[i] = gvalid ? rp[i] : make_float4(0.f, 0.f, 0.f, 0.f);
    }

    float c[2][4][4];
#pragma unroll
    for (int a = 0; a < 2; a++)
#pragma unroll
        for (int b = 0; b < 4; b++)
#pragma unroll
            for (int d = 0; d < 4; d++) c[a][b][d] = 0.f;

#pragma unroll 1
    for (int ch = 0; ch < 3; ch++) {
        __syncthreads();
#pragma unroll
        for (int i = 0; i < 2; i++) {
            uint4 hi, lo;
            split8(av[2 * i], av[2 * i + 1], hi, lo);
            uint32_t off = panel_off((uint32_t)gm, (uint32_t)(gq * 16 + i * 8));
            *(uint4*)(dsm + off)        = hi;
            *(uint4*)(dsm + 8192 + off) = lo;
        }
        if (ch < 2) {
            const int nc = ch + 1;
            uint32_t dhi = 16384u + (uint32_t)((nc & 1) * 32768);
            const __half* shi = g_nW1t_hi + (size_t)bn * 192 + nc * 64 + bq * 32;
            const __half* slo = g_nW1t_lo + (size_t)bn * 192 + nc * 64 + bq * 32;
#pragma unroll
            for (int j = 0; j < 4; j++) {
                uint32_t off = panel_off((uint32_t)bn, (uint32_t)(bq * 32 + j * 8));
                cp16(sb + dhi + off, shi + j * 8);
                cp16(sb + dhi + 16384u + off, slo + j * 8);
            }
            CP_COMMIT();
            const float* rowp = (nc < 2) ? xn + grow * NODE_C + nc * 64
                                         : g_aggr + grow * EDGE_C;
            const float4* rp = reinterpret_cast<const float4*>(rowp) + gq * 4;
#pragma unroll
            for (int i = 0; i < 4; i++)
                av[i] = gvalid ? rp[i] : make_float4(0.f, 0.f, 0.f, 0.f);
        } else {
            const __half* shi = g_nW2t_hi + (size_t)bn * 128;
            const __half* slo = g_nW2t_lo + (size_t)bn * 128;
#pragma unroll
            for (int j = 0; j < 8; j++) {
                int seg = bq * 8 + j;
                uint32_t p = (uint32_t)(seg >> 3);
                uint32_t off = p * 16384u + panel_off((uint32_t)bn, (uint32_t)((seg & 7) * 8));
                cp16(sb + 49152u + off, shi + seg * 8);
                cp16(sb + 81920u + off, slo + seg * 8);
            }
            CP_COMMIT();
        }
        CP_WAIT(1);
        __syncthreads();

        const uint32_t Bhi = sb + 16384u + (uint32_t)((ch & 1) * 32768);
        const uint32_t Blo = Bhi + 16384u;
#pragma unroll
        for (int ks = 0; ks < 4; ks++) {
            const uint32_t kb = ks * 16;
            uint32_t ah[2][4], al[2][4];
#pragma unroll
            for (int mf = 0; mf < 2; mf++) {
                uint32_t r = (uint32_t)(mw * 32 + mf * 16) + la_r;
                uint32_t po = panel_off(r, kb + la_kb);
                ldsm_x4(ah[mf], sb + po);
                ldsm_x4(al[mf], sb + 8192u + po);
            }
#pragma unroll
            for (int nf = 0; nf < 4; nf++) {
                uint32_t n = (uint32_t)(nw * 32 + nf * 8) + lb_r;
                uint32_t po = panel_off(n, kb + lb_kb);
                uint32_t bh[2], bl[2];
                ldsm_x2(bh, Bhi + po);
                ldsm_x2(bl, Blo + po);
#pragma unroll
                for (int mf = 0; mf < 2; mf++) {
                    MMA16816(c[mf][nf], ah[mf], bh);
                    MMA16816(c[mf][nf], ah[mf], bl);
                    MMA16816(c[mf][nf], al[mf], bh);
                }
            }
        }
    }
    __syncthreads();

    {
        const int l4 = lane >> 2;
        const int l2 = (lane & 3) * 2;
        const uint32_t p = (uint32_t)(nw >> 1);
        const uint32_t hb_hi = p * 8192u;
        const uint32_t hb_lo = 16384u + p * 8192u;
#pragma unroll
        for (int nf = 0; nf < 4; nf++) {
            int col = nw * 32 + nf * 8 + l2;
            float b0 = __ldg(nb1 + col), b1 = __ldg(nb1 + col + 1);
            uint32_t kk = (uint32_t)((nw & 1) * 32 + nf * 8 + l2);
#pragma unroll
            for (int mf = 0; mf < 2; mf++) {
                uint32_t m = (uint32_t)(mw * 32 + mf * 16 + l4);
                float x0 = silu_f(c[mf][nf][0] + b0);
                float x1 = silu_f(c[mf][nf][1] + b1);
                float x2 = silu_f(c[mf][nf][2] + b0);
                float x3 = silu_f(c[mf][nf][3] + b1);
                float h0 = h_round(x0), h1 = h_round(x1);
                float h2 = h_round(x2), h3 = h_round(x3);
                uint32_t o0 = panel_off(m, kk);
                uint32_t o1 = panel_off(m + 8, kk);
                *(uint32_t*)(dsm + hb_hi + o0) = f16x2(h0, h1);
                *(uint32_t*)(dsm + hb_lo + o0) = f16x2(x0 - h0, x1 - h1);
                *(uint32_t*)(dsm + hb_hi + o1) = f16x2(h2, h3);
                *(uint32_t*)(dsm + hb_lo + o1) = f16x2(x2 - h2, x3 - h3);
            }
        }
    }
    CP_WAIT(0);
    __syncthreads();

    float c2[2][4][4];
#pragma unroll
    for (int a = 0; a < 2; a++)
#pragma unroll
        for (int b = 0; b < 4; b++)
#pragma unroll
            for (int d = 0; d < 4; d++) c2[a][b][d] = 0.f;

#pragma unroll
    for (int p = 0; p < 2; p++) {
        const uint32_t Ah = sb + (uint32_t)p * 8192u;
        const uint32_t Al = sb + 16384u + (uint32_t)p * 8192u;
        const uint32_t Bh = sb + 49152u + (uint32_t)p * 16384u;
        const uint32_t Bl = sb + 81920u + (uint32_t)p * 16384u;
#pragma unroll
        for (int ks = 0; ks < 4; ks++) {
            const uint32_t kb = ks * 16;
            uint32_t ah[2][4], al[2][4];
#pragma unroll
            for (int mf = 0; mf < 2; mf++) {
                uint32_t r = (uint32_t)(mw * 32 + mf * 16) + la_r;
                uint32_t po = panel_off(r, kb + la_kb);
                ldsm_x4(ah[mf], Ah + po);
                ldsm_x4(al[mf], Al + po);
            }
#pragma unroll
            for (int nf = 0; nf < 4; nf++) {
                uint32_t n = (uint32_t)(nw * 32 + nf * 8) + lb_r;
                uint32_t po = panel_off(n, kb + lb_kb);
                uint32_t bh[2], bl[2];
                ldsm_x2(bh, Bh + po);
                ldsm_x2(bl, Bl + po);
#pragma unroll
                for (int mf = 0; mf < 2; mf++) {
                    MMA16816(c2[mf][nf], ah[mf], bh);
                    MMA16816(c2[mf][nf], ah[mf], bl);
                    MMA16816(c2[mf][nf], al[mf], bh);
                }
            }
        }
    }

    {
        const int l4 = lane >> 2;
        const int l2 = (lane & 3) * 2;
        float b0[4], b1[4];
#pragma unroll
        for (int nf = 0; nf < 4; nf++) {
            int col = nw * 32 + nf * 8 + l2;
            b0[nf] = __ldg(nb2 + col);
            b1[nf] = __ldg(nb2 + col + 1);
        }
#pragma unroll
        for (int mf = 0; mf < 2; mf++) {
#pragma unroll
            for (int half = 0; half < 2; half++) {
                size_t row = (size_t)m0 + mw * 32 + mf * 16 + l4 + half * 8;
                if (row < N_NODES) {
                    float* orow = nodes_out + row * NODE_C;
#pragma unroll
                    for (int nf = 0; nf < 4; nf++) {
                        int col = nw * 32 + nf * 8 + l2;
                        float2 ov;
                        ov.x = c2[mf][nf][half * 2]     + b0[nf];
                        ov.y = c2[mf][nf][half * 2 + 1] + b1[nf];
                        *reinterpret_cast<float2*>(orow + col) = ov;
                    }
                }
            }
        }
    }
}

// ---------------------------------------------------------------------------
extern "C" void kernel_launch(void* const* d_in, const int* in_sizes, int n_in,
                              void* d_out, int out_size)
{
    const float* xn   = (const float*)d_in[0];
    const float* xe   = (const float*)d_in[1];
    const void*  eidx =               d_in[2];
    const float* eW1  = (const float*)d_in[3];
    const float* eb1  = (const float*)d_in[4];
    const float* eW2  = (const float*)d_in[5];
    const float* eb2  = (const float*)d_in[6];
    const float* nW1  = (const float*)d_in[7];
    const float* nb1  = (const float*)d_in[8];
    const float* nW2  = (const float*)d_in[9];
    const float* nb2  = (const float*)d_in[10];

    float* nodes_out = (float*)d_out;
    float* edges_out = (float*)d_out + (size_t)N_NODES * NODE_C;

    cudaFuncSetAttribute(edge_mma_kernel, cudaFuncAttributeMaxDynamicSharedMemorySize, EDGE_SMEM);
    cudaFuncSetAttribute(node_mma_kernel, cudaFuncAttributeMaxDynamicSharedMemorySize, NODE_SMEM);

    prep_weights_kernel<<<160, 256>>>(eW1, eW2, nW1, nW2);
    zero_aggr_kernel<<<(N_NODES * EDGE_C / 4 + 255) / 256, 256>>>();
    edge_mma_kernel<<<N_EDGES / 128, 256, EDGE_SMEM>>>(xn, xe, eidx, eb1, eb2, edges_out);
    node_mma_kernel<<<(N_NODES + 63) / 64, 256, NODE_SMEM>>>(xn, nb1, nb2, nodes_out);
}

// round 8
// speedup vs baseline: 3.7629x; 1.2109x over previous
#include <cuda_runtime.h>
#include <cuda_fp16.h>
#include <cstdint>

#define N_NODES 50000
#define N_EDGES 800000
#define NODE_C  128
#define EDGE_C  64

// ---------------------------------------------------------------------------
// Device scratch (no cudaMalloc allowed)
// ---------------------------------------------------------------------------
__device__ float g_aggr[(size_t)N_NODES * EDGE_C];
// Pre-transposed single-fp16 weights: Wt[n][k] = W[k][n]
__device__ __align__(16) __half g_eW1t[128 * 320];
__device__ __align__(16) __half g_eW2t[64 * 128];
__device__ __align__(16) __half g_nW1t[128 * 192];
__device__ __align__(16) __half g_nW2t[128 * 128];

// ---------------------------------------------------------------------------
// Helpers
// ---------------------------------------------------------------------------
__device__ __forceinline__ uint32_t smem_u32(const void* p) {
    uint32_t a;
    asm("{ .reg .u64 t; cvta.to.shared.u64 t, %1; cvt.u32.u64 %0, t; }"
        : "=r"(a) : "l"(p));
    return a;
}

// Panels: [rows][64] fp16, 128-byte rows, XOR-swizzled 16B blocks.
__device__ __forceinline__ uint32_t panel_off(uint32_t r, uint32_t k) {
    return r * 128u + ((((k >> 3) ^ (r & 7u)) << 4) | ((k & 7u) << 1));
}

__device__ __forceinline__ void ldsm_x4(uint32_t* d, uint32_t a) {
    asm volatile("ldmatrix.sync.aligned.m8n8.x4.shared.b16 {%0,%1,%2,%3}, [%4];"
                 : "=r"(d[0]), "=r"(d[1]), "=r"(d[2]), "=r"(d[3]) : "r"(a));
}

#define MMA16816(c, a, b) \
    asm volatile("mma.sync.aligned.m16n8k16.row.col.f32.f16.f16.f32 " \
        "{%0,%1,%2,%3},{%4,%5,%6,%7},{%8,%9},{%0,%1,%2,%3};" \
        : "+f"((c)[0]), "+f"((c)[1]), "+f"((c)[2]), "+f"((c)[3]) \
        : "r"((a)[0]), "r"((a)[1]), "r"((a)[2]), "r"((a)[3]), \
          "r"((b)[0]), "r"((b)[1]))

__device__ __forceinline__ void cp16(uint32_t dst, const void* src) {
    asm volatile("cp.async.cg.shared.global [%0], [%1], 16;"
                 :: "r"(dst), "l"(src) : "memory");
}
#define CP_COMMIT() asm volatile("cp.async.commit_group;" ::: "memory")
#define CP_WAIT(n)  asm volatile("cp.async.wait_group %0;" :: "n"(n) : "memory")

__device__ __forceinline__ uint32_t f16x2(float lo, float hi) {
    uint32_t r;
    asm("cvt.rn.f16x2.f32 %0, %1, %2;" : "=r"(r) : "f"(hi), "f"(lo));
    return r;
}
__device__ __forceinline__ float h_round(float x) {
    return __half2float(__float2half_rn(x));
}
__device__ __forceinline__ float silu_f(float x) {
    return x / (1.0f + __expf(-x));
}
__device__ __forceinline__ void split8(float4 v0, float4 v1, uint4& hi, uint4& lo) {
    float a0 = h_round(v0.x), a1 = h_round(v0.y), a2 = h_round(v0.z), a3 = h_round(v0.w);
    float a4 = h_round(v1.x), a5 = h_round(v1.y), a6 = h_round(v1.z), a7 = h_round(v1.w);
    hi.x = f16x2(a0, a1); hi.y = f16x2(a2, a3); hi.z = f16x2(a4, a5); hi.w = f16x2(a6, a7);
    lo.x = f16x2(v0.x - a0, v0.y - a1);
    lo.y = f16x2(v0.z - a2, v0.w - a3);
    lo.z = f16x2(v1.x - a4, v1.y - a5);
    lo.w = f16x2(v1.z - a6, v1.w - a7);
}

// ---------------------------------------------------------------------------
// Setup kernels
// ---------------------------------------------------------------------------
__global__ void zero_aggr_kernel() {
    size_t i = (size_t)blockIdx.x * blockDim.x + threadIdx.x;
    size_t n4 = (size_t)N_NODES * EDGE_C / 4;
    if (i < n4) reinterpret_cast<float4*>(g_aggr)[i] = make_float4(0.f, 0.f, 0.f, 0.f);
}

__global__ void prep_weights_kernel(const float* __restrict__ eW1,
                                    const float* __restrict__ eW2,
                                    const float* __restrict__ nW1,
                                    const float* __restrict__ nW2) {
    int i = blockIdx.x * 256 + threadIdx.x;
    if (i < 128 * 320) {
        int n = i / 320, k = i % 320;
        g_eW1t[i] = __float2half_rn(eW1[(size_t)k * 128 + n]);
    }
    if (i < 64 * 128) {
        int n = i / 128, k = i % 128;
        g_eW2t[i] = __float2half_rn(eW2[(size_t)k * 64 + n]);
    }
    if (i < 128 * 192) {
        int n = i / 192, k = i % 192;
        g_nW1t[i] = __float2half_rn(nW1[(size_t)k * 128 + n]);
    }
    if (i < 128 * 128) {
        int n = i / 128, k = i % 128;
        g_nW2t[i] = __float2half_rn(nW2[(size_t)k * 128 + n]);
    }
}

// ---------------------------------------------------------------------------
// Edge kernel: 128 edges / CTA, 256 threads, 8 warps = 4 M-strips x 2 N-strips
// 2 CTAs/SM. SMEM 80KB:
//   A_hi@0 (16K), A_lo@16K (16K)
//   B buf0@32K (16K), buf1@48K (16K)
//   After GEMM1:
//     h_hi p0@0 p1@16K, h_lo p0@32K p1@48K
//     B2 (eW2t 64x128): p0@64K p1@72K
// ---------------------------------------------------------------------------
#define EDGE_SMEM 81920
#define NODE_SMEM 81920

__global__ __launch_bounds__(256, 2)
void edge_mma_kernel(const float* __restrict__ xn,
                     const float* __restrict__ xe,
                     const void*  __restrict__ eidx,
                     const float* __restrict__ eb1,
                     const float* __restrict__ eb2,
                     float* __restrict__ edges_out)
{
    extern __shared__ __align__(1024) char dsm[];
    __shared__ int s_snd[128], s_rcv[128];

    const int tid  = threadIdx.x;
    const int wid  = tid >> 5;
    const int lane = tid & 31;
    const int mw   = wid & 3;      // 32-row strip
    const int nw   = wid >> 2;     // 64-col strip (GEMM1) / 32-col (GEMM2)
    const int e0   = blockIdx.x * 128;

    const uint32_t sb = smem_u32(dsm);
    const uint32_t la_r  = lane & 15;
    const uint32_t la_kb = (lane >> 4) << 3;
    const uint32_t lb_r  = (lane & 7) | ((lane >> 4) << 3);   // x4 B: (n, n+8) pair
    const uint32_t lb_kb = ((lane >> 3) & 1) << 3;

    // edge indices
    {
        const unsigned* w = reinterpret_cast<const unsigned*>(eidx);
        const bool is64 = ((w[1] | w[3] | w[5] | w[7] | w[9] | w[11] | w[13] | w[15]) == 0u);
        if (tid < 128) {
            size_t e = (size_t)e0 + tid;
            if (is64) {
                const long long* p = reinterpret_cast<const long long*>(eidx);
                s_snd[tid] = (int)p[e];
                s_rcv[tid] = (int)p[(size_t)N_EDGES + e];
            } else {
                const int* p = reinterpret_cast<const int*>(eidx);
                s_snd[tid] = p[e];
                s_rcv[tid] = p[(size_t)N_EDGES + e];
            }
        }
    }
    __syncthreads();

    const int gm = tid >> 1;      // gather row (0..127), 2 threads/row
    const int gh = tid & 1;       // 32-float half of the 64-k chunk
    const int bn = tid >> 1;      // weight row (0..127)
    const int bq = tid & 1;       // 32-k half
    const int my_snd = s_snd[gm];
    const int my_rcv = s_rcv[gm];

    // prefetch chunk 0 B (single fp16)
    {
        const __half* s = g_eW1t + (size_t)bn * 320 + bq * 32;
#pragma unroll
        for (int j = 0; j < 4; j++) {
            uint32_t off = panel_off((uint32_t)bn, (uint32_t)(bq * 32 + j * 8));
            cp16(sb + 32768u + off, s + j * 8);
        }
        CP_COMMIT();
    }
    // prefetch chunk 0 A first half
    const float4* cur_rp = reinterpret_cast<const float4*>(xn + (size_t)my_snd * NODE_C) + gh * 8;
    float4 av[4];
#pragma unroll
    for (int i = 0; i < 4; i++) av[i] = cur_rp[i];

    float c[2][8][4];
#pragma unroll
    for (int a = 0; a < 2; a++)
#pragma unroll
        for (int b = 0; b < 8; b++)
#pragma unroll
            for (int d = 0; d < 4; d++) c[a][b][d] = 0.f;

    // ---------------- GEMM1: 5 K-chunks of 64 ----------------
#pragma unroll 1
    for (int ch = 0; ch < 5; ch++) {
        __syncthreads();
        float4 av2[4];
#pragma unroll
        for (int i = 0; i < 4; i++) av2[i] = cur_rp[4 + i];
#pragma unroll
        for (int i = 0; i < 2; i++) {
            uint4 hi, lo;
            split8(av[2 * i], av[2 * i + 1], hi, lo);
            uint32_t off = panel_off((uint32_t)gm, (uint32_t)(gh * 32 + i * 8));
            *(uint4*)(dsm + off)         = hi;
            *(uint4*)(dsm + 16384 + off) = lo;
        }
        if (ch < 4) {
            const int nc = ch + 1;
            uint32_t dst = 32768u + (uint32_t)((nc & 1) * 16384);
            const __half* s = g_eW1t + (size_t)bn * 320 + nc * 64 + bq * 32;
#pragma unroll
            for (int j = 0; j < 4; j++) {
                uint32_t off = panel_off((uint32_t)bn, (uint32_t)(bq * 32 + j * 8));
                cp16(sb + dst + off, s + j * 8);
            }
            CP_COMMIT();
            const float* rowp;
            if (nc < 2)      rowp = xn + (size_t)my_snd * NODE_C + nc * 64;
            else if (nc < 4) rowp = xn + (size_t)my_rcv * NODE_C + (nc - 2) * 64;
            else             rowp = xe + (size_t)(e0 + gm) * EDGE_C;
            cur_rp = reinterpret_cast<const float4*>(rowp) + gh * 8;
#pragma unroll
            for (int i = 0; i < 4; i++) av[i] = cur_rp[i];
        } else {
            // prefetch B2 (eW2t 64x128 single): p0@64K p1@72K
            const int n2 = tid >> 2;
            const int q2 = tid & 3;
            const __half* s = g_eW2t + (size_t)n2 * 128;
#pragma unroll
            for (int j = 0; j < 4; j++) {
                int seg = q2 * 4 + j;
                uint32_t p = (uint32_t)(seg >> 3);
                uint32_t off = p * 8192u + panel_off((uint32_t)n2, (uint32_t)((seg & 7) * 8));
                cp16(sb + 65536u + off, s + seg * 8);
            }
            CP_COMMIT();
        }
#pragma unroll
        for (int i = 0; i < 2; i++) {
            uint4 hi, lo;
            split8(av2[2 * i], av2[2 * i + 1], hi, lo);
            uint32_t off = panel_off((uint32_t)gm, (uint32_t)(gh * 32 + 16 + i * 8));
            *(uint4*)(dsm + off)         = hi;
            *(uint4*)(dsm + 16384 + off) = lo;
        }
        CP_WAIT(1);
        __syncthreads();

        const uint32_t Bp = sb + 32768u + (uint32_t)((ch & 1) * 16384);
#pragma unroll
        for (int ks = 0; ks < 4; ks++) {
            const uint32_t kb = ks * 16;
            uint32_t ah[2][4], al[2][4];
#pragma unroll
            for (int mf = 0; mf < 2; mf++) {
                uint32_t r = (uint32_t)(mw * 32 + mf * 16) + la_r;
                uint32_t po = panel_off(r, kb + la_kb);
                ldsm_x4(ah[mf], sb + po);
                ldsm_x4(al[mf], sb + 16384u + po);
            }
#pragma unroll
            for (int np = 0; np < 4; np++) {   // 4 n-frag pairs = 64 cols
                uint32_t n = (uint32_t)(nw * 64 + np * 16) + lb_r;
                uint32_t po = panel_off(n, kb + lb_kb);
                uint32_t b4[4];
                ldsm_x4(b4, Bp + po);
#pragma unroll
                for (int mf = 0; mf < 2; mf++) {
                    MMA16816(c[mf][np * 2],     ah[mf], b4);
                    MMA16816(c[mf][np * 2],     al[mf], b4);
                    MMA16816(c[mf][np * 2 + 1], ah[mf], b4 + 2);
                    MMA16816(c[mf][np * 2 + 1], al[mf], b4 + 2);
                }
            }
        }
    }
    __syncthreads();

    // ------------- Epilogue1: bias + SiLU -> h split panels -------------
    {
        const int l4 = lane >> 2;
        const int l2 = (lane & 3) * 2;
        const uint32_t hb_hi = (uint32_t)nw * 16384u;
        const uint32_t hb_lo = 32768u + (uint32_t)nw * 16384u;
#pragma unroll
        for (int nf = 0; nf < 8; nf++) {
            int col = nw * 64 + nf * 8 + l2;
            float b0 = __ldg(eb1 + col), b1 = __ldg(eb1 + col + 1);
            uint32_t kk = (uint32_t)(nf * 8 + l2);
#pragma unroll
            for (int mf = 0; mf < 2; mf++) {
                uint32_t m = (uint32_t)(mw * 32 + mf * 16 + l4);
                float x0 = silu_f(c[mf][nf][0] + b0);
                float x1 = silu_f(c[mf][nf][1] + b1);
                float x2 = silu_f(c[mf][nf][2] + b0);
                float x3 = silu_f(c[mf][nf][3] + b1);
                float h0 = h_round(x0), h1 = h_round(x1);
                float h2 = h_round(x2), h3 = h_round(x3);
                uint32_t o0 = panel_off(m, kk);
                uint32_t o1 = panel_off(m + 8, kk);
                *(uint32_t*)(dsm + hb_hi + o0) = f16x2(h0, h1);
                *(uint32_t*)(dsm + hb_lo + o0) = f16x2(x0 - h0, x1 - h1);
                *(uint32_t*)(dsm + hb_hi + o1) = f16x2(h2, h3);
                *(uint32_t*)(dsm + hb_lo + o1) = f16x2(x2 - h2, x3 - h3);
            }
        }
    }
    CP_WAIT(0);
    __syncthreads();

    // ---------------- GEMM2: h[128,128] @ eW2t^T -> [128,64] ----------------
    float c2[2][4][4];
#pragma unroll
    for (int a = 0; a < 2; a++)
#pragma unroll
        for (int b = 0; b < 4; b++)
#pragma unroll
            for (int d = 0; d < 4; d++) c2[a][b][d] = 0.f;

#pragma unroll
    for (int p = 0; p < 2; p++) {
        const uint32_t Ah = sb + (uint32_t)p * 16384u;
        const uint32_t Al = sb + 32768u + (uint32_t)p * 16384u;
        const uint32_t Bp = sb + 65536u + (uint32_t)p * 8192u;
#pragma unroll
        for (int ks = 0; ks < 4; ks++) {
            const uint32_t kb = ks * 16;
            uint32_t ah[2][4], al[2][4];
#pragma unroll
            for (int mf = 0; mf < 2; mf++) {
                uint32_t r = (uint32_t)(mw * 32 + mf * 16) + la_r;
                uint32_t po = panel_off(r, kb + la_kb);
                ldsm_x4(ah[mf], Ah + po);
                ldsm_x4(al[mf], Al + po);
            }
#pragma unroll
            for (int np = 0; np < 2; np++) {   // 2 n-frag pairs = 32 cols
                uint32_t n = (uint32_t)(nw * 32 + np * 16) + lb_r;
                uint32_t po = panel_off(n, kb + lb_kb);
                uint32_t b4[4];
                ldsm_x4(b4, Bp + po);
#pragma unroll
                for (int mf = 0; mf < 2; mf++) {
                    MMA16816(c2[mf][np * 2],     ah[mf], b4);
                    MMA16816(c2[mf][np * 2],     al[mf], b4);
                    MMA16816(c2[mf][np * 2 + 1], ah[mf], b4 + 2);
                    MMA16816(c2[mf][np * 2 + 1], al[mf], b4 + 2);
                }
            }
        }
    }

    // ------------- Epilogue2: SiLU, store, scatter-add -------------
    {
        const int l4 = lane >> 2;
        const int l2 = (lane & 3) * 2;
        float b0[4], b1[4];
#pragma unroll
        for (int nf = 0; nf < 4; nf++) {
            int col = nw * 32 + nf * 8 + l2;
            b0[nf] = __ldg(eb2 + col);
            b1[nf] = __ldg(eb2 + col + 1);
        }
#pragma unroll
        for (int mf = 0; mf < 2; mf++) {
#pragma unroll
            for (int half = 0; half < 2; half++) {
                int m = mw * 32 + mf * 16 + l4 + half * 8;
                int rcv = s_rcv[m];
                float* orow = edges_out + (size_t)(e0 + m) * EDGE_C;
                float* arow = g_aggr + (size_t)rcv * EDGE_C;
#pragma unroll
                for (int nf = 0; nf < 4; nf++) {
                    int col = nw * 32 + nf * 8 + l2;
                    float o0 = silu_f(c2[mf][nf][half * 2]     + b0[nf]);
                    float o1 = silu_f(c2[mf][nf][half * 2 + 1] + b1[nf]);
                    float2 ov = {o0, o1};
                    *reinterpret_cast<float2*>(orow + col) = ov;
                    atomicAdd(arow + col,     o0);
                    atomicAdd(arow + col + 1, o1);
                }
            }
        }
    }
}

// ---------------------------------------------------------------------------
// Node kernel: 64 nodes / CTA, 256 threads, 2 CTAs/SM. SMEM 80KB:
//   A_hi@0 (8K), A_lo@8K (8K)
//   B buf0@16K (16K), buf1@32K (16K)
//   After GEMM1: h_hi p0@0 p1@8K, h_lo p0@16K p1@24K
//   B2 (nW2t 128x128 single): p0@48K p1@64K
// ---------------------------------------------------------------------------
__global__ __launch_bounds__(256, 2)
void node_mma_kernel(const float* __restrict__ xn,
                     const float* __restrict__ nb1,
                     const float* __restrict__ nb2,
                     float* __restrict__ nodes_out)
{
    extern __shared__ __align__(1024) char dsm[];

    const int tid  = threadIdx.x;
    const int wid  = tid >> 5;
    const int lane = tid & 31;
    const int mw   = wid & 1;
    const int nw   = wid >> 1;
    const int m0   = blockIdx.x * 64;

    const uint32_t sb = smem_u32(dsm);
    const uint32_t la_r  = lane & 15;
    const uint32_t la_kb = (lane >> 4) << 3;
    const uint32_t lb_r  = (lane & 7) | ((lane >> 4) << 3);
    const uint32_t lb_kb = ((lane >> 3) & 1) << 3;

    const int gm = tid >> 2;
    const int gq = tid & 3;
    const int bn = tid >> 1;
    const int bq = tid & 1;
    const size_t grow = (size_t)m0 + gm;
    const bool gvalid = grow < N_NODES;

    {
        const __half* s = g_nW1t + (size_t)bn * 192 + bq * 32;
#pragma unroll
        for (int j = 0; j < 4; j++) {
            uint32_t off = panel_off((uint32_t)bn, (uint32_t)(bq * 32 + j * 8));
            cp16(sb + 16384u + off, s + j * 8);
        }
        CP_COMMIT();
    }
    float4 av[4];
    {
        const float4* rp = reinterpret_cast<const float4*>(xn + grow * NODE_C) + gq * 4;
#pragma unroll
        for (int i = 0; i < 4; i++)
            av[i] = gvalid ? rp[i] : make_float4(0.f, 0.f, 0.f, 0.f);
    }

    float c[2][4][4];
#pragma unroll
    for (int a = 0; a < 2; a++)
#pragma unroll
        for (int b = 0; b < 4; b++)
#pragma unroll
            for (int d = 0; d < 4; d++) c[a][b][d] = 0.f;

#pragma unroll 1
    for (int ch = 0; ch < 3; ch++) {
        __syncthreads();
#pragma unroll
        for (int i = 0; i < 2; i++) {
            uint4 hi, lo;
            split8(av[2 * i], av[2 * i + 1], hi, lo);
            uint32_t off = panel_off((uint32_t)gm, (uint32_t)(gq * 16 + i * 8));
            *(uint4*)(dsm + off)        = hi;
            *(uint4*)(dsm + 8192 + off) = lo;
        }
        if (ch < 2) {
            const int nc = ch + 1;
            uint32_t dst = 16384u + (uint32_t)((nc & 1) * 16384);
            const __half* s = g_nW1t + (size_t)bn * 192 + nc * 64 + bq * 32;
#pragma unroll
            for (int j = 0; j < 4; j++) {
                uint32_t off = panel_off((uint32_t)bn, (uint32_t)(bq * 32 + j * 8));
                cp16(sb + dst + off, s + j * 8);
            }
            CP_COMMIT();
            const float* rowp = (nc < 2) ? xn + grow * NODE_C + nc * 64
                                         : g_aggr + grow * EDGE_C;
            const float4* rp = reinterpret_cast<const float4*>(rowp) + gq * 4;
#pragma unroll
            for (int i = 0; i < 4; i++)
                av[i] = gvalid ? rp[i] : make_float4(0.f, 0.f, 0.f, 0.f);
        } else {
            // prefetch B2 (nW2t 128x128 single): p0@48K p1@64K
            const __half* s = g_nW2t + (size_t)bn * 128;
#pragma unroll
            for (int j = 0; j < 8; j++) {
                int seg = bq * 8 + j;
                uint32_t p = (uint32_t)(seg >> 3);
                uint32_t off = p * 16384u + panel_off((uint32_t)bn, (uint32_t)((seg & 7) * 8));
                cp16(sb + 49152u + off, s + seg * 8);
            }
            CP_COMMIT();
        }
        CP_WAIT(1);
        __syncthreads();

        const uint32_t Bp = sb + 16384u + (uint32_t)((ch & 1) * 16384);
#pragma unroll
        for (int ks = 0; ks < 4; ks++) {
            const uint32_t kb = ks * 16;
            uint32_t ah[2][4], al[2][4];
#pragma unroll
            for (int mf = 0; mf < 2; mf++) {
                uint32_t r = (uint32_t)(mw * 32 + mf * 16) + la_r;
                uint32_t po = panel_off(r, kb + la_kb);
                ldsm_x4(ah[mf], sb + po);
                ldsm_x4(al[mf], sb + 8192u + po);
            }
#pragma unroll
            for (int np = 0; np < 2; np++) {   // 2 n-frag pairs = 32 cols
                uint32_t n = (uint32_t)(nw * 32 + np * 16) + lb_r;
                uint32_t po = panel_off(n, kb + lb_kb);
                uint32_t b4[4];
                ldsm_x4(b4, Bp + po);
#pragma unroll
                for (int mf = 0; mf < 2; mf++) {
                    MMA16816(c[mf][np * 2],     ah[mf], b4);
                    MMA16816(c[mf][np * 2],     al[mf], b4);
                    MMA16816(c[mf][np * 2 + 1], ah[mf], b4 + 2);
                    MMA16816(c[mf][np * 2 + 1], al[mf], b4 + 2);
                }
            }
        }
    }
    __syncthreads();

    // Epilogue1: bias + SiLU -> h split
    {
        const int l4 = lane >> 2;
        const int l2 = (lane & 3) * 2;
        const uint32_t p = (uint32_t)(nw >> 1);
        const uint32_t hb_hi = p * 8192u;
        const uint32_t hb_lo = 16384u + p * 8192u;
#pragma unroll
        for (int nf = 0; nf < 4; nf++) {
            int col = nw * 32 + nf * 8 + l2;
            float b0 = __ldg(nb1 + col), b1 = __ldg(nb1 + col + 1);
            uint32_t kk = (uint32_t)((nw & 1) * 32 + nf * 8 + l2);
#pragma unroll
            for (int mf = 0; mf < 2; mf++) {
                uint32_t m = (uint32_t)(mw * 32 + mf * 16 + l4);
                float x0 = silu_f(c[mf][nf][0] + b0);
                float x1 = silu_f(c[mf][nf][1] + b1);
                float x2 = silu_f(c[mf][nf][2] + b0);
                float x3 = silu_f(c[mf][nf][3] + b1);
                float h0 = h_round(x0), h1 = h_round(x1);
                float h2 = h_round(x2), h3 = h_round(x3);
                uint32_t o0 = panel_off(m, kk);
                uint32_t o1 = panel_off(m + 8, kk);
                *(uint32_t*)(dsm + hb_hi + o0) = f16x2(h0, h1);
                *(uint32_t*)(dsm + hb_lo + o0) = f16x2(x0 - h0, x1 - h1);
                *(uint32_t*)(dsm + hb_hi + o1) = f16x2(h2, h3);
                *(uint32_t*)(dsm + hb_lo + o1) = f16x2(x2 - h2, x3 - h3);
            }
        }
    }
    CP_WAIT(0);
    __syncthreads();

    // GEMM2: h[64,128] @ nW2t^T -> [64,128]
    float c2[2][4][4];
#pragma unroll
    for (int a = 0; a < 2; a++)
#pragma unroll
        for (int b = 0; b < 4; b++)
#pragma unroll
            for (int d = 0; d < 4; d++) c2[a][b][d] = 0.f;

#pragma unroll
    for (int p = 0; p < 2; p++) {
        const uint32_t Ah = sb + (uint32_t)p * 8192u;
        const uint32_t Al = sb + 16384u + (uint32_t)p * 8192u;
        const uint32_t Bp = sb + 49152u + (uint32_t)p * 16384u;
#pragma unroll
        for (int ks = 0; ks < 4; ks++) {
            const uint32_t kb = ks * 16;
            uint32_t ah[2][4], al[2][4];
#pragma unroll
            for (int mf = 0; mf < 2; mf++) {
                uint32_t r = (uint32_t)(mw * 32 + mf * 16) + la_r;
                uint32_t po = panel_off(r, kb + la_kb);
                ldsm_x4(ah[mf], Ah + po);
                ldsm_x4(al[mf], Al + po);
            }
#pragma unroll
            for (int np = 0; np < 2; np++) {
                uint32_t n = (uint32_t)(nw * 32 + np * 16) + lb_r;
                uint32_t po = panel_off(n, kb + lb_kb);
                uint32_t b4[4];
                ldsm_x4(b4, Bp + po);
#pragma unroll
                for (int mf = 0; mf < 2; mf++) {
                    MMA16816(c2[mf][np * 2],     ah[mf], b4);
                    MMA16816(c2[mf][np * 2],     al[mf], b4);
                    MMA16816(c2[mf][np * 2 + 1], ah[mf], b4 + 2);
                    MMA16816(c2[mf][np * 2 + 1], al[mf], b4 + 2);
                }
            }
        }
    }

    // Epilogue2: + bias, store
    {
        const int l4 = lane >> 2;
        const int l2 = (lane & 3) * 2;
        float b0[4], b1[4];
#pragma unroll
        for (int nf = 0; nf < 4; nf++) {
            int col = nw * 32 + nf * 8 + l2;
            b0[nf] = __ldg(nb2 + col);
            b1[nf] = __ldg(nb2 + col + 1);
        }
#pragma unroll
        for (int mf = 0; mf < 2; mf++) {
#pragma unroll
            for (int half = 0; half < 2; half++) {
                size_t row = (size_t)m0 + mw * 32 + mf * 16 + l4 + half * 8;
                if (row < N_NODES) {
                    float* orow = nodes_out + row * NODE_C;
#pragma unroll
                    for (int nf = 0; nf < 4; nf++) {
                        int col = nw * 32 + nf * 8 + l2;
                        float2 ov;
                        ov.x = c2[mf][nf][half * 2]     + b0[nf];
                        ov.y = c2[mf][nf][half * 2 + 1] + b1[nf];
                        *reinterpret_cast<float2*>(orow + col) = ov;
                    }
                }
            }
        }
    }
}

// ---------------------------------------------------------------------------
extern "C" void kernel_launch(void* const* d_in, const int* in_sizes, int n_in,
                              void* d_out, int out_size)
{
    const float* xn   = (const float*)d_in[0];
    const float* xe   = (const float*)d_in[1];
    const void*  eidx =               d_in[2];
    const float* eW1  = (const float*)d_in[3];
    const float* eb1  = (const float*)d_in[4];
    const float* eW2  = (const float*)d_in[5];
    const float* eb2  = (const float*)d_in[6];
    const float* nW1  = (const float*)d_in[7];
    const float* nb1  = (const float*)d_in[8];
    const float* nW2  = (const float*)d_in[9];
    const float* nb2  = (const float*)d_in[10];

    float* nodes_out = (float*)d_out;
    float* edges_out = (float*)d_out + (size_t)N_NODES * NODE_C;

    cudaFuncSetAttribute(edge_mma_kernel, cudaFuncAttributeMaxDynamicSharedMemorySize, EDGE_SMEM);
    cudaFuncSetAttribute(node_mma_kernel, cudaFuncAttributeMaxDynamicSharedMemorySize, NODE_SMEM);

    prep_weights_kernel<<<160, 256>>>(eW1, eW2, nW1, nW2);
    zero_aggr_kernel<<<(N_NODES * EDGE_C / 4 + 255) / 256, 256>>>();
    edge_mma_kernel<<<N_EDGES / 128, 256, EDGE_SMEM>>>(xn, xe, eidx, eb1, eb2, edges_out);
    node_mma_kernel<<<(N_NODES + 63) / 64, 256, NODE_SMEM>>>(xn, nb1, nb2, nodes_out);
}

// round 9
// speedup vs baseline: 4.4372x; 1.1792x over previous
#include <cuda_runtime.h>
#include <cuda_fp16.h>
#include <cstdint>

#define N_NODES 50000
#define N_EDGES 800000
#define NODE_C  128
#define EDGE_C  64

// ---------------------------------------------------------------------------
// Device scratch (no cudaMalloc allowed)
// ---------------------------------------------------------------------------
__device__ float g_aggr[(size_t)N_NODES * EDGE_C];
// Pre-transposed single-fp16 weights: Wt[n][k] = W[k][n]
__device__ __align__(16) __half g_eW1t[128 * 320];
__device__ __align__(16) __half g_eW2t[64 * 128];
__device__ __align__(16) __half g_nW1t[128 * 192];
__device__ __align__(16) __half g_nW2t[128 * 128];

// ---------------------------------------------------------------------------
// Helpers
// ---------------------------------------------------------------------------
__device__ __forceinline__ uint32_t smem_u32(const void* p) {
    uint32_t a;
    asm("{ .reg .u64 t; cvta.to.shared.u64 t, %1; cvt.u32.u64 %0, t; }"
        : "=r"(a) : "l"(p));
    return a;
}

// Panels: [rows][64] fp16, 128-byte rows, XOR-swizzled 16B blocks.
__device__ __forceinline__ uint32_t panel_off(uint32_t r, uint32_t k) {
    return r * 128u + ((((k >> 3) ^ (r & 7u)) << 4) | ((k & 7u) << 1));
}

__device__ __forceinline__ void ldsm_x4(uint32_t* d, uint32_t a) {
    asm volatile("ldmatrix.sync.aligned.m8n8.x4.shared.b16 {%0,%1,%2,%3}, [%4];"
                 : "=r"(d[0]), "=r"(d[1]), "=r"(d[2]), "=r"(d[3]) : "r"(a));
}

#define MMA16816(c, a, b) \
    asm volatile("mma.sync.aligned.m16n8k16.row.col.f32.f16.f16.f32 " \
        "{%0,%1,%2,%3},{%4,%5,%6,%7},{%8,%9},{%0,%1,%2,%3};" \
        : "+f"((c)[0]), "+f"((c)[1]), "+f"((c)[2]), "+f"((c)[3]) \
        : "r"((a)[0]), "r"((a)[1]), "r"((a)[2]), "r"((a)[3]), \
          "r"((b)[0]), "r"((b)[1]))

__device__ __forceinline__ void cp16(uint32_t dst, const void* src) {
    asm volatile("cp.async.cg.shared.global [%0], [%1], 16;"
                 :: "r"(dst), "l"(src) : "memory");
}
#define CP_COMMIT() asm volatile("cp.async.commit_group;" ::: "memory")
#define CP_WAIT(n)  asm volatile("cp.async.wait_group %0;" :: "n"(n) : "memory")

__device__ __forceinline__ uint32_t f16x2(float lo, float hi) {
    uint32_t r;
    asm("cvt.rn.f16x2.f32 %0, %1, %2;" : "=r"(r) : "f"(hi), "f"(lo));
    return r;
}
__device__ __forceinline__ float silu_f(float x) {
    return x / (1.0f + __expf(-x));
}
// Pack 8 floats (two float4) to 8 fp16 (one uint4)
__device__ __forceinline__ uint4 pack8(float4 v0, float4 v1) {
    uint4 r;
    r.x = f16x2(v0.x, v0.y);
    r.y = f16x2(v0.z, v0.w);
    r.z = f16x2(v1.x, v1.y);
    r.w = f16x2(v1.z, v1.w);
    return r;
}

// ---------------------------------------------------------------------------
// Setup kernels
// ---------------------------------------------------------------------------
__global__ void zero_aggr_kernel() {
    size_t i = (size_t)blockIdx.x * blockDim.x + threadIdx.x;
    size_t n4 = (size_t)N_NODES * EDGE_C / 4;
    if (i < n4) reinterpret_cast<float4*>(g_aggr)[i] = make_float4(0.f, 0.f, 0.f, 0.f);
}

__global__ void prep_weights_kernel(const float* __restrict__ eW1,
                                    const float* __restrict__ eW2,
                                    const float* __restrict__ nW1,
                                    const float* __restrict__ nW2) {
    int i = blockIdx.x * 256 + threadIdx.x;
    if (i < 128 * 320) {
        int n = i / 320, k = i % 320;
        g_eW1t[i] = __float2half_rn(eW1[(size_t)k * 128 + n]);
    }
    if (i < 64 * 128) {
        int n = i / 128, k = i % 128;
        g_eW2t[i] = __float2half_rn(eW2[(size_t)k * 64 + n]);
    }
    if (i < 128 * 192) {
        int n = i / 192, k = i % 192;
        g_nW1t[i] = __float2half_rn(nW1[(size_t)k * 128 + n]);
    }
    if (i < 128 * 128) {
        int n = i / 128, k = i % 128;
        g_nW2t[i] = __float2half_rn(nW2[(size_t)k * 128 + n]);
    }
}

// ---------------------------------------------------------------------------
// Edge kernel: 128 edges / CTA, 256 threads, 8 warps = 4 M-strips x 2 N-strips
// Full fp16 operands, fp32 accum. 2 CTAs/SM. SMEM 64KB:
//   A@0 (16K)
//   B buf0@16K (16K), buf1@32K (16K)
//   B2 (eW2t 64x128): p0@48K p1@56K  (prefetched during last chunk, buf0 in use)
//   After GEMM1: h p0@0 (A region), p1@16K (buf0, written post-sync)
// ---------------------------------------------------------------------------
#define EDGE_SMEM 65536
#define NODE_SMEM 73728

__global__ __launch_bounds__(256, 2)
void edge_mma_kernel(const float* __restrict__ xn,
                     const float* __restrict__ xe,
                     const void*  __restrict__ eidx,
                     const float* __restrict__ eb1,
                     const float* __restrict__ eb2,
                     float* __restrict__ edges_out)
{
    extern __shared__ __align__(1024) char dsm[];
    __shared__ int s_snd[128], s_rcv[128];

    const int tid  = threadIdx.x;
    const int wid  = tid >> 5;
    const int lane = tid & 31;
    const int mw   = wid & 3;      // 32-row strip
    const int nw   = wid >> 2;     // 64-col strip (GEMM1) / 32-col (GEMM2)
    const int e0   = blockIdx.x * 128;

    const uint32_t sb = smem_u32(dsm);
    const uint32_t la_r  = lane & 15;
    const uint32_t la_kb = (lane >> 4) << 3;
    const uint32_t lb_r  = (lane & 7) | ((lane >> 4) << 3);   // x4 B: (n, n+8) pair
    const uint32_t lb_kb = ((lane >> 3) & 1) << 3;

    // edge indices
    {
        const unsigned* w = reinterpret_cast<const unsigned*>(eidx);
        const bool is64 = ((w[1] | w[3] | w[5] | w[7] | w[9] | w[11] | w[13] | w[15]) == 0u);
        if (tid < 128) {
            size_t e = (size_t)e0 + tid;
            if (is64) {
                const long long* p = reinterpret_cast<const long long*>(eidx);
                s_snd[tid] = (int)p[e];
                s_rcv[tid] = (int)p[(size_t)N_EDGES + e];
            } else {
                const int* p = reinterpret_cast<const int*>(eidx);
                s_snd[tid] = p[e];
                s_rcv[tid] = p[(size_t)N_EDGES + e];
            }
        }
    }
    __syncthreads();

    const int gm = tid >> 1;      // gather row (0..127), 2 threads/row
    const int gh = tid & 1;       // 32-float half of the 64-k chunk
    const int bn = tid >> 1;      // weight row (0..127)
    const int bq = tid & 1;       // 32-k half
    const int my_snd = s_snd[gm];
    const int my_rcv = s_rcv[gm];

    // prefetch chunk 0 B
    {
        const __half* s = g_eW1t + (size_t)bn * 320 + bq * 32;
#pragma unroll
        for (int j = 0; j < 4; j++) {
            uint32_t off = panel_off((uint32_t)bn, (uint32_t)(bq * 32 + j * 8));
            cp16(sb + 16384u + off, s + j * 8);
        }
        CP_COMMIT();
    }
    // prefetch chunk 0 A (all 32 of my floats)
    const float4* cur_rp = reinterpret_cast<const float4*>(xn + (size_t)my_snd * NODE_C) + gh * 8;
    float4 av[8];
#pragma unroll
    for (int i = 0; i < 8; i++) av[i] = cur_rp[i];

    float c[2][8][4];
#pragma unroll
    for (int a = 0; a < 2; a++)
#pragma unroll
        for (int b = 0; b < 8; b++)
#pragma unroll
            for (int d = 0; d < 4; d++) c[a][b][d] = 0.f;

    // ---------------- GEMM1: 5 K-chunks of 64 ----------------
#pragma unroll 1
    for (int ch = 0; ch < 5; ch++) {
        __syncthreads();
        // store A (single fp16)
#pragma unroll
        for (int i = 0; i < 4; i++) {
            uint32_t off = panel_off((uint32_t)gm, (uint32_t)(gh * 32 + i * 8));
            *(uint4*)(dsm + off) = pack8(av[2 * i], av[2 * i + 1]);
        }
        if (ch < 4) {
            const int nc = ch + 1;
            uint32_t dst = 16384u + (uint32_t)((nc & 1) * 16384);
            const __half* s = g_eW1t + (size_t)bn * 320 + nc * 64 + bq * 32;
#pragma unroll
            for (int j = 0; j < 4; j++) {
                uint32_t off = panel_off((uint32_t)bn, (uint32_t)(bq * 32 + j * 8));
                cp16(sb + dst + off, s + j * 8);
            }
            CP_COMMIT();
            const float* rowp;
            if (nc < 2)      rowp = xn + (size_t)my_snd * NODE_C + nc * 64;
            else if (nc < 4) rowp = xn + (size_t)my_rcv * NODE_C + (nc - 2) * 64;
            else             rowp = xe + (size_t)(e0 + gm) * EDGE_C;
            cur_rp = reinterpret_cast<const float4*>(rowp) + gh * 8;
#pragma unroll
            for (int i = 0; i < 8; i++) av[i] = cur_rp[i];
        } else {
            // prefetch B2 (eW2t 64x128): p0@48K p1@56K
            const int n2 = tid >> 2;
            const int q2 = tid & 3;
            const __half* s = g_eW2t + (size_t)n2 * 128;
#pragma unroll
            for (int j = 0; j < 4; j++) {
                int seg = q2 * 4 + j;
                uint32_t p = (uint32_t)(seg >> 3);
                uint32_t off = p * 8192u + panel_off((uint32_t)n2, (uint32_t)((seg & 7) * 8));
                cp16(sb + 49152u + off, s + seg * 8);
            }
            CP_COMMIT();
        }
        CP_WAIT(1);
        __syncthreads();

        const uint32_t Bp = sb + 16384u + (uint32_t)((ch & 1) * 16384);
#pragma unroll
        for (int ks = 0; ks < 4; ks++) {
            const uint32_t kb = ks * 16;
            uint32_t a4[2][4];
#pragma unroll
            for (int mf = 0; mf < 2; mf++) {
                uint32_t r = (uint32_t)(mw * 32 + mf * 16) + la_r;
                ldsm_x4(a4[mf], sb + panel_off(r, kb + la_kb));
            }
#pragma unroll
            for (int np = 0; np < 4; np++) {   // 4 n-frag pairs = 64 cols
                uint32_t n = (uint32_t)(nw * 64 + np * 16) + lb_r;
                uint32_t b4[4];
                ldsm_x4(b4, Bp + panel_off(n, kb + lb_kb));
#pragma unroll
                for (int mf = 0; mf < 2; mf++) {
                    MMA16816(c[mf][np * 2],     a4[mf], b4);
                    MMA16816(c[mf][np * 2 + 1], a4[mf], b4 + 2);
                }
            }
        }
    }
    __syncthreads();

    // ------------- Epilogue1: bias + SiLU -> h fp16 panels -------------
    {
        const int l4 = lane >> 2;
        const int l2 = (lane & 3) * 2;
        const uint32_t hb = (uint32_t)nw * 16384u;   // p0@0, p1@16K
#pragma unroll
        for (int nf = 0; nf < 8; nf++) {
            int col = nw * 64 + nf * 8 + l2;
            float b0 = __ldg(eb1 + col), b1 = __ldg(eb1 + col + 1);
            uint32_t kk = (uint32_t)(nf * 8 + l2);
#pragma unroll
            for (int mf = 0; mf < 2; mf++) {
                uint32_t m = (uint32_t)(mw * 32 + mf * 16 + l4);
                float x0 = silu_f(c[mf][nf][0] + b0);
                float x1 = silu_f(c[mf][nf][1] + b1);
                float x2 = silu_f(c[mf][nf][2] + b0);
                float x3 = silu_f(c[mf][nf][3] + b1);
                *(uint32_t*)(dsm + hb + panel_off(m, kk))     = f16x2(x0, x1);
                *(uint32_t*)(dsm + hb + panel_off(m + 8, kk)) = f16x2(x2, x3);
            }
        }
    }
    CP_WAIT(0);
    __syncthreads();

    // ---------------- GEMM2: h[128,128] @ eW2t^T -> [128,64] ----------------
    float c2[2][4][4];
#pragma unroll
    for (int a = 0; a < 2; a++)
#pragma unroll
        for (int b = 0; b < 4; b++)
#pragma unroll
            for (int d = 0; d < 4; d++) c2[a][b][d] = 0.f;

#pragma unroll
    for (int p = 0; p < 2; p++) {
        const uint32_t Ap = sb + (uint32_t)p * 16384u;
        const uint32_t Bp = sb + 49152u + (uint32_t)p * 8192u;
#pragma unroll
        for (int ks = 0; ks < 4; ks++) {
            const uint32_t kb = ks * 16;
            uint32_t a4[2][4];
#pragma unroll
            for (int mf = 0; mf < 2; mf++) {
                uint32_t r = (uint32_t)(mw * 32 + mf * 16) + la_r;
                ldsm_x4(a4[mf], Ap + panel_off(r, kb + la_kb));
            }
#pragma unroll
            for (int np = 0; np < 2; np++) {   // 2 n-frag pairs = 32 cols
                uint32_t n = (uint32_t)(nw * 32 + np * 16) + lb_r;
                uint32_t b4[4];
                ldsm_x4(b4, Bp + panel_off(n, kb + lb_kb));
#pragma unroll
                for (int mf = 0; mf < 2; mf++) {
                    MMA16816(c2[mf][np * 2],     a4[mf], b4);
                    MMA16816(c2[mf][np * 2 + 1], a4[mf], b4 + 2);
                }
            }
        }
    }

    // ------------- Epilogue2: SiLU, store, scatter-add -------------
    {
        const int l4 = lane >> 2;
        const int l2 = (lane & 3) * 2;
        float b0[4], b1[4];
#pragma unroll
        for (int nf = 0; nf < 4; nf++) {
            int col = nw * 32 + nf * 8 + l2;
            b0[nf] = __ldg(eb2 + col);
            b1[nf] = __ldg(eb2 + col + 1);
        }
#pragma unroll
        for (int mf = 0; mf < 2; mf++) {
#pragma unroll
            for (int half = 0; half < 2; half++) {
                int m = mw * 32 + mf * 16 + l4 + half * 8;
                int rcv = s_rcv[m];
                float* orow = edges_out + (size_t)(e0 + m) * EDGE_C;
                float* arow = g_aggr + (size_t)rcv * EDGE_C;
#pragma unroll
                for (int nf = 0; nf < 4; nf++) {
                    int col = nw * 32 + nf * 8 + l2;
                    float o0 = silu_f(c2[mf][nf][half * 2]     + b0[nf]);
                    float o1 = silu_f(c2[mf][nf][half * 2 + 1] + b1[nf]);
                    float2 ov = {o0, o1};
                    *reinterpret_cast<float2*>(orow + col) = ov;
                    atomicAdd(arow + col,     o0);
                    atomicAdd(arow + col + 1, o1);
                }
            }
        }
    }
}

// ---------------------------------------------------------------------------
// Node kernel: 64 nodes / CTA, 256 threads, 2 CTAs/SM. SMEM 72KB:
//   A@0 (8K)
//   B buf0@8K (16K), buf1@24K (16K)
//   B2 (nW2t 128x128): p0@40K p1@56K (16K each)
//   After GEMM1: h p0@0, p1@8K (buf0, post-sync)
// ---------------------------------------------------------------------------
__global__ __launch_bounds__(256, 2)
void node_mma_kernel(const float* __restrict__ xn,
                     const float* __restrict__ nb1,
                     const float* __restrict__ nb2,
                     float* __restrict__ nodes_out)
{
    extern __shared__ __align__(1024) char dsm[];

    const int tid  = threadIdx.x;
    const int wid  = tid >> 5;
    const int lane = tid & 31;
    const int mw   = wid & 1;
    const int nw   = wid >> 1;
    const int m0   = blockIdx.x * 64;

    const uint32_t sb = smem_u32(dsm);
    const uint32_t la_r  = lane & 15;
    const uint32_t la_kb = (lane >> 4) << 3;
    const uint32_t lb_r  = (lane & 7) | ((lane >> 4) << 3);
    const uint32_t lb_kb = ((lane >> 3) & 1) << 3;

    const int gm = tid >> 2;
    const int gq = tid & 3;
    const int bn = tid >> 1;
    const int bq = tid & 1;
    const size_t grow = (size_t)m0 + gm;
    const bool gvalid = grow < N_NODES;

    {
        const __half* s = g_nW1t + (size_t)bn * 192 + bq * 32;
#pragma unroll
        for (int j = 0; j < 4; j++) {
            uint32_t off = panel_off((uint32_t)bn, (uint32_t)(bq * 32 + j * 8));
            cp16(sb + 8192u + off, s + j * 8);
        }
        CP_COMMIT();
    }
    float4 av[4];
    {
        const float4* rp = reinterpret_cast<const float4*>(xn + grow * NODE_C) + gq * 4;
#pragma unroll
        for (int i = 0; i < 4; i++)
            av[i] = gvalid ? rp[i] : make_float4(0.f, 0.f, 0.f, 0.f);
    }

    float c[2][4][4];
#pragma unroll
    for (int a = 0; a < 2; a++)
#pragma unroll
        for (int b = 0; b < 4; b++)
#pragma unroll
            for (int d = 0; d < 4; d++) c[a][b][d] = 0.f;

#pragma unroll 1
    for (int ch = 0; ch < 3; ch++) {
        __syncthreads();
#pragma unroll
        for (int i = 0; i < 2; i++) {
            uint32_t off = panel_off((uint32_t)gm, (uint32_t)(gq * 16 + i * 8));
            *(uint4*)(dsm + off) = pack8(av[2 * i], av[2 * i + 1]);
        }
        if (ch < 2) {
            const int nc = ch + 1;
            uint32_t dst = 8192u + (uint32_t)((nc & 1) * 16384);
            const __half* s = g_nW1t + (size_t)bn * 192 + nc * 64 + bq * 32;
#pragma unroll
            for (int j = 0; j < 4; j++) {
                uint32_t off = panel_off((uint32_t)bn, (uint32_t)(bq * 32 + j * 8));
                cp16(sb + dst + off, s + j * 8);
            }
            CP_COMMIT();
            const float* rowp = (nc < 2) ? xn + grow * NODE_C + nc * 64
                                         : g_aggr + grow * EDGE_C;
            const float4* rp = reinterpret_cast<const float4*>(rowp) + gq * 4;
#pragma unroll
            for (int i = 0; i < 4; i++)
                av[i] = gvalid ? rp[i] : make_float4(0.f, 0.f, 0.f, 0.f);
        } else {
            // prefetch B2 (nW2t 128x128): p0@40K p1@56K
            const __half* s = g_nW2t + (size_t)bn * 128;
#pragma unroll
            for (int j = 0; j < 8; j++) {
                int seg = bq * 8 + j;
                uint32_t p = (uint32_t)(seg >> 3);
                uint32_t off = p * 16384u + panel_off((uint32_t)bn, (uint32_t)((seg & 7) * 8));
                cp16(sb + 40960u + off, s + seg * 8);
            }
            CP_COMMIT();
        }
        CP_WAIT(1);
        __syncthreads();

        const uint32_t Bp = sb + 8192u + (uint32_t)((ch & 1) * 16384);
#pragma unroll
        for (int ks = 0; ks < 4; ks++) {
            const uint32_t kb = ks * 16;
            uint32_t a4[2][4];
#pragma unroll
            for (int mf = 0; mf < 2; mf++) {
                uint32_t r = (uint32_t)(mw * 32 + mf * 16) + la_r;
                ldsm_x4(a4[mf], sb + panel_off(r, kb + la_kb));
            }
#pragma unroll
            for (int np = 0; np < 2; np++) {
                uint32_t n = (uint32_t)(nw * 32 + np * 16) + lb_r;
                uint32_t b4[4];
                ldsm_x4(b4, Bp + panel_off(n, kb + lb_kb));
#pragma unroll
                for (int mf = 0; mf < 2; mf++) {
                    MMA16816(c[mf][np * 2],     a4[mf], b4);
                    MMA16816(c[mf][np * 2 + 1], a4[mf], b4 + 2);
                }
            }
        }
    }
    __syncthreads();

    // Epilogue1: bias + SiLU -> h fp16
    {
        const int l4 = lane >> 2;
        const int l2 = (lane & 3) * 2;
        const uint32_t hb = (uint32_t)(nw >> 1) * 8192u;   // p0@0, p1@8K
#pragma unroll
        for (int nf = 0; nf < 4; nf++) {
            int col = nw * 32 + nf * 8 + l2;
            float b0 = __ldg(nb1 + col), b1 = __ldg(nb1 + col + 1);
            uint32_t kk = (uint32_t)((nw & 1) * 32 + nf * 8 + l2);
#pragma unroll
            for (int mf = 0; mf < 2; mf++) {
                uint32_t m = (uint32_t)(mw * 32 + mf * 16 + l4);
                float x0 = silu_f(c[mf][nf][0] + b0);
                float x1 = silu_f(c[mf][nf][1] + b1);
                float x2 = silu_f(c[mf][nf][2] + b0);
                float x3 = silu_f(c[mf][nf][3] + b1);
                *(uint32_t*)(dsm + hb + panel_off(m, kk))     = f16x2(x0, x1);
                *(uint32_t*)(dsm + hb + panel_off(m + 8, kk)) = f16x2(x2, x3);
            }
        }
    }
    CP_WAIT(0);
    __syncthreads();

    // GEMM2: h[64,128] @ nW2t^T -> [64,128]
    float c2[2][4][4];
#pragma unroll
    for (int a = 0; a < 2; a++)
#pragma unroll
        for (int b = 0; b < 4; b++)
#pragma unroll
            for (int d = 0; d < 4; d++) c2[a][b][d] = 0.f;

#pragma unroll
    for (int p = 0; p < 2; p++) {
        const uint32_t Ap = sb + (uint32_t)p * 8192u;
        const uint32_t Bp = sb + 40960u + (uint32_t)p * 16384u;
#pragma unroll
        for (int ks = 0; ks < 4; ks++) {
            const uint32_t kb = ks * 16;
            uint32_t a4[2][4];
#pragma unroll
            for (int mf = 0; mf < 2; mf++) {
                uint32_t r = (uint32_t)(mw * 32 + mf * 16) + la_r;
                ldsm_x4(a4[mf], Ap + panel_off(r, kb + la_kb));
            }
#pragma unroll
            for (int np = 0; np < 2; np++) {
                uint32_t n = (uint32_t)(nw * 32 + np * 16) + lb_r;
                uint32_t b4[4];
                ldsm_x4(b4, Bp + panel_off(n, kb + lb_kb));
#pragma unroll
                for (int mf = 0; mf < 2; mf++) {
                    MMA16816(c2[mf][np * 2],     a4[mf], b4);
                    MMA16816(c2[mf][np * 2 + 1], a4[mf], b4 + 2);
                }
            }
        }
    }

    // Epilogue2: + bias, store
    {
        const int l4 = lane >> 2;
        const int l2 = (lane & 3) * 2;
        float b0[4], b1[4];
#pragma unroll
        for (int nf = 0; nf < 4; nf++) {
            int col = nw * 32 + nf * 8 + l2;
            b0[nf] = __ldg(nb2 + col);
            b1[nf] = __ldg(nb2 + col + 1);
        }
#pragma unroll
        for (int mf = 0; mf < 2; mf++) {
#pragma unroll
            for (int half = 0; half < 2; half++) {
                size_t row = (size_t)m0 + mw * 32 + mf * 16 + l4 + half * 8;
                if (row < N_NODES) {
                    float* orow = nodes_out + row * NODE_C;
#pragma unroll
                    for (int nf = 0; nf < 4; nf++) {
                        int col = nw * 32 + nf * 8 + l2;
                        float2 ov;
                        ov.x = c2[mf][nf][half * 2]     + b0[nf];
                        ov.y = c2[mf][nf][half * 2 + 1] + b1[nf];
                        *reinterpret_cast<float2*>(orow + col) = ov;
                    }
                }
            }
        }
    }
}

// ---------------------------------------------------------------------------
extern "C" void kernel_launch(void* const* d_in, const int* in_sizes, int n_in,
                              void* d_out, int out_size)
{
    const float* xn   = (const float*)d_in[0];
    const float* xe   = (const float*)d_in[1];
    const void*  eidx =               d_in[2];
    const float* eW1  = (const float*)d_in[3];
    const float* eb1  = (const float*)d_in[4];
    const float* eW2  = (const float*)d_in[5];
    const float* eb2  = (const float*)d_in[6];
    const float* nW1  = (const float*)d_in[7];
    const float* nb1  = (const float*)d_in[8];
    const float* nW2  = (const float*)d_in[9];
    const float* nb2  = (const float*)d_in[10];

    float* nodes_out = (float*)d_out;
    float* edges_out = (float*)d_out + (size_t)N_NODES * NODE_C;

    cudaFuncSetAttribute(edge_mma_kernel, cudaFuncAttributeMaxDynamicSharedMemorySize, EDGE_SMEM);
    cudaFuncSetAttribute(node_mma_kernel, cudaFuncAttributeMaxDynamicSharedMemorySize, NODE_SMEM);

    prep_weights_kernel<<<160, 256>>>(eW1, eW2, nW1, nW2);
    zero_aggr_kernel<<<(N_NODES * EDGE_C / 4 + 255) / 256, 256>>>();
    edge_mma_kernel<<<N_EDGES / 128, 256, EDGE_SMEM>>>(xn, xe, eidx, eb1, eb2, edges_out);
    node_mma_kernel<<<(N_NODES + 63) / 64, 256, NODE_SMEM>>>(xn, nb1, nb2, nodes_out);
}